// round 8
// baseline (speedup 1.0000x reference)
#include <cuda_runtime.h>
#include <math.h>

#define NN 10000   // nodes per branch
#define NE 160000  // edges per branch
#define NG 32      // graphs per branch
#define HD 128     // hidden
#define NB (2*NN)  // stacked nodes (both branches)

typedef unsigned long long ull;

// ---------------------------------------------------------------------------
// Static device scratch (allocation-free rule). Both branches stacked.
// ---------------------------------------------------------------------------
__device__ float g_h [NB * HD];        // node state h                 [2N,128]
__device__ float g_A [NB * 2 * HD];    // h@W1_top + b1 ; reused as agg [2N,256]
__device__ float g_B [NB * 2 * HD];    // h@W1_bot ; reused as relu(update)
__device__ float g_T [NB * 2 * HD];    // segment-summed relu ; reused as nx
__device__ float g_dg[NB];             // per-node in-degree (float)
__device__ float g_gg[2 * NG * HD];    // pooled per-graph             [64,128]

// ---------------------------------------------------------------------------
// SGEMM: C[M,N] = op(A[M,K] @ Bw[K,N] + bias)       (row-major)
//   EPI 0 : C = acc + bias (bias optionally scaled per-row by rowscale)
//   EPI 2 : C = C + acc + bias                      (residual accumulate)
//   EPI 3 : C = relu(C + acc + bias)                (split-K relu finish)
// TM=8 -> BM=128 ; TM=4 -> BM=64. BN=128, BK=16, 256 threads.
// A duplicated in smem ((a,a) pairs) so the inner loop is pure
// LDS.128 + fma.rn.f32x2 (FFMA2). N % 128 == 0, K % 16 == 0.
// ---------------------------------------------------------------------------
template <int EPI, int TM>
__global__ __launch_bounds__(256, 2)
void sgemm(const float* __restrict__ Ag, const float* __restrict__ Bg,
           float* __restrict__ C, const float* __restrict__ bias,
           const float* __restrict__ rowscale, int M, int N, int K)
{
    constexpr int BM = TM * 16, BN = 128, BK = 16, TN2 = 4;
    constexpr int ALD = (BM * 4) / 256;   // float4 A-loads per thread (2 or 1)

    __shared__ __align__(16) float As2[2][BK][2 * BM];  // duplicated A (transposed)
    __shared__ __align__(16) float Bs [2][BK][BN];

    const int tid = threadIdx.x;
    const int tx = tid & 15;
    const int ty = tid >> 4;
    const int m0 = blockIdx.x * BM;
    const int n0 = blockIdx.y * BN;

    const int brow = tid >> 5;
    const int bc4  = tid & 31;

    ull acc[TM][TN2];
#pragma unroll
    for (int i = 0; i < TM; i++)
#pragma unroll
        for (int j = 0; j < TN2; j++) acc[i][j] = 0ULL;

    float4 aR[ALD], bR0, bR1;

    auto ldg = [&](int kt) {
#pragma unroll
        for (int i = 0; i < ALD; i++) {
            const int idx = tid + i * 256;
            const int r = idx >> 2, c4 = idx & 3;
            const int gr = m0 + r;
            aR[i] = (gr < M)
                ? *reinterpret_cast<const float4*>(Ag + (size_t)gr * K + kt * BK + c4 * 4)
                : make_float4(0.f, 0.f, 0.f, 0.f);
        }
        bR0 = *reinterpret_cast<const float4*>(Bg + (size_t)(kt * BK + brow)     * N + n0 + bc4 * 4);
        bR1 = *reinterpret_cast<const float4*>(Bg + (size_t)(kt * BK + brow + 8) * N + n0 + bc4 * 4);
    };
    auto sts = [&](int buf) {
#pragma unroll
        for (int i = 0; i < ALD; i++) {
            const int idx = tid + i * 256;
            const int r = idx >> 2, c4 = idx & 3;
            *reinterpret_cast<float2*>(&As2[buf][c4 * 4 + 0][2 * r]) = make_float2(aR[i].x, aR[i].x);
            *reinterpret_cast<float2*>(&As2[buf][c4 * 4 + 1][2 * r]) = make_float2(aR[i].y, aR[i].y);
            *reinterpret_cast<float2*>(&As2[buf][c4 * 4 + 2][2 * r]) = make_float2(aR[i].z, aR[i].z);
            *reinterpret_cast<float2*>(&As2[buf][c4 * 4 + 3][2 * r]) = make_float2(aR[i].w, aR[i].w);
        }
        *reinterpret_cast<float4*>(&Bs[buf][brow][bc4 * 4])     = bR0;
        *reinterpret_cast<float4*>(&Bs[buf][brow + 8][bc4 * 4]) = bR1;
    };

    ldg(0); sts(0); __syncthreads();

    const int nt = K >> 4;
    for (int t = 0; t < nt; t++) {
        const int buf = t & 1;
        if (t + 1 < nt) ldg(t + 1);           // prefetch, hidden under compute

#pragma unroll
        for (int k = 0; k < BK; k++) {
            ull a[TM];
            const ulonglong2* ap =
                reinterpret_cast<const ulonglong2*>(&As2[buf][k][ty * 2 * TM]);
#pragma unroll
            for (int q = 0; q < TM / 2; q++) {
                ulonglong2 v = ap[q];
                a[2 * q] = v.x; a[2 * q + 1] = v.y;
            }
            ull b[TN2];
            ulonglong2 b0 = *reinterpret_cast<const ulonglong2*>(&Bs[buf][k][tx * 4]);
            ulonglong2 b1 = *reinterpret_cast<const ulonglong2*>(&Bs[buf][k][64 + tx * 4]);
            b[0] = b0.x; b[1] = b0.y; b[2] = b1.x; b[3] = b1.y;
#pragma unroll
            for (int i = 0; i < TM; i++)
#pragma unroll
                for (int j = 0; j < TN2; j++)
                    asm("fma.rn.f32x2 %0, %1, %2, %0;"
                        : "+l"(acc[i][j]) : "l"(a[i]), "l"(b[j]));
        }

        if (t + 1 < nt) sts(buf ^ 1);
        __syncthreads();
    }

    // --- epilogue ----------------------------------------------------------
    float bv[8];
#pragma unroll
    for (int j = 0; j < 4; j++) {
        bv[j]     = bias ? bias[n0 + tx * 4 + j]      : 0.f;
        bv[4 + j] = bias ? bias[n0 + 64 + tx * 4 + j] : 0.f;
    }

#pragma unroll
    for (int i = 0; i < TM; i++) {
        const int r = m0 + ty * TM + i;
        if (r < M) {
            const float rs = rowscale ? rowscale[r] : 1.f;
            float w[8];
#pragma unroll
            for (int j = 0; j < 4; j++) {
                unsigned lo, hi;
                asm("mov.b64 {%0,%1}, %2;" : "=r"(lo), "=r"(hi) : "l"(acc[i][j]));
                w[2 * j]     = __uint_as_float(lo) + bv[2 * j]     * rs;
                w[2 * j + 1] = __uint_as_float(hi) + bv[2 * j + 1] * rs;
            }
            float* c0 = C + (size_t)r * N + n0 + tx * 4;
            float* c1 = c0 + 64;
            if (EPI >= 2) {
                float4 p0 = *reinterpret_cast<float4*>(c0);
                float4 p1 = *reinterpret_cast<float4*>(c1);
                w[0] += p0.x; w[1] += p0.y; w[2] += p0.z; w[3] += p0.w;
                w[4] += p1.x; w[5] += p1.y; w[6] += p1.z; w[7] += p1.w;
            }
            if (EPI == 3) {
#pragma unroll
                for (int j = 0; j < 8; j++) w[j] = fmaxf(w[j], 0.f);
            }
            *reinterpret_cast<float4*>(c0) = make_float4(w[0], w[1], w[2], w[3]);
            *reinterpret_cast<float4*>(c1) = make_float4(w[4], w[5], w[6], w[7]);
        }
    }
}

// ---------------------------------------------------------------------------
// Elementwise / graph kernels (both branches fused)
// ---------------------------------------------------------------------------
__global__ void zero_kernel(float4* __restrict__ p, int n4) {
    int i = blockIdx.x * blockDim.x + threadIdx.x;
    if (i < n4) p[i] = make_float4(0.f, 0.f, 0.f, 0.f);
}

__global__ void deg_kernel(const int* __restrict__ ei1, const int* __restrict__ ei2,
                           float* __restrict__ deg) {
    int e = blockIdx.x * blockDim.x + threadIdx.x;
    if (e >= 2 * NE) return;
    int t = (e < NE) ? ei1[e] : (ei2[e - NE] + NN);
    atomicAdd(deg + t, 1.0f);
}

// Per edge: t = relu(A[src] + B[tgt]) (256 floats) ; T[tgt] += t.
// 64 threads per edge (one float4 each). Both branches in one grid.
__global__ void edge_kernel(const int* __restrict__ ei1, const int* __restrict__ ei2,
                            const float* __restrict__ A, const float* __restrict__ B,
                            float* __restrict__ T) {
    long long gid = (long long)blockIdx.x * blockDim.x + threadIdx.x;
    int e    = (int)(gid >> 6);
    int lane = (int)(gid & 63);
    if (e >= 2 * NE) return;
    int tgt, src;
    if (e < NE) { tgt = ei1[e];      src = ei1[NE + e]; }
    else        { e -= NE; tgt = ei2[e] + NN; src = ei2[NE + e] + NN; }
    float4 a = *(reinterpret_cast<const float4*>(A + (size_t)src * 256) + lane);
    float4 b = *(reinterpret_cast<const float4*>(B + (size_t)tgt * 256) + lane);
    float4 t;
    t.x = fmaxf(a.x + b.x, 0.f);
    t.y = fmaxf(a.y + b.y, 0.f);
    t.z = fmaxf(a.z + b.z, 0.f);
    t.w = fmaxf(a.w + b.w, 0.f);
    atomicAdd(reinterpret_cast<float4*>(T + (size_t)tgt * 256) + lane, t);
}

// v = sigmoid(nx[:, :128]) * nx[:, 128:] ; gg[graph(node)] += v
__global__ void gatepool_kernel(const float* __restrict__ nx,
                                const int* __restrict__ batch1,
                                const int* __restrict__ batch2,
                                float* __restrict__ gg) {
    int i = blockIdx.x * blockDim.x + threadIdx.x;
    if (i >= NB * 32) return;
    int node = i >> 5;
    int c4   = i & 31;
    const float4* row = reinterpret_cast<const float4*>(nx + (size_t)node * 256);
    float4 g = row[c4];
    float4 v = row[32 + c4];
    float4 o;
    o.x = v.x / (1.f + expf(-g.x));
    o.y = v.y / (1.f + expf(-g.y));
    o.z = v.z / (1.f + expf(-g.z));
    o.w = v.w / (1.f + expf(-g.w));
    int b = (node < NN) ? batch1[node] : (batch2[node - NN] + NG);
    atomicAdd(reinterpret_cast<float4*>(gg + (size_t)b * HD) + c4, o);
}

// ---------------------------------------------------------------------------
// Host orchestration — both branches stacked (M = 20000 GEMMs, shared weights)
// ---------------------------------------------------------------------------
extern "C" void kernel_launch(void* const* d_in, const int* in_sizes, int n_in,
                              void* d_out, int out_size)
{
    (void)in_sizes; (void)n_in; (void)out_size;

    const float* x1      = (const float*)d_in[0];
    const int*   ei1     = (const int*)  d_in[1];
    const int*   batch1  = (const int*)  d_in[2];
    const float* x2      = (const float*)d_in[3];
    const int*   ei2     = (const int*)  d_in[4];
    const int*   batch2  = (const int*)  d_in[5];
    const float* W_emb   = (const float*)d_in[6];
    const float* b_emb   = (const float*)d_in[7];
    const float* msg_W1  = (const float*)d_in[8];
    const float* msg_b1  = (const float*)d_in[9];
    const float* msg_W2  = (const float*)d_in[10];
    const float* msg_b2  = (const float*)d_in[11];
    const float* upd_W1  = (const float*)d_in[12];
    const float* upd_b1  = (const float*)d_in[13];
    const float* upd_W2  = (const float*)d_in[14];
    const float* upd_b2  = (const float*)d_in[15];
    const float* node_W  = (const float*)d_in[16];
    const float* node_b  = (const float*)d_in[17];
    const float* graph_W = (const float*)d_in[18];
    const float* graph_b = (const float*)d_in[19];

    void *ph, *pA, *pB, *pT, *pdg, *pgg;
    cudaGetSymbolAddress(&ph,  g_h);
    cudaGetSymbolAddress(&pA,  g_A);
    cudaGetSymbolAddress(&pB,  g_B);
    cudaGetSymbolAddress(&pT,  g_T);
    cudaGetSymbolAddress(&pdg, g_dg);
    cudaGetSymbolAddress(&pgg, g_gg);
    float* h  = (float*)ph;
    float* A  = (float*)pA;
    float* B  = (float*)pB;
    float* T  = (float*)pT;
    float* dg = (float*)pdg;
    float* gg = (float*)pgg;

    const dim3 gBig ((NB + 127) / 128, 2);   // BM=128, N=256 -> 314 blocks
    const dim3 gMed ((NB + 63) / 64, 1);     // BM=64,  N=128 -> 313 blocks
    const dim3 gEmb ((NN + 63) / 64, 1);     // per-branch embedding

    // h = x @ W_emb + b_emb  (two source buffers, stacked destination)
    sgemm<0, 4><<<gEmb, 256>>>(x1, W_emb, h,            b_emb, nullptr, NN, HD, 64);
    sgemm<0, 4><<<gEmb, 256>>>(x2, W_emb, h + (size_t)NN * HD, b_emb, nullptr, NN, HD, 64);

    // per-node in-degree (both branches)
    zero_kernel<<<(NB / 4 + 255) / 256, 256>>>((float4*)dg, NB / 4);
    deg_kernel<<<(2 * NE + 255) / 256, 256>>>(ei1, ei2, dg);

    for (int l = 0; l < 2; l++) {
        const float* Wm1 = msg_W1 + (size_t)l * 256 * 256;
        const float* bm1 = msg_b1 + (size_t)l * 256;
        const float* Wm2 = msg_W2 + (size_t)l * 256 * 256;
        const float* bm2 = msg_b2 + (size_t)l * 256;
        const float* Wu1 = upd_W1 + (size_t)l * 384 * 256;
        const float* bu1 = upd_b1 + (size_t)l * 256;
        const float* Wu2 = upd_W2 + (size_t)l * 256 * 128;
        const float* bu2 = upd_b2 + (size_t)l * 128;

        // A = h @ W1[:128,:] + b1 ; B = h @ W1[128:,:]   (node-level hoist)
        sgemm<0, 8><<<gBig, 256>>>(h, Wm1,             A, bm1,     nullptr, NB, 256, 128);
        sgemm<0, 8><<<gBig, 256>>>(h, Wm1 + 128 * 256, B, nullptr, nullptr, NB, 256, 128);

        // T[n] = sum_{e: tgt=n} relu(A[src] + B[tgt])
        zero_kernel<<<(NB * 64 + 255) / 256, 256>>>((float4*)T, NB * 64);
        edge_kernel<<<(2 * NE * 64 + 255) / 256, 256>>>(ei1, ei2, A, B, T);

        // agg = T @ W2 + deg * b2   (hoist past segment-sum) -> A
        sgemm<0, 8><<<gBig, 256>>>(T, Wm2, A, bm2, dg, NB, 256, 256);

        // u1 = relu(agg @ Wu1[:256] + h @ Wu1[256:] + bu1)   (concat fused away)
        sgemm<0, 8><<<gBig, 256>>>(A, Wu1,             B, bu1,     nullptr, NB, 256, 256);
        sgemm<3, 8><<<gBig, 256>>>(h, Wu1 + 256 * 256, B, nullptr, nullptr, NB, 256, 128);

        // h += u1 @ uW2 + ub2       (residual epilogue)
        sgemm<2, 4><<<gMed, 256>>>(B, Wu2, h, bu2, nullptr, NB, 128, 256);
    }

    // readout: nx = h @ node_W + node_b -> T ; gate+pool ; graph GEMM
    sgemm<0, 8><<<gBig, 256>>>(h, node_W, T, node_b, nullptr, NB, 256, 128);
    zero_kernel<<<(2 * NG * 32 + 255) / 256, 256>>>((float4*)gg, 2 * NG * 32);
    gatepool_kernel<<<(NB * 32 + 255) / 256, 256>>>(T, batch1, batch2, gg);
    // out[2,32,128] contiguous = [64,128]
    sgemm<0, 4><<<dim3(1, 1), 256>>>(gg, graph_W, (float*)d_out, graph_b, nullptr,
                                     2 * NG, HD, HD);
}

// round 9
// speedup vs baseline: 2.0636x; 2.0636x over previous
#include <cuda_runtime.h>
#include <math.h>

#define NN 10000   // nodes per branch
#define NE 160000  // edges per branch
#define NG 32      // graphs per branch
#define HD 128     // hidden
#define NB (2*NN)  // stacked nodes

// ---------------------------------------------------------------------------
// Static device scratch (allocation-free rule)
// ---------------------------------------------------------------------------
__device__ float g_AB[NB * 512];    // [A_row(256) | B_row(256)] per node (msg W1 out)
__device__ float g_UI[NB * 384];    // cols 0:256 = agg, cols 256:384 = h (persistent)
__device__ float g_T [NB * 256];    // edge sums / u1 / nx scratch
__device__ float g_dg[NB];          // in-degree (float)
__device__ float g_gg[2 * NG * HD]; // pooled per-graph [64,128]
__device__ int   g_cnt[NB];         // counts, then scatter cursor
__device__ int   g_off[NB + 1];     // CSR offsets
__device__ int   g_src[2 * NE];     // CSR source lists
__device__ float g_W [582656];      // packed tf32-rounded weights + bcat

// packed weight offsets (floats)
#define OFF_EMB    0
#define OFF_NODE   8192
#define OFF_GRAPH  40960
#define OFF_LAYER(l) (57344 + (l) * 262144)
#define OFF_WCAT   0
#define OFF_WM2    65536
#define OFF_WU1    131072
#define OFF_WU2    229376
#define OFF_BCAT   581632
#define W_TOTAL    582656

// ---------------------------------------------------------------------------
// helpers
// ---------------------------------------------------------------------------
__device__ __forceinline__ float round_tf32(float f) {
    unsigned u;
    asm("cvt.rna.tf32.f32 %0, %1;" : "=r"(u) : "f"(f));
    return __uint_as_float(u);
}
__device__ __forceinline__ void cp16(void* smem, const void* g, int sz) {
    unsigned s = (unsigned)__cvta_generic_to_shared(smem);
    asm volatile("cp.async.cg.shared.global [%0], [%1], 16, %2;"
                 :: "r"(s), "l"(g), "r"(sz));
}

// ---------------------------------------------------------------------------
// TF32 tensor-core GEMM: C[M,N] = op(A[M,K] @ B[K,N] + bias)
//   EPI 0: C = acc + bias (bias optionally scaled per-row by rowscale)
//   EPI 1: C = relu(acc + bias)
//   EPI 2: C = C + acc + bias        (residual)
// BM=128, BN=128, BK=16, 256 threads (8 warps, 2x4), warp tile 64x32,
// mma.m16n8k4 tf32. A-fragments cvt.rna'd in-loop; B (weights) pre-rounded.
// Requires N%128==0, K%16==0. A row stride lda, C row stride ldc, B stride N.
// ---------------------------------------------------------------------------
template <int EPI>
__global__ __launch_bounds__(256, 2)
void tgemm(const float* __restrict__ Ag, int lda,
           const float* __restrict__ Bg,
           float* __restrict__ C, int ldc,
           const float* __restrict__ bias,
           const float* __restrict__ rowscale,
           int M, int N, int K)
{
    constexpr int BM = 128, BK = 16;
    __shared__ __align__(16) float As[2][BM][20];   // [m][k] pad->conflict-free frags
    __shared__ __align__(16) float Bs[2][BK][136];  // [k][n] pad 8

    const int tid = threadIdx.x;
    const int l = tid & 31, w = tid >> 5;
    const int wm = (w >> 2) * 64, wn = (w & 3) * 32;
    const int m0 = blockIdx.x * BM, n0 = blockIdx.y * 128;

    float acc[4][4][4];
#pragma unroll
    for (int a = 0; a < 4; a++)
#pragma unroll
        for (int b = 0; b < 4; b++)
#pragma unroll
            for (int c = 0; c < 4; c++) acc[a][b][c] = 0.f;

    auto docopy = [&](int t, int buf) {
#pragma unroll
        for (int i = 0; i < 2; i++) {                 // A: 128x16 = 512 float4
            int idx = tid + i * 256;
            int m = idx >> 2, k4 = idx & 3;
            const float* src = Ag + (size_t)(m0 + m) * lda + t * BK + k4 * 4;
            int sz = (m0 + m < M) ? 16 : 0;
            if (!sz) src = Ag;                         // safe dummy address
            cp16(&As[buf][m][k4 * 4], src, sz);
        }
#pragma unroll
        for (int i = 0; i < 2; i++) {                 // B: 16x128 = 512 float4
            int idx = tid + i * 256;
            int k = idx >> 5, n4 = idx & 31;
            cp16(&Bs[buf][k][n4 * 4],
                 Bg + (size_t)(t * BK + k) * N + n0 + n4 * 4, 16);
        }
        asm volatile("cp.async.commit_group;");
    };

    docopy(0, 0);
    const int nt = K / BK;
    int buf = 0;
    for (int t = 0; t < nt; t++) {
        if (t + 1 < nt) {
            docopy(t + 1, buf ^ 1);
            asm volatile("cp.async.wait_group 1;");
        } else {
            asm volatile("cp.async.wait_group 0;");
        }
        __syncthreads();

#pragma unroll
        for (int j = 0; j < 4; j++) {                 // 4 k4-steps per BK=16
            unsigned ua0[4], ua1[4], ub[4];
#pragma unroll
            for (int mt = 0; mt < 4; mt++) {
                float f0 = As[buf][wm + mt * 16 +     (l >> 2)][j * 4 + (l & 3)];
                float f1 = As[buf][wm + mt * 16 + 8 + (l >> 2)][j * 4 + (l & 3)];
                asm("cvt.rna.tf32.f32 %0, %1;" : "=r"(ua0[mt]) : "f"(f0));
                asm("cvt.rna.tf32.f32 %0, %1;" : "=r"(ua1[mt]) : "f"(f1));
            }
#pragma unroll
            for (int q = 0; q < 4; q++)
                ub[q] = __float_as_uint(Bs[buf][j * 4 + (l & 3)][wn + q * 8 + (l >> 2)]);
#pragma unroll
            for (int mt = 0; mt < 4; mt++)
#pragma unroll
                for (int q = 0; q < 4; q++)
                    asm volatile(
                        "mma.sync.aligned.m16n8k4.row.col.f32.tf32.tf32.f32 "
                        "{%0,%1,%2,%3}, {%4,%5}, {%6}, {%0,%1,%2,%3};"
                        : "+f"(acc[mt][q][0]), "+f"(acc[mt][q][1]),
                          "+f"(acc[mt][q][2]), "+f"(acc[mt][q][3])
                        : "r"(ua0[mt]), "r"(ua1[mt]), "r"(ub[q]));
        }
        __syncthreads();
        buf ^= 1;
    }

    // epilogue
#pragma unroll
    for (int mt = 0; mt < 4; mt++) {
#pragma unroll
        for (int half = 0; half < 2; half++) {
            const int r = m0 + wm + mt * 16 + half * 8 + (l >> 2);
            if (r < M) {
                const float rs = rowscale ? rowscale[r] : 1.f;
#pragma unroll
                for (int q = 0; q < 4; q++) {
                    const int c = n0 + wn + q * 8 + 2 * (l & 3);
                    float v0 = acc[mt][q][half * 2 + 0];
                    float v1 = acc[mt][q][half * 2 + 1];
                    if (bias) { v0 += bias[c] * rs; v1 += bias[c + 1] * rs; }
                    float* cp = C + (size_t)r * ldc + c;
                    if (EPI == 2) { v0 += cp[0]; v1 += cp[1]; }
                    if (EPI == 1) { v0 = fmaxf(v0, 0.f); v1 = fmaxf(v1, 0.f); }
                    *reinterpret_cast<float2*>(cp) = make_float2(v0, v1);
                }
            }
        }
    }
}

// ---------------------------------------------------------------------------
// Weight prep: round to tf32 and pack (Wcat = [W1_top | W1_bot] cols)
// ---------------------------------------------------------------------------
__global__ void prep_weights(const float* __restrict__ W_emb,
                             const float* __restrict__ node_W,
                             const float* __restrict__ graph_W,
                             const float* __restrict__ mW1,
                             const float* __restrict__ mb1,
                             const float* __restrict__ mW2,
                             const float* __restrict__ uW1,
                             const float* __restrict__ uW2,
                             float* __restrict__ gw)
{
    int i = blockIdx.x * 256 + threadIdx.x;
    if (i >= W_TOTAL) return;
    float v;
    if (i < OFF_NODE)        v = round_tf32(W_emb[i - OFF_EMB]);
    else if (i < OFF_GRAPH)  v = round_tf32(node_W[i - OFF_NODE]);
    else if (i < 57344)      v = round_tf32(graph_W[i - OFF_GRAPH]);
    else if (i < OFF_BCAT) {
        int j = i - 57344;
        int lay = j / 262144, r = j % 262144;
        if (r < 65536) {                       // Wcat: [128][512]
            int k = r >> 9, c = r & 511;
            float s = (c < 256) ? mW1[(size_t)lay * 65536 + k * 256 + c]
                                : mW1[(size_t)lay * 65536 + (k + 128) * 256 + (c - 256)];
            v = round_tf32(s);
        } else if (r < 131072) v = round_tf32(mW2[(size_t)lay * 65536 + (r - 65536)]);
        else if (r < 229376)   v = round_tf32(uW1[(size_t)lay * 98304 + (r - 131072)]);
        else                   v = round_tf32(uW2[(size_t)lay * 32768 + (r - 229376)]);
    } else {                                   // bcat: fp32, [bm1 | zeros]
        int j = i - OFF_BCAT;
        int lay = j >> 9, c = j & 511;
        v = (c < 256) ? mb1[lay * 256 + c] : 0.f;
    }
    gw[i] = v;
}

// ---------------------------------------------------------------------------
// CSR construction (one-time; reused by both layers)
// ---------------------------------------------------------------------------
__global__ void zero_kernel(float4* __restrict__ p, int n4) {
    int i = blockIdx.x * blockDim.x + threadIdx.x;
    if (i < n4) p[i] = make_float4(0.f, 0.f, 0.f, 0.f);
}

__global__ void count_kernel(const int* __restrict__ ei1, const int* __restrict__ ei2,
                             int* __restrict__ cnt) {
    int e = blockIdx.x * blockDim.x + threadIdx.x;
    if (e >= 2 * NE) return;
    int t = (e < NE) ? ei1[e] : (ei2[e - NE] + NN);
    atomicAdd(cnt + t, 1);
}

// single-block exclusive scan of cnt[NB] -> off, cursor(=cnt), dg(float)
__global__ void scan_kernel(int* __restrict__ cnt, int* __restrict__ off,
                            float* __restrict__ dg) {
    __shared__ int sm[1024];
    __shared__ int s_carry;
    const int t = threadIdx.x;
    if (t == 0) s_carry = 0;
    __syncthreads();
    for (int base = 0; base < NB; base += 1024) {
        int i = base + t;
        int v = (i < NB) ? cnt[i] : 0;
        sm[t] = v;
        __syncthreads();
        for (int d = 1; d < 1024; d <<= 1) {
            int x = (t >= d) ? sm[t - d] : 0;
            __syncthreads();
            sm[t] += x;
            __syncthreads();
        }
        int carry = s_carry;
        int excl = carry + sm[t] - v;
        if (i < NB) { off[i] = excl; cnt[i] = excl; dg[i] = (float)v; }
        __syncthreads();
        if (t == 1023) s_carry = carry + sm[t];
        __syncthreads();
    }
    if (t == 0) off[NB] = s_carry;
}

__global__ void scatter_kernel(const int* __restrict__ ei1, const int* __restrict__ ei2,
                               int* __restrict__ cursor, int* __restrict__ srcs) {
    int e = blockIdx.x * blockDim.x + threadIdx.x;
    if (e >= 2 * NE) return;
    int t, s;
    if (e < NE) { t = ei1[e];      s = ei1[NE + e]; }
    else        { int e2 = e - NE; t = ei2[e2] + NN; s = ei2[NE + e2] + NN; }
    int p = atomicAdd(cursor + t, 1);
    srcs[p] = s;
}

// ---------------------------------------------------------------------------
// Edge aggregation (CSR): T[n] = sum_{src in csr(n)} relu(A[src] + B[n])
// 64 threads per node (one float4 each); no atomics, no pre-zero.
// AB rows: [A(256) | B(256)] -> 128 float4; A at +0, B at +64.
// ---------------------------------------------------------------------------
__global__ void edge_csr(const int* __restrict__ off, const int* __restrict__ srcs,
                         const float* __restrict__ AB, float* __restrict__ T) {
    const int node = blockIdx.x * 4 + (threadIdx.x >> 6);
    const int lane = threadIdx.x & 63;
    const float4* ABf = reinterpret_cast<const float4*>(AB);
    const int p0 = off[node], p1 = off[node + 1];
    float4 b = ABf[(size_t)node * 128 + 64 + lane];
    float4 acc = make_float4(0.f, 0.f, 0.f, 0.f);
    for (int p = p0; p < p1; ++p) {
        int s = srcs[p];
        float4 a = ABf[(size_t)s * 128 + lane];
        acc.x += fmaxf(a.x + b.x, 0.f);
        acc.y += fmaxf(a.y + b.y, 0.f);
        acc.z += fmaxf(a.z + b.z, 0.f);
        acc.w += fmaxf(a.w + b.w, 0.f);
    }
    reinterpret_cast<float4*>(T)[(size_t)node * 64 + lane] = acc;
}

// v = sigmoid(nx[:, :128]) * nx[:, 128:] ; gg[graph(node)] += v
__global__ void gatepool_kernel(const float* __restrict__ nx,
                                const int* __restrict__ batch1,
                                const int* __restrict__ batch2,
                                float* __restrict__ gg) {
    int i = blockIdx.x * blockDim.x + threadIdx.x;
    if (i >= NB * 32) return;
    int node = i >> 5;
    int c4   = i & 31;
    const float4* row = reinterpret_cast<const float4*>(nx + (size_t)node * 256);
    float4 g = row[c4];
    float4 v = row[32 + c4];
    float4 o;
    o.x = v.x / (1.f + expf(-g.x));
    o.y = v.y / (1.f + expf(-g.y));
    o.z = v.z / (1.f + expf(-g.z));
    o.w = v.w / (1.f + expf(-g.w));
    int b = (node < NN) ? batch1[node] : (batch2[node - NN] + NG);
    atomicAdd(reinterpret_cast<float4*>(gg + (size_t)b * HD) + c4, o);
}

// ---------------------------------------------------------------------------
// Host orchestration
// ---------------------------------------------------------------------------
extern "C" void kernel_launch(void* const* d_in, const int* in_sizes, int n_in,
                              void* d_out, int out_size)
{
    (void)in_sizes; (void)n_in; (void)out_size;

    const float* x1      = (const float*)d_in[0];
    const int*   ei1     = (const int*)  d_in[1];
    const int*   batch1  = (const int*)  d_in[2];
    const float* x2      = (const float*)d_in[3];
    const int*   ei2     = (const int*)  d_in[4];
    const int*   batch2  = (const int*)  d_in[5];
    const float* W_emb   = (const float*)d_in[6];
    const float* b_emb   = (const float*)d_in[7];
    const float* msg_W1  = (const float*)d_in[8];
    const float* msg_b1  = (const float*)d_in[9];
    const float* msg_W2  = (const float*)d_in[10];
    const float* msg_b2  = (const float*)d_in[11];
    const float* upd_W1  = (const float*)d_in[12];
    const float* upd_b1  = (const float*)d_in[13];
    const float* upd_W2  = (const float*)d_in[14];
    const float* upd_b2  = (const float*)d_in[15];
    const float* node_b  = (const float*)d_in[17];
    const float* graph_b = (const float*)d_in[19];

    void *pAB, *pUI, *pT, *pdg, *pgg, *pcnt, *poff, *psrc, *pW;
    cudaGetSymbolAddress(&pAB,  g_AB);
    cudaGetSymbolAddress(&pUI,  g_UI);
    cudaGetSymbolAddress(&pT,   g_T);
    cudaGetSymbolAddress(&pdg,  g_dg);
    cudaGetSymbolAddress(&pgg,  g_gg);
    cudaGetSymbolAddress(&pcnt, g_cnt);
    cudaGetSymbolAddress(&poff, g_off);
    cudaGetSymbolAddress(&psrc, g_src);
    cudaGetSymbolAddress(&pW,   g_W);
    float* AB  = (float*)pAB;
    float* UI  = (float*)pUI;
    float* T   = (float*)pT;
    float* dg  = (float*)pdg;
    float* gg  = (float*)pgg;
    int*   cnt = (int*)pcnt;
    int*   off = (int*)poff;
    int*   src = (int*)psrc;
    float* gw  = (float*)pW;

    float* h = UI + 256;                 // h lives at UI cols [256,384), stride 384

    // 0. round + pack weights
    prep_weights<<<(W_TOTAL + 255) / 256, 256>>>(
        W_emb, (const float*)d_in[16], (const float*)d_in[18],
        msg_W1, msg_b1, msg_W2, upd_W1, upd_W2, gw);

    // 1. CSR build (shared by both layers)
    zero_kernel<<<(NB / 4 + 255) / 256, 256>>>((float4*)cnt, NB / 4);
    count_kernel<<<(2 * NE + 255) / 256, 256>>>(ei1, ei2, cnt);
    scan_kernel<<<1, 1024>>>(cnt, off, dg);
    scatter_kernel<<<(2 * NE + 255) / 256, 256>>>(ei1, ei2, cnt, src);

    // 2. embedding: h = x @ W_emb + b_emb  (into UI[:,256:384])
    const dim3 gEmb((NN + 127) / 128, 1);
    tgemm<0><<<gEmb, 256>>>(x1, 64, gw + OFF_EMB, h, 384, b_emb, nullptr, NN, HD, 64);
    tgemm<0><<<gEmb, 256>>>(x2, 64, gw + OFF_EMB, h + (size_t)NN * 384, 384,
                            b_emb, nullptr, NN, HD, 64);

    const int GM = (NB + 127) / 128;     // 157

    for (int l = 0; l < 2; l++) {
        const float* Wcat = gw + OFF_LAYER(l) + OFF_WCAT;
        const float* Wm2  = gw + OFF_LAYER(l) + OFF_WM2;
        const float* Wu1  = gw + OFF_LAYER(l) + OFF_WU1;
        const float* Wu2  = gw + OFF_LAYER(l) + OFF_WU2;
        const float* bcat = gw + OFF_BCAT + (size_t)l * 512;
        const float* bm2  = msg_b2 + (size_t)l * 256;
        const float* bu1  = upd_b1 + (size_t)l * 256;
        const float* bu2  = upd_b2 + (size_t)l * 128;

        // [A|B] = h @ Wcat + bcat              [2N,512]
        tgemm<0><<<dim3(GM, 4), 256>>>(h, 384, Wcat, AB, 512, bcat, nullptr,
                                       NB, 512, 128);
        // T[n] = sum relu(A[src] + B[n])       (CSR, no atomics)
        edge_csr<<<NB / 4, 256>>>(off, src, AB, T);
        // agg = T @ Wm2 + deg*b2  -> UI[:,0:256]
        tgemm<0><<<dim3(GM, 2), 256>>>(T, 256, Wm2, UI, 384, bm2, dg,
                                       NB, 256, 256);
        // u1 = relu(UI @ Wu1 + bu1)            (K=384, concat-free) -> T
        tgemm<1><<<dim3(GM, 2), 256>>>(UI, 384, Wu1, T, 256, bu1, nullptr,
                                       NB, 256, 384);
        // h += u1 @ Wu2 + bu2                  (residual, ldc=384)
        tgemm<2><<<dim3(GM, 1), 256>>>(T, 256, Wu2, h, 384, bu2, nullptr,
                                       NB, 128, 256);
    }

    // 3. readout
    tgemm<0><<<dim3(GM, 2), 256>>>(h, 384, gw + OFF_NODE, AB, 256, node_b, nullptr,
                                   NB, 256, 128);
    zero_kernel<<<(2 * NG * 32 + 255) / 256, 256>>>((float4*)gg, 2 * NG * 32);
    gatepool_kernel<<<(NB * 32 + 255) / 256, 256>>>(AB, batch1, batch2, gg);
    tgemm<0><<<dim3(1, 1), 256>>>(gg, 128, gw + OFF_GRAPH, (float*)d_out, 128,
                                  graph_b, nullptr, 2 * NG, HD, 128);
}

// round 10
// speedup vs baseline: 2.0697x; 1.0030x over previous
#include <cuda_runtime.h>
#include <math.h>

#define NN 10000   // nodes per branch
#define NE 160000  // edges per branch
#define NG 32      // graphs per branch
#define HD 128     // hidden
#define NB (2*NN)  // stacked nodes

// ---------------------------------------------------------------------------
// Static device scratch (allocation-free rule)
// ---------------------------------------------------------------------------
__device__ float g_AB[NB * 512];    // [A_row(256) | B_row(256)] per node (msg W1 out)
__device__ float g_UI[NB * 384];    // cols 0:256 = agg, cols 256:384 = h (persistent)
__device__ float g_T [NB * 256];    // edge sums / u1 / nx scratch
__device__ float g_dg[NB];          // in-degree (float)
__device__ float g_gg[2 * NG * HD]; // pooled per-graph [64,128]
__device__ int   g_cnt[NB];         // counts, then scatter cursor
__device__ int   g_off[NB + 1];     // CSR offsets
__device__ int   g_src[2 * NE];     // CSR source lists
__device__ float g_W [582656];      // packed tf32-rounded weights + bcat

// packed weight offsets (floats)
#define OFF_EMB    0
#define OFF_NODE   8192
#define OFF_GRAPH  40960
#define OFF_LAYER(l) (57344 + (l) * 262144)
#define OFF_WCAT   0
#define OFF_WM2    65536
#define OFF_WU1    131072
#define OFF_WU2    229376
#define OFF_BCAT   581632
#define W_TOTAL    582656

// ---------------------------------------------------------------------------
// helpers
// ---------------------------------------------------------------------------
__device__ __forceinline__ float round_tf32(float f) {
    unsigned u;
    asm("cvt.rna.tf32.f32 %0, %1;" : "=r"(u) : "f"(f));
    return __uint_as_float(u);
}
__device__ __forceinline__ void cp16(void* smem, const void* g, int sz) {
    unsigned s = (unsigned)__cvta_generic_to_shared(smem);
    asm volatile("cp.async.cg.shared.global [%0], [%1], 16, %2;"
                 :: "r"(s), "l"(g), "r"(sz));
}

// ---------------------------------------------------------------------------
// TF32 tensor-core GEMM: C[M,N] = op(A[M,K] @ B[K,N] + bias)
//   EPI 0: C = acc + bias (bias optionally scaled per-row by rowscale)
//   EPI 1: C = relu(acc + bias)
//   EPI 2: C = C + acc + bias        (residual)
// BM=128, BN=128, BK=16, 256 threads (8 warps, 2x4), warp tile 64x32,
// mma.m16n8k4 tf32. A-fragments cvt.rna'd in-loop; B (weights) pre-rounded.
// Requires N%128==0, K%16==0. A row stride lda, C row stride ldc, B stride N.
// ---------------------------------------------------------------------------
template <int EPI>
__global__ __launch_bounds__(256, 2)
void tgemm(const float* __restrict__ Ag, int lda,
           const float* __restrict__ Bg,
           float* __restrict__ C, int ldc,
           const float* __restrict__ bias,
           const float* __restrict__ rowscale,
           int M, int N, int K)
{
    constexpr int BM = 128, BK = 16;
    __shared__ __align__(16) float As[2][BM][20];   // [m][k] pad->conflict-free frags
    __shared__ __align__(16) float Bs[2][BK][136];  // [k][n] pad 8

    const int tid = threadIdx.x;
    const int l = tid & 31, w = tid >> 5;
    const int wm = (w >> 2) * 64, wn = (w & 3) * 32;
    const int m0 = blockIdx.x * BM, n0 = blockIdx.y * 128;

    float acc[4][4][4];
#pragma unroll
    for (int a = 0; a < 4; a++)
#pragma unroll
        for (int b = 0; b < 4; b++)
#pragma unroll
            for (int c = 0; c < 4; c++) acc[a][b][c] = 0.f;

    auto docopy = [&](int t, int buf) {
#pragma unroll
        for (int i = 0; i < 2; i++) {                 // A: 128x16 = 512 float4
            int idx = tid + i * 256;
            int m = idx >> 2, k4 = idx & 3;
            const float* src = Ag + (size_t)(m0 + m) * lda + t * BK + k4 * 4;
            int sz = (m0 + m < M) ? 16 : 0;
            if (!sz) src = Ag;                         // safe dummy address
            cp16(&As[buf][m][k4 * 4], src, sz);
        }
#pragma unroll
        for (int i = 0; i < 2; i++) {                 // B: 16x128 = 512 float4
            int idx = tid + i * 256;
            int k = idx >> 5, n4 = idx & 31;
            cp16(&Bs[buf][k][n4 * 4],
                 Bg + (size_t)(t * BK + k) * N + n0 + n4 * 4, 16);
        }
        asm volatile("cp.async.commit_group;");
    };

    docopy(0, 0);
    const int nt = K / BK;
    int buf = 0;
    for (int t = 0; t < nt; t++) {
        if (t + 1 < nt) {
            docopy(t + 1, buf ^ 1);
            asm volatile("cp.async.wait_group 1;");
        } else {
            asm volatile("cp.async.wait_group 0;");
        }
        __syncthreads();

#pragma unroll
        for (int j = 0; j < 4; j++) {                 // 4 k4-steps per BK=16
            unsigned ua0[4], ua1[4], ub[4];
#pragma unroll
            for (int mt = 0; mt < 4; mt++) {
                float f0 = As[buf][wm + mt * 16 +     (l >> 2)][j * 4 + (l & 3)];
                float f1 = As[buf][wm + mt * 16 + 8 + (l >> 2)][j * 4 + (l & 3)];
                asm("cvt.rna.tf32.f32 %0, %1;" : "=r"(ua0[mt]) : "f"(f0));
                asm("cvt.rna.tf32.f32 %0, %1;" : "=r"(ua1[mt]) : "f"(f1));
            }
#pragma unroll
            for (int q = 0; q < 4; q++)
                ub[q] = __float_as_uint(Bs[buf][j * 4 + (l & 3)][wn + q * 8 + (l >> 2)]);
#pragma unroll
            for (int mt = 0; mt < 4; mt++)
#pragma unroll
                for (int q = 0; q < 4; q++)
                    asm volatile(
                        "mma.sync.aligned.m16n8k4.row.col.f32.tf32.tf32.f32 "
                        "{%0,%1,%2,%3}, {%4,%5}, {%6}, {%0,%1,%2,%3};"
                        : "+f"(acc[mt][q][0]), "+f"(acc[mt][q][1]),
                          "+f"(acc[mt][q][2]), "+f"(acc[mt][q][3])
                        : "r"(ua0[mt]), "r"(ua1[mt]), "r"(ub[q]));
        }
        __syncthreads();
        buf ^= 1;
    }

    // epilogue
#pragma unroll
    for (int mt = 0; mt < 4; mt++) {
#pragma unroll
        for (int half = 0; half < 2; half++) {
            const int r = m0 + wm + mt * 16 + half * 8 + (l >> 2);
            if (r < M) {
                const float rs = rowscale ? rowscale[r] : 1.f;
#pragma unroll
                for (int q = 0; q < 4; q++) {
                    const int c = n0 + wn + q * 8 + 2 * (l & 3);
                    float v0 = acc[mt][q][half * 2 + 0];
                    float v1 = acc[mt][q][half * 2 + 1];
                    if (bias) { v0 += bias[c] * rs; v1 += bias[c + 1] * rs; }
                    float* cp = C + (size_t)r * ldc + c;
                    if (EPI == 2) { v0 += cp[0]; v1 += cp[1]; }
                    if (EPI == 1) { v0 = fmaxf(v0, 0.f); v1 = fmaxf(v1, 0.f); }
                    *reinterpret_cast<float2*>(cp) = make_float2(v0, v1);
                }
            }
        }
    }
}

// ---------------------------------------------------------------------------
// Weight prep: round to tf32 and pack (Wcat = [W1_top | W1_bot] cols)
// ---------------------------------------------------------------------------
__global__ void prep_weights(const float* __restrict__ W_emb,
                             const float* __restrict__ node_W,
                             const float* __restrict__ graph_W,
                             const float* __restrict__ mW1,
                             const float* __restrict__ mb1,
                             const float* __restrict__ mW2,
                             const float* __restrict__ uW1,
                             const float* __restrict__ uW2,
                             float* __restrict__ gw)
{
    int i = blockIdx.x * 256 + threadIdx.x;
    if (i >= W_TOTAL) return;
    float v;
    if (i < OFF_NODE)        v = round_tf32(W_emb[i - OFF_EMB]);
    else if (i < OFF_GRAPH)  v = round_tf32(node_W[i - OFF_NODE]);
    else if (i < 57344)      v = round_tf32(graph_W[i - OFF_GRAPH]);
    else if (i < OFF_BCAT) {
        int j = i - 57344;
        int lay = j / 262144, r = j % 262144;
        if (r < 65536) {                       // Wcat: [128][512]
            int k = r >> 9, c = r & 511;
            float s = (c < 256) ? mW1[(size_t)lay * 65536 + k * 256 + c]
                                : mW1[(size_t)lay * 65536 + (k + 128) * 256 + (c - 256)];
            v = round_tf32(s);
        } else if (r < 131072) v = round_tf32(mW2[(size_t)lay * 65536 + (r - 65536)]);
        else if (r < 229376)   v = round_tf32(uW1[(size_t)lay * 98304 + (r - 131072)]);
        else                   v = round_tf32(uW2[(size_t)lay * 32768 + (r - 229376)]);
    } else {                                   // bcat: fp32, [bm1 | zeros]
        int j = i - OFF_BCAT;
        int lay = j >> 9, c = j & 511;
        v = (c < 256) ? mb1[lay * 256 + c] : 0.f;
    }
    gw[i] = v;
}

// ---------------------------------------------------------------------------
// CSR construction (one-time; reused by both layers)
// ---------------------------------------------------------------------------
__global__ void zero_kernel(float4* __restrict__ p, int n4) {
    int i = blockIdx.x * blockDim.x + threadIdx.x;
    if (i < n4) p[i] = make_float4(0.f, 0.f, 0.f, 0.f);
}

__global__ void count_kernel(const int* __restrict__ ei1, const int* __restrict__ ei2,
                             int* __restrict__ cnt) {
    int e = blockIdx.x * blockDim.x + threadIdx.x;
    if (e >= 2 * NE) return;
    int t = (e < NE) ? ei1[e] : (ei2[e - NE] + NN);
    atomicAdd(cnt + t, 1);
}

// single-block exclusive scan of cnt[NB] -> off, cursor(=cnt), dg(float)
__global__ void scan_kernel(int* __restrict__ cnt, int* __restrict__ off,
                            float* __restrict__ dg) {
    __shared__ int sm[1024];
    __shared__ int s_carry;
    const int t = threadIdx.x;
    if (t == 0) s_carry = 0;
    __syncthreads();
    for (int base = 0; base < NB; base += 1024) {
        int i = base + t;
        int v = (i < NB) ? cnt[i] : 0;
        sm[t] = v;
        __syncthreads();
        for (int d = 1; d < 1024; d <<= 1) {
            int x = (t >= d) ? sm[t - d] : 0;
            __syncthreads();
            sm[t] += x;
            __syncthreads();
        }
        int carry = s_carry;
        int excl = carry + sm[t] - v;
        if (i < NB) { off[i] = excl; cnt[i] = excl; dg[i] = (float)v; }
        __syncthreads();
        if (t == 1023) s_carry = carry + sm[t];
        __syncthreads();
    }
    if (t == 0) off[NB] = s_carry;
}

__global__ void scatter_kernel(const int* __restrict__ ei1, const int* __restrict__ ei2,
                               int* __restrict__ cursor, int* __restrict__ srcs) {
    int e = blockIdx.x * blockDim.x + threadIdx.x;
    if (e >= 2 * NE) return;
    int t, s;
    if (e < NE) { t = ei1[e];      s = ei1[NE + e]; }
    else        { int e2 = e - NE; t = ei2[e2] + NN; s = ei2[NE + e2] + NN; }
    int p = atomicAdd(cursor + t, 1);
    srcs[p] = s;
}

// ---------------------------------------------------------------------------
// Edge aggregation (CSR): T[n] = sum_{src in csr(n)} relu(A[src] + B[n])
// 64 threads per node (one float4 each); no atomics, no pre-zero.
// AB rows: [A(256) | B(256)] -> 128 float4; A at +0, B at +64.
// ---------------------------------------------------------------------------
__global__ void edge_csr(const int* __restrict__ off, const int* __restrict__ srcs,
                         const float* __restrict__ AB, float* __restrict__ T) {
    const int node = blockIdx.x * 4 + (threadIdx.x >> 6);
    const int lane = threadIdx.x & 63;
    const float4* ABf = reinterpret_cast<const float4*>(AB);
    const int p0 = off[node], p1 = off[node + 1];
    float4 b = ABf[(size_t)node * 128 + 64 + lane];
    float4 acc = make_float4(0.f, 0.f, 0.f, 0.f);
    for (int p = p0; p < p1; ++p) {
        int s = srcs[p];
        float4 a = ABf[(size_t)s * 128 + lane];
        acc.x += fmaxf(a.x + b.x, 0.f);
        acc.y += fmaxf(a.y + b.y, 0.f);
        acc.z += fmaxf(a.z + b.z, 0.f);
        acc.w += fmaxf(a.w + b.w, 0.f);
    }
    reinterpret_cast<float4*>(T)[(size_t)node * 64 + lane] = acc;
}

// v = sigmoid(nx[:, :128]) * nx[:, 128:] ; gg[graph(node)] += v
__global__ void gatepool_kernel(const float* __restrict__ nx,
                                const int* __restrict__ batch1,
                                const int* __restrict__ batch2,
                                float* __restrict__ gg) {
    int i = blockIdx.x * blockDim.x + threadIdx.x;
    if (i >= NB * 32) return;
    int node = i >> 5;
    int c4   = i & 31;
    const float4* row = reinterpret_cast<const float4*>(nx + (size_t)node * 256);
    float4 g = row[c4];
    float4 v = row[32 + c4];
    float4 o;
    o.x = v.x / (1.f + expf(-g.x));
    o.y = v.y / (1.f + expf(-g.y));
    o.z = v.z / (1.f + expf(-g.z));
    o.w = v.w / (1.f + expf(-g.w));
    int b = (node < NN) ? batch1[node] : (batch2[node - NN] + NG);
    atomicAdd(reinterpret_cast<float4*>(gg + (size_t)b * HD) + c4, o);
}

// ---------------------------------------------------------------------------
// Host orchestration
// ---------------------------------------------------------------------------
extern "C" void kernel_launch(void* const* d_in, const int* in_sizes, int n_in,
                              void* d_out, int out_size)
{
    (void)in_sizes; (void)n_in; (void)out_size;

    const float* x1      = (const float*)d_in[0];
    const int*   ei1     = (const int*)  d_in[1];
    const int*   batch1  = (const int*)  d_in[2];
    const float* x2      = (const float*)d_in[3];
    const int*   ei2     = (const int*)  d_in[4];
    const int*   batch2  = (const int*)  d_in[5];
    const float* W_emb   = (const float*)d_in[6];
    const float* b_emb   = (const float*)d_in[7];
    const float* msg_W1  = (const float*)d_in[8];
    const float* msg_b1  = (const float*)d_in[9];
    const float* msg_W2  = (const float*)d_in[10];
    const float* msg_b2  = (const float*)d_in[11];
    const float* upd_W1  = (const float*)d_in[12];
    const float* upd_b1  = (const float*)d_in[13];
    const float* upd_W2  = (const float*)d_in[14];
    const float* upd_b2  = (const float*)d_in[15];
    const float* node_b  = (const float*)d_in[17];
    const float* graph_b = (const float*)d_in[19];

    void *pAB, *pUI, *pT, *pdg, *pgg, *pcnt, *poff, *psrc, *pW;
    cudaGetSymbolAddress(&pAB,  g_AB);
    cudaGetSymbolAddress(&pUI,  g_UI);
    cudaGetSymbolAddress(&pT,   g_T);
    cudaGetSymbolAddress(&pdg,  g_dg);
    cudaGetSymbolAddress(&pgg,  g_gg);
    cudaGetSymbolAddress(&pcnt, g_cnt);
    cudaGetSymbolAddress(&poff, g_off);
    cudaGetSymbolAddress(&psrc, g_src);
    cudaGetSymbolAddress(&pW,   g_W);
    float* AB  = (float*)pAB;
    float* UI  = (float*)pUI;
    float* T   = (float*)pT;
    float* dg  = (float*)pdg;
    float* gg  = (float*)pgg;
    int*   cnt = (int*)pcnt;
    int*   off = (int*)poff;
    int*   src = (int*)psrc;
    float* gw  = (float*)pW;

    float* h = UI + 256;                 // h lives at UI cols [256,384), stride 384

    // 0. round + pack weights
    prep_weights<<<(W_TOTAL + 255) / 256, 256>>>(
        W_emb, (const float*)d_in[16], (const float*)d_in[18],
        msg_W1, msg_b1, msg_W2, upd_W1, upd_W2, gw);

    // 1. CSR build (shared by both layers)
    zero_kernel<<<(NB / 4 + 255) / 256, 256>>>((float4*)cnt, NB / 4);
    count_kernel<<<(2 * NE + 255) / 256, 256>>>(ei1, ei2, cnt);
    scan_kernel<<<1, 1024>>>(cnt, off, dg);
    scatter_kernel<<<(2 * NE + 255) / 256, 256>>>(ei1, ei2, cnt, src);

    // 2. embedding: h = x @ W_emb + b_emb  (into UI[:,256:384])
    const dim3 gEmb((NN + 127) / 128, 1);
    tgemm<0><<<gEmb, 256>>>(x1, 64, gw + OFF_EMB, h, 384, b_emb, nullptr, NN, HD, 64);
    tgemm<0><<<gEmb, 256>>>(x2, 64, gw + OFF_EMB, h + (size_t)NN * 384, 384,
                            b_emb, nullptr, NN, HD, 64);

    const int GM = (NB + 127) / 128;     // 157

    for (int l = 0; l < 2; l++) {
        const float* Wcat = gw + OFF_LAYER(l) + OFF_WCAT;
        const float* Wm2  = gw + OFF_LAYER(l) + OFF_WM2;
        const float* Wu1  = gw + OFF_LAYER(l) + OFF_WU1;
        const float* Wu2  = gw + OFF_LAYER(l) + OFF_WU2;
        const float* bcat = gw + OFF_BCAT + (size_t)l * 512;
        const float* bm2  = msg_b2 + (size_t)l * 256;
        const float* bu1  = upd_b1 + (size_t)l * 256;
        const float* bu2  = upd_b2 + (size_t)l * 128;

        // [A|B] = h @ Wcat + bcat              [2N,512]
        tgemm<0><<<dim3(GM, 4), 256>>>(h, 384, Wcat, AB, 512, bcat, nullptr,
                                       NB, 512, 128);
        // T[n] = sum relu(A[src] + B[n])       (CSR, no atomics)
        edge_csr<<<NB / 4, 256>>>(off, src, AB, T);
        // agg = T @ Wm2 + deg*b2  -> UI[:,0:256]
        tgemm<0><<<dim3(GM, 2), 256>>>(T, 256, Wm2, UI, 384, bm2, dg,
                                       NB, 256, 256);
        // u1 = relu(UI @ Wu1 + bu1)            (K=384, concat-free) -> T
        tgemm<1><<<dim3(GM, 2), 256>>>(UI, 384, Wu1, T, 256, bu1, nullptr,
                                       NB, 256, 384);
        // h += u1 @ Wu2 + bu2                  (residual, ldc=384)
        tgemm<2><<<dim3(GM, 1), 256>>>(T, 256, Wu2, h, 384, bu2, nullptr,
                                       NB, 128, 256);
    }

    // 3. readout
    tgemm<0><<<dim3(GM, 2), 256>>>(h, 384, gw + OFF_NODE, AB, 256, node_b, nullptr,
                                   NB, 256, 128);
    zero_kernel<<<(2 * NG * 32 + 255) / 256, 256>>>((float4*)gg, 2 * NG * 32);
    gatepool_kernel<<<(NB * 32 + 255) / 256, 256>>>(AB, batch1, batch2, gg);
    tgemm<0><<<dim3(1, 1), 256>>>(gg, 128, gw + OFF_GRAPH, (float*)d_out, 128,
                                  graph_b, nullptr, 2 * NG, HD, 128);
}

// round 11
// speedup vs baseline: 2.4182x; 1.1684x over previous
#include <cuda_runtime.h>
#include <math.h>

#define NN 10000   // nodes per branch
#define NE 160000  // edges per branch
#define NG 32      // graphs per branch
#define HD 128     // hidden
#define NB (2*NN)  // stacked nodes

// ---------------------------------------------------------------------------
// Static device scratch (allocation-free rule)
// ---------------------------------------------------------------------------
__device__ float g_AB[NB * 512];    // [A_row(256) | B_row(256)] per node (msg W1 out)
__device__ float g_UI[NB * 384];    // cols 0:256 = agg, cols 256:384 = h (persistent)
__device__ float g_T [NB * 256];    // edge sums / u1 / nx scratch
__device__ float g_dg[NB];          // in-degree (float)
__device__ float g_gg[2 * NG * HD]; // pooled per-graph [64,128]
__device__ int   g_cnt[NB];         // counts, then scatter cursor
__device__ int   g_off[NB + 1];     // CSR offsets
__device__ int   g_src[2 * NE];     // CSR source lists
__device__ float g_W [582656];      // packed tf32-rounded weights + bcat

// packed weight offsets (floats)
#define OFF_EMB    0
#define OFF_NODE   8192
#define OFF_GRAPH  40960
#define OFF_LAYER(l) (57344 + (l) * 262144)
#define OFF_WCAT   0
#define OFF_WM2    65536
#define OFF_WU1    131072
#define OFF_WU2    229376
#define OFF_BCAT   581632
#define W_TOTAL    582656

// ---------------------------------------------------------------------------
// helpers
// ---------------------------------------------------------------------------
__device__ __forceinline__ float round_tf32(float f) {
    unsigned u;
    asm("cvt.rna.tf32.f32 %0, %1;" : "=r"(u) : "f"(f));
    return __uint_as_float(u);
}
__device__ __forceinline__ void cp16(void* smem, const void* g, int sz) {
    unsigned s = (unsigned)__cvta_generic_to_shared(smem);
    asm volatile("cp.async.cg.shared.global [%0], [%1], 16, %2;"
                 :: "r"(s), "l"(g), "r"(sz));
}

// ---------------------------------------------------------------------------
// TF32 tensor-core GEMM: C[M,N] = op(A[M,K] @ B[K,N] + bias)
//   EPI 0: C = acc + bias (bias optionally scaled per-row by rowscale)
//   EPI 1: C = relu(acc + bias)
//   EPI 2: C = C + acc + bias        (residual)
// BM=128, BN=128, BK=16, 256 threads (8 warps, 2x4), warp tile 64x32,
// mma.m16n8k8 tf32 (native tf32 k-step). A cvt.rna'd in-loop; B pre-rounded.
// ---------------------------------------------------------------------------
template <int EPI>
__global__ __launch_bounds__(256, 2)
void tgemm(const float* __restrict__ Ag, int lda,
           const float* __restrict__ Bg,
           float* __restrict__ C, int ldc,
           const float* __restrict__ bias,
           const float* __restrict__ rowscale,
           int M, int N, int K)
{
    constexpr int BM = 128, BK = 16;
    __shared__ __align__(16) float As[2][BM][20];   // [m][k] pad 4 -> conflict-free
    __shared__ __align__(16) float Bs[2][BK][136];  // [k][n] pad 8

    const int tid = threadIdx.x;
    const int l = tid & 31, w = tid >> 5;
    const int wm = (w >> 2) * 64, wn = (w & 3) * 32;
    const int m0 = blockIdx.x * BM, n0 = blockIdx.y * 128;

    float acc[4][4][4];
#pragma unroll
    for (int a = 0; a < 4; a++)
#pragma unroll
        for (int b = 0; b < 4; b++)
#pragma unroll
            for (int c = 0; c < 4; c++) acc[a][b][c] = 0.f;

    auto docopy = [&](int t, int buf) {
#pragma unroll
        for (int i = 0; i < 2; i++) {                 // A: 128x16 = 512 float4
            int idx = tid + i * 256;
            int m = idx >> 2, k4 = idx & 3;
            const float* src = Ag + (size_t)(m0 + m) * lda + t * BK + k4 * 4;
            int sz = (m0 + m < M) ? 16 : 0;
            if (!sz) src = Ag;                         // safe dummy address
            cp16(&As[buf][m][k4 * 4], src, sz);
        }
#pragma unroll
        for (int i = 0; i < 2; i++) {                 // B: 16x128 = 512 float4
            int idx = tid + i * 256;
            int k = idx >> 5, n4 = idx & 31;
            cp16(&Bs[buf][k][n4 * 4],
                 Bg + (size_t)(t * BK + k) * N + n0 + n4 * 4, 16);
        }
        asm volatile("cp.async.commit_group;");
    };

    docopy(0, 0);
    const int nt = K / BK;
    int buf = 0;
    for (int t = 0; t < nt; t++) {
        if (t + 1 < nt) {
            docopy(t + 1, buf ^ 1);
            asm volatile("cp.async.wait_group 1;");
        } else {
            asm volatile("cp.async.wait_group 0;");
        }
        __syncthreads();

#pragma unroll
        for (int j = 0; j < 2; j++) {                 // 2 k8-steps per BK=16
            const int kb = j * 8;
            unsigned ua[4][4];
#pragma unroll
            for (int mt = 0; mt < 4; mt++) {
                float f0 = As[buf][wm + mt * 16 +     (l >> 2)][kb +     (l & 3)];
                float f1 = As[buf][wm + mt * 16 + 8 + (l >> 2)][kb +     (l & 3)];
                float f2 = As[buf][wm + mt * 16 +     (l >> 2)][kb + 4 + (l & 3)];
                float f3 = As[buf][wm + mt * 16 + 8 + (l >> 2)][kb + 4 + (l & 3)];
                asm("cvt.rna.tf32.f32 %0, %1;" : "=r"(ua[mt][0]) : "f"(f0));
                asm("cvt.rna.tf32.f32 %0, %1;" : "=r"(ua[mt][1]) : "f"(f1));
                asm("cvt.rna.tf32.f32 %0, %1;" : "=r"(ua[mt][2]) : "f"(f2));
                asm("cvt.rna.tf32.f32 %0, %1;" : "=r"(ua[mt][3]) : "f"(f3));
            }
            unsigned ub[4][2];
#pragma unroll
            for (int q = 0; q < 4; q++) {
                ub[q][0] = __float_as_uint(Bs[buf][kb +     (l & 3)][wn + q * 8 + (l >> 2)]);
                ub[q][1] = __float_as_uint(Bs[buf][kb + 4 + (l & 3)][wn + q * 8 + (l >> 2)]);
            }
#pragma unroll
            for (int mt = 0; mt < 4; mt++)
#pragma unroll
                for (int q = 0; q < 4; q++)
                    asm volatile(
                        "mma.sync.aligned.m16n8k8.row.col.f32.tf32.tf32.f32 "
                        "{%0,%1,%2,%3}, {%4,%5,%6,%7}, {%8,%9}, {%0,%1,%2,%3};"
                        : "+f"(acc[mt][q][0]), "+f"(acc[mt][q][1]),
                          "+f"(acc[mt][q][2]), "+f"(acc[mt][q][3])
                        : "r"(ua[mt][0]), "r"(ua[mt][1]),
                          "r"(ua[mt][2]), "r"(ua[mt][3]),
                          "r"(ub[q][0]), "r"(ub[q][1]));
        }
        __syncthreads();
        buf ^= 1;
    }

    // epilogue (C layout identical to m16n8k4)
#pragma unroll
    for (int mt = 0; mt < 4; mt++) {
#pragma unroll
        for (int half = 0; half < 2; half++) {
            const int r = m0 + wm + mt * 16 + half * 8 + (l >> 2);
            if (r < M) {
                const float rs = rowscale ? rowscale[r] : 1.f;
#pragma unroll
                for (int q = 0; q < 4; q++) {
                    const int c = n0 + wn + q * 8 + 2 * (l & 3);
                    float v0 = acc[mt][q][half * 2 + 0];
                    float v1 = acc[mt][q][half * 2 + 1];
                    if (bias) { v0 += bias[c] * rs; v1 += bias[c + 1] * rs; }
                    float* cp = C + (size_t)r * ldc + c;
                    if (EPI == 2) { v0 += cp[0]; v1 += cp[1]; }
                    if (EPI == 1) { v0 = fmaxf(v0, 0.f); v1 = fmaxf(v1, 0.f); }
                    *reinterpret_cast<float2*>(cp) = make_float2(v0, v1);
                }
            }
        }
    }
}

// ---------------------------------------------------------------------------
// Weight prep: round to tf32 and pack (Wcat = [W1_top | W1_bot] cols)
// ---------------------------------------------------------------------------
__global__ void prep_weights(const float* __restrict__ W_emb,
                             const float* __restrict__ node_W,
                             const float* __restrict__ graph_W,
                             const float* __restrict__ mW1,
                             const float* __restrict__ mb1,
                             const float* __restrict__ mW2,
                             const float* __restrict__ uW1,
                             const float* __restrict__ uW2,
                             float* __restrict__ gw)
{
    int i = blockIdx.x * 256 + threadIdx.x;
    if (i >= W_TOTAL) return;
    float v;
    if (i < OFF_NODE)        v = round_tf32(W_emb[i - OFF_EMB]);
    else if (i < OFF_GRAPH)  v = round_tf32(node_W[i - OFF_NODE]);
    else if (i < 57344)      v = round_tf32(graph_W[i - OFF_GRAPH]);
    else if (i < OFF_BCAT) {
        int j = i - 57344;
        int lay = j / 262144, r = j % 262144;
        if (r < 65536) {                       // Wcat: [128][512]
            int k = r >> 9, c = r & 511;
            float s = (c < 256) ? mW1[(size_t)lay * 65536 + k * 256 + c]
                                : mW1[(size_t)lay * 65536 + (k + 128) * 256 + (c - 256)];
            v = round_tf32(s);
        } else if (r < 131072) v = round_tf32(mW2[(size_t)lay * 65536 + (r - 65536)]);
        else if (r < 229376)   v = round_tf32(uW1[(size_t)lay * 98304 + (r - 131072)]);
        else                   v = round_tf32(uW2[(size_t)lay * 32768 + (r - 229376)]);
    } else {                                   // bcat: fp32, [bm1 | zeros]
        int j = i - OFF_BCAT;
        int lay = j >> 9, c = j & 511;
        v = (c < 256) ? mb1[lay * 256 + c] : 0.f;
    }
    gw[i] = v;
}

// ---------------------------------------------------------------------------
// CSR construction (one-time; reused by both layers)
// ---------------------------------------------------------------------------
__global__ void zero_kernel(float4* __restrict__ p, int n4) {
    int i = blockIdx.x * blockDim.x + threadIdx.x;
    if (i < n4) p[i] = make_float4(0.f, 0.f, 0.f, 0.f);
}

__global__ void count_kernel(const int* __restrict__ ei1, const int* __restrict__ ei2,
                             int* __restrict__ cnt) {
    int e = blockIdx.x * blockDim.x + threadIdx.x;
    if (e >= 2 * NE) return;
    int t = (e < NE) ? ei1[e] : (ei2[e - NE] + NN);
    atomicAdd(cnt + t, 1);
}

// single-block thread-coarsened scan: 1024 threads x 20 elems, 2 barriers total
__global__ void scan_kernel(int* __restrict__ cnt, int* __restrict__ off,
                            float* __restrict__ dg) {
    __shared__ int wsum[32];
    const int t = threadIdx.x;
    const int lane = t & 31, wid = t >> 5;
    const int base = t * 20;
    int x[20];
    int s = 0;
#pragma unroll
    for (int i = 0; i < 20; i++) {
        int idx = base + i;
        x[i] = (idx < NB) ? cnt[idx] : 0;
        s += x[i];
    }
    int inc = s;
#pragma unroll
    for (int d = 1; d < 32; d <<= 1) {
        int y = __shfl_up_sync(0xffffffffu, inc, d);
        if (lane >= d) inc += y;
    }
    if (lane == 31) wsum[wid] = inc;
    __syncthreads();
    if (wid == 0) {
        int ws = wsum[lane];
#pragma unroll
        for (int d = 1; d < 32; d <<= 1) {
            int y = __shfl_up_sync(0xffffffffu, ws, d);
            if (lane >= d) ws += y;
        }
        wsum[lane] = ws;
    }
    __syncthreads();
    int e = inc - s + (wid ? wsum[wid - 1] : 0);   // thread exclusive prefix
#pragma unroll
    for (int i = 0; i < 20; i++) {
        int idx = base + i;
        if (idx < NB) {
            off[idx] = e;
            cnt[idx] = e;
            dg[idx]  = (float)x[i];
            e += x[i];
        }
    }
    if (t == 1023) off[NB] = e;                    // grand total
}

__global__ void scatter_kernel(const int* __restrict__ ei1, const int* __restrict__ ei2,
                               int* __restrict__ cursor, int* __restrict__ srcs) {
    int e = blockIdx.x * blockDim.x + threadIdx.x;
    if (e >= 2 * NE) return;
    int t, s;
    if (e < NE) { t = ei1[e];      s = ei1[NE + e]; }
    else        { int e2 = e - NE; t = ei2[e2] + NN; s = ei2[NE + e2] + NN; }
    int p = atomicAdd(cursor + t, 1);
    srcs[p] = s;
}

// ---------------------------------------------------------------------------
// Edge aggregation (CSR): T[n] = sum_{src in csr(n)} relu(A[src] + B[n])
// ---------------------------------------------------------------------------
__global__ void edge_csr(const int* __restrict__ off, const int* __restrict__ srcs,
                         const float* __restrict__ AB, float* __restrict__ T) {
    const int node = blockIdx.x * 4 + (threadIdx.x >> 6);
    const int lane = threadIdx.x & 63;
    const float4* ABf = reinterpret_cast<const float4*>(AB);
    const int p0 = off[node], p1 = off[node + 1];
    float4 b = ABf[(size_t)node * 128 + 64 + lane];
    float4 acc = make_float4(0.f, 0.f, 0.f, 0.f);
    for (int p = p0; p < p1; ++p) {
        int s = srcs[p];
        float4 a = ABf[(size_t)s * 128 + lane];
        acc.x += fmaxf(a.x + b.x, 0.f);
        acc.y += fmaxf(a.y + b.y, 0.f);
        acc.z += fmaxf(a.z + b.z, 0.f);
        acc.w += fmaxf(a.w + b.w, 0.f);
    }
    reinterpret_cast<float4*>(T)[(size_t)node * 64 + lane] = acc;
}

// ---------------------------------------------------------------------------
// Gate + pool, exploiting sorted batch: register run-accumulation, atomic
// flush only on graph-id change (~63 boundaries total).
// Thread (r, c4) handles lane c4 over 16 consecutive nodes.
// ---------------------------------------------------------------------------
#define GP_L 16
__global__ void gatepool_kernel(const float* __restrict__ nx,
                                const int* __restrict__ batch1,
                                const int* __restrict__ batch2,
                                float* __restrict__ gg) {
    const int r = threadIdx.x >> 5, c4 = threadIdx.x & 31;
    const int start = (blockIdx.x * 8 + r) * GP_L;
    float4 acc = make_float4(0.f, 0.f, 0.f, 0.f);
    int curb = -1;
    for (int i = 0; i < GP_L; i++) {
        int node = start + i;
        if (node >= NB) break;
        int b = (node < NN) ? batch1[node] : (batch2[node - NN] + NG);
        if (b != curb) {
            if (curb >= 0)
                atomicAdd(reinterpret_cast<float4*>(gg + (size_t)curb * HD) + c4, acc);
            acc = make_float4(0.f, 0.f, 0.f, 0.f);
            curb = b;
        }
        const float4* row = reinterpret_cast<const float4*>(nx + (size_t)node * 256);
        float4 g = row[c4];
        float4 v = row[32 + c4];
        acc.x += v.x / (1.f + expf(-g.x));
        acc.y += v.y / (1.f + expf(-g.y));
        acc.z += v.z / (1.f + expf(-g.z));
        acc.w += v.w / (1.f + expf(-g.w));
    }
    if (curb >= 0)
        atomicAdd(reinterpret_cast<float4*>(gg + (size_t)curb * HD) + c4, acc);
}

// ---------------------------------------------------------------------------
// Host orchestration
// ---------------------------------------------------------------------------
extern "C" void kernel_launch(void* const* d_in, const int* in_sizes, int n_in,
                              void* d_out, int out_size)
{
    (void)in_sizes; (void)n_in; (void)out_size;

    const float* x1      = (const float*)d_in[0];
    const int*   ei1     = (const int*)  d_in[1];
    const int*   batch1  = (const int*)  d_in[2];
    const float* x2      = (const float*)d_in[3];
    const int*   ei2     = (const int*)  d_in[4];
    const int*   batch2  = (const int*)  d_in[5];
    const float* W_emb   = (const float*)d_in[6];
    const float* b_emb   = (const float*)d_in[7];
    const float* msg_W1  = (const float*)d_in[8];
    const float* msg_b1  = (const float*)d_in[9];
    const float* msg_W2  = (const float*)d_in[10];
    const float* msg_b2  = (const float*)d_in[11];
    const float* upd_W1  = (const float*)d_in[12];
    const float* upd_b1  = (const float*)d_in[13];
    const float* upd_W2  = (const float*)d_in[14];
    const float* upd_b2  = (const float*)d_in[15];
    const float* node_b  = (const float*)d_in[17];
    const float* graph_b = (const float*)d_in[19];

    void *pAB, *pUI, *pT, *pdg, *pgg, *pcnt, *poff, *psrc, *pW;
    cudaGetSymbolAddress(&pAB,  g_AB);
    cudaGetSymbolAddress(&pUI,  g_UI);
    cudaGetSymbolAddress(&pT,   g_T);
    cudaGetSymbolAddress(&pdg,  g_dg);
    cudaGetSymbolAddress(&pgg,  g_gg);
    cudaGetSymbolAddress(&pcnt, g_cnt);
    cudaGetSymbolAddress(&poff, g_off);
    cudaGetSymbolAddress(&psrc, g_src);
    cudaGetSymbolAddress(&pW,   g_W);
    float* AB  = (float*)pAB;
    float* UI  = (float*)pUI;
    float* T   = (float*)pT;
    float* dg  = (float*)pdg;
    float* gg  = (float*)pgg;
    int*   cnt = (int*)pcnt;
    int*   off = (int*)poff;
    int*   src = (int*)psrc;
    float* gw  = (float*)pW;

    float* h = UI + 256;                 // h lives at UI cols [256,384), stride 384

    // 0. round + pack weights
    prep_weights<<<(W_TOTAL + 255) / 256, 256>>>(
        W_emb, (const float*)d_in[16], (const float*)d_in[18],
        msg_W1, msg_b1, msg_W2, upd_W1, upd_W2, gw);

    // 1. CSR build (shared by both layers)
    zero_kernel<<<(NB / 4 + 255) / 256, 256>>>((float4*)cnt, NB / 4);
    count_kernel<<<(2 * NE + 255) / 256, 256>>>(ei1, ei2, cnt);
    scan_kernel<<<1, 1024>>>(cnt, off, dg);
    scatter_kernel<<<(2 * NE + 255) / 256, 256>>>(ei1, ei2, cnt, src);

    // 2. embedding: h = x @ W_emb + b_emb  (into UI[:,256:384])
    const dim3 gEmb((NN + 127) / 128, 1);
    tgemm<0><<<gEmb, 256>>>(x1, 64, gw + OFF_EMB, h, 384, b_emb, nullptr, NN, HD, 64);
    tgemm<0><<<gEmb, 256>>>(x2, 64, gw + OFF_EMB, h + (size_t)NN * 384, 384,
                            b_emb, nullptr, NN, HD, 64);

    const int GM = (NB + 127) / 128;     // 157

    for (int l = 0; l < 2; l++) {
        const float* Wcat = gw + OFF_LAYER(l) + OFF_WCAT;
        const float* Wm2  = gw + OFF_LAYER(l) + OFF_WM2;
        const float* Wu1  = gw + OFF_LAYER(l) + OFF_WU1;
        const float* Wu2  = gw + OFF_LAYER(l) + OFF_WU2;
        const float* bcat = gw + OFF_BCAT + (size_t)l * 512;
        const float* bm2  = msg_b2 + (size_t)l * 256;
        const float* bu1  = upd_b1 + (size_t)l * 256;
        const float* bu2  = upd_b2 + (size_t)l * 128;

        // [A|B] = h @ Wcat + bcat              [2N,512]
        tgemm<0><<<dim3(GM, 4), 256>>>(h, 384, Wcat, AB, 512, bcat, nullptr,
                                       NB, 512, 128);
        // T[n] = sum relu(A[src] + B[n])       (CSR, no atomics)
        edge_csr<<<NB / 4, 256>>>(off, src, AB, T);
        // agg = T @ Wm2 + deg*b2  -> UI[:,0:256]
        tgemm<0><<<dim3(GM, 2), 256>>>(T, 256, Wm2, UI, 384, bm2, dg,
                                       NB, 256, 256);
        // u1 = relu(UI @ Wu1 + bu1)            (K=384, concat-free) -> T
        tgemm<1><<<dim3(GM, 2), 256>>>(UI, 384, Wu1, T, 256, bu1, nullptr,
                                       NB, 256, 384);
        // h += u1 @ Wu2 + bu2                  (residual, ldc=384)
        tgemm<2><<<dim3(GM, 1), 256>>>(T, 256, Wu2, h, 384, bu2, nullptr,
                                       NB, 128, 256);
    }

    // 3. readout
    tgemm<0><<<dim3(GM, 2), 256>>>(h, 384, gw + OFF_NODE, AB, 256, node_b, nullptr,
                                   NB, 256, 128);
    zero_kernel<<<(2 * NG * 32 + 255) / 256, 256>>>((float4*)gg, 2 * NG * 32);
    gatepool_kernel<<<(NB / 128) + 1, 256>>>(AB, batch1, batch2, gg);
    tgemm<0><<<dim3(1, 1), 256>>>(gg, 128, gw + OFF_GRAPH, (float*)d_out, 128,
                                  graph_b, nullptr, 2 * NG, HD, 128);
}

// round 12
// speedup vs baseline: 2.6110x; 1.0797x over previous
#include <cuda_runtime.h>
#include <math.h>

#define NN 10000   // nodes per branch
#define NE 160000  // edges per branch
#define NG 32      // graphs per branch
#define HD 128     // hidden
#define NB (2*NN)  // stacked nodes
#define SCAN_B 20  // scan blocks (1024 each >= NB)

// ---------------------------------------------------------------------------
// Static device scratch (allocation-free rule)
// ---------------------------------------------------------------------------
__device__ float g_AB[NB * 512];    // [A_row(256) | B_row(256)] per node (msg W1 out)
__device__ float g_UI[NB * 384];    // cols 0:256 = agg, cols 256:384 = h (persistent)
__device__ float g_T [NB * 256];    // edge sums / u1 / nx scratch
__device__ float g_dg[NB];          // in-degree (float)
__device__ float g_gg[2 * NG * HD]; // pooled per-graph [64,128]
__device__ int   g_cnt[NB];         // counts, then scatter cursor
__device__ int   g_off[NB + 1];     // CSR offsets
__device__ int   g_src[2 * NE];     // CSR source lists
__device__ int   g_bsum[SCAN_B];    // per-block scan sums
__device__ float g_W [582656];      // packed tf32-rounded weights + bcat

// packed weight offsets (floats)
#define OFF_EMB    0
#define OFF_NODE   8192
#define OFF_GRAPH  40960
#define OFF_LAYER(l) (57344 + (l) * 262144)
#define OFF_WCAT   0
#define OFF_WM2    65536
#define OFF_WU1    131072
#define OFF_WU2    229376
#define OFF_BCAT   581632
#define W_TOTAL    582656

// ---------------------------------------------------------------------------
// helpers
// ---------------------------------------------------------------------------
__device__ __forceinline__ float round_tf32(float f) {
    unsigned u;
    asm("cvt.rna.tf32.f32 %0, %1;" : "=r"(u) : "f"(f));
    return __uint_as_float(u);
}
__device__ __forceinline__ void cp16(void* smem, const void* g, int sz) {
    unsigned s = (unsigned)__cvta_generic_to_shared(smem);
    asm volatile("cp.async.cg.shared.global [%0], [%1], 16, %2;"
                 :: "r"(s), "l"(g), "r"(sz));
}

// ---------------------------------------------------------------------------
// TF32 tensor-core GEMM (m16n8k8): unchanged from R11 (it works; protect it)
// ---------------------------------------------------------------------------
template <int EPI>
__global__ __launch_bounds__(256, 2)
void tgemm(const float* __restrict__ Ag, int lda,
           const float* __restrict__ Bg,
           float* __restrict__ C, int ldc,
           const float* __restrict__ bias,
           const float* __restrict__ rowscale,
           int M, int N, int K)
{
    constexpr int BM = 128, BK = 16;
    __shared__ __align__(16) float As[2][BM][20];
    __shared__ __align__(16) float Bs[2][BK][136];

    const int tid = threadIdx.x;
    const int l = tid & 31, w = tid >> 5;
    const int wm = (w >> 2) * 64, wn = (w & 3) * 32;
    const int m0 = blockIdx.x * BM, n0 = blockIdx.y * 128;

    float acc[4][4][4];
#pragma unroll
    for (int a = 0; a < 4; a++)
#pragma unroll
        for (int b = 0; b < 4; b++)
#pragma unroll
            for (int c = 0; c < 4; c++) acc[a][b][c] = 0.f;

    auto docopy = [&](int t, int buf) {
#pragma unroll
        for (int i = 0; i < 2; i++) {
            int idx = tid + i * 256;
            int m = idx >> 2, k4 = idx & 3;
            const float* src = Ag + (size_t)(m0 + m) * lda + t * BK + k4 * 4;
            int sz = (m0 + m < M) ? 16 : 0;
            if (!sz) src = Ag;
            cp16(&As[buf][m][k4 * 4], src, sz);
        }
#pragma unroll
        for (int i = 0; i < 2; i++) {
            int idx = tid + i * 256;
            int k = idx >> 5, n4 = idx & 31;
            cp16(&Bs[buf][k][n4 * 4],
                 Bg + (size_t)(t * BK + k) * N + n0 + n4 * 4, 16);
        }
        asm volatile("cp.async.commit_group;");
    };

    docopy(0, 0);
    const int nt = K / BK;
    int buf = 0;
    for (int t = 0; t < nt; t++) {
        if (t + 1 < nt) {
            docopy(t + 1, buf ^ 1);
            asm volatile("cp.async.wait_group 1;");
        } else {
            asm volatile("cp.async.wait_group 0;");
        }
        __syncthreads();

#pragma unroll
        for (int j = 0; j < 2; j++) {
            const int kb = j * 8;
            unsigned ua[4][4];
#pragma unroll
            for (int mt = 0; mt < 4; mt++) {
                float f0 = As[buf][wm + mt * 16 +     (l >> 2)][kb +     (l & 3)];
                float f1 = As[buf][wm + mt * 16 + 8 + (l >> 2)][kb +     (l & 3)];
                float f2 = As[buf][wm + mt * 16 +     (l >> 2)][kb + 4 + (l & 3)];
                float f3 = As[buf][wm + mt * 16 + 8 + (l >> 2)][kb + 4 + (l & 3)];
                asm("cvt.rna.tf32.f32 %0, %1;" : "=r"(ua[mt][0]) : "f"(f0));
                asm("cvt.rna.tf32.f32 %0, %1;" : "=r"(ua[mt][1]) : "f"(f1));
                asm("cvt.rna.tf32.f32 %0, %1;" : "=r"(ua[mt][2]) : "f"(f2));
                asm("cvt.rna.tf32.f32 %0, %1;" : "=r"(ua[mt][3]) : "f"(f3));
            }
            unsigned ub[4][2];
#pragma unroll
            for (int q = 0; q < 4; q++) {
                ub[q][0] = __float_as_uint(Bs[buf][kb +     (l & 3)][wn + q * 8 + (l >> 2)]);
                ub[q][1] = __float_as_uint(Bs[buf][kb + 4 + (l & 3)][wn + q * 8 + (l >> 2)]);
            }
#pragma unroll
            for (int mt = 0; mt < 4; mt++)
#pragma unroll
                for (int q = 0; q < 4; q++)
                    asm volatile(
                        "mma.sync.aligned.m16n8k8.row.col.f32.tf32.tf32.f32 "
                        "{%0,%1,%2,%3}, {%4,%5,%6,%7}, {%8,%9}, {%0,%1,%2,%3};"
                        : "+f"(acc[mt][q][0]), "+f"(acc[mt][q][1]),
                          "+f"(acc[mt][q][2]), "+f"(acc[mt][q][3])
                        : "r"(ua[mt][0]), "r"(ua[mt][1]),
                          "r"(ua[mt][2]), "r"(ua[mt][3]),
                          "r"(ub[q][0]), "r"(ub[q][1]));
        }
        __syncthreads();
        buf ^= 1;
    }

#pragma unroll
    for (int mt = 0; mt < 4; mt++) {
#pragma unroll
        for (int half = 0; half < 2; half++) {
            const int r = m0 + wm + mt * 16 + half * 8 + (l >> 2);
            if (r < M) {
                const float rs = rowscale ? rowscale[r] : 1.f;
#pragma unroll
                for (int q = 0; q < 4; q++) {
                    const int c = n0 + wn + q * 8 + 2 * (l & 3);
                    float v0 = acc[mt][q][half * 2 + 0];
                    float v1 = acc[mt][q][half * 2 + 1];
                    if (bias) { v0 += bias[c] * rs; v1 += bias[c + 1] * rs; }
                    float* cp = C + (size_t)r * ldc + c;
                    if (EPI == 2) { v0 += cp[0]; v1 += cp[1]; }
                    if (EPI == 1) { v0 = fmaxf(v0, 0.f); v1 = fmaxf(v1, 0.f); }
                    *reinterpret_cast<float2*>(cp) = make_float2(v0, v1);
                }
            }
        }
    }
}

// ---------------------------------------------------------------------------
// Weight prep: round to tf32 and pack (Wcat = [W1_top | W1_bot] cols)
// ---------------------------------------------------------------------------
__global__ void prep_weights(const float* __restrict__ W_emb,
                             const float* __restrict__ node_W,
                             const float* __restrict__ graph_W,
                             const float* __restrict__ mW1,
                             const float* __restrict__ mb1,
                             const float* __restrict__ mW2,
                             const float* __restrict__ uW1,
                             const float* __restrict__ uW2,
                             float* __restrict__ gw)
{
    int i = blockIdx.x * 256 + threadIdx.x;
    if (i >= W_TOTAL) return;
    float v;
    if (i < OFF_NODE)        v = round_tf32(W_emb[i - OFF_EMB]);
    else if (i < OFF_GRAPH)  v = round_tf32(node_W[i - OFF_NODE]);
    else if (i < 57344)      v = round_tf32(graph_W[i - OFF_GRAPH]);
    else if (i < OFF_BCAT) {
        int j = i - 57344;
        int lay = j / 262144, r = j % 262144;
        if (r < 65536) {
            int k = r >> 9, c = r & 511;
            float s = (c < 256) ? mW1[(size_t)lay * 65536 + k * 256 + c]
                                : mW1[(size_t)lay * 65536 + (k + 128) * 256 + (c - 256)];
            v = round_tf32(s);
        } else if (r < 131072) v = round_tf32(mW2[(size_t)lay * 65536 + (r - 65536)]);
        else if (r < 229376)   v = round_tf32(uW1[(size_t)lay * 98304 + (r - 131072)]);
        else                   v = round_tf32(uW2[(size_t)lay * 32768 + (r - 229376)]);
    } else {
        int j = i - OFF_BCAT;
        int lay = j >> 9, c = j & 511;
        v = (c < 256) ? mb1[lay * 256 + c] : 0.f;
    }
    gw[i] = v;
}

// ---------------------------------------------------------------------------
// CSR construction
// ---------------------------------------------------------------------------
__global__ void zero_kernel(float4* __restrict__ p, int n4) {
    int i = blockIdx.x * blockDim.x + threadIdx.x;
    if (i < n4) p[i] = make_float4(0.f, 0.f, 0.f, 0.f);
}

__global__ void count_kernel(const int* __restrict__ ei1, const int* __restrict__ ei2,
                             int* __restrict__ cnt) {
    int e = blockIdx.x * blockDim.x + threadIdx.x;
    if (e >= 2 * NE) return;
    int t = (e < NE) ? ei1[e] : (ei2[e - NE] + NN);
    atomicAdd(cnt + t, 1);
}

// scan stage 1: per-block coalesced exclusive scan (1 elem/thread, 20 blocks)
__global__ void scan1_kernel(const int* __restrict__ cnt, int* __restrict__ off,
                             float* __restrict__ dg, int* __restrict__ bsum) {
    __shared__ int wsum[32];
    const int t = threadIdx.x, lane = t & 31, wid = t >> 5;
    const int i = blockIdx.x * 1024 + t;
    int v = (i < NB) ? cnt[i] : 0;
    int inc = v;
#pragma unroll
    for (int d = 1; d < 32; d <<= 1) {
        int y = __shfl_up_sync(0xffffffffu, inc, d);
        if (lane >= d) inc += y;
    }
    if (lane == 31) wsum[wid] = inc;
    __syncthreads();
    if (wid == 0) {
        int ws = wsum[lane];
#pragma unroll
        for (int d = 1; d < 32; d <<= 1) {
            int y = __shfl_up_sync(0xffffffffu, ws, d);
            if (lane >= d) ws += y;
        }
        wsum[lane] = ws;
    }
    __syncthreads();
    int e = inc - v + (wid ? wsum[wid - 1] : 0);   // block-local exclusive
    if (i < NB) { off[i] = e; dg[i] = (float)v; }
    if (t == 1023) bsum[blockIdx.x] = e + v;       // block total
}

// scan stage 2: add block bases (each block re-scans the 20 sums in-warp)
__global__ void scan2_kernel(int* __restrict__ off, int* __restrict__ cnt,
                             const int* __restrict__ bsum) {
    __shared__ int sbase, stot;
    const int t = threadIdx.x, lane = t & 31;
    if (t < 32) {
        int v = (lane < SCAN_B) ? bsum[lane] : 0;
        int inc = v;
#pragma unroll
        for (int d = 1; d < 32; d <<= 1) {
            int y = __shfl_up_sync(0xffffffffu, inc, d);
            if (lane >= d) inc += y;
        }
        if (lane == (int)blockIdx.x) sbase = inc - v;
        if (lane == SCAN_B - 1)      stot = inc;
    }
    __syncthreads();
    const int i = blockIdx.x * 1024 + t;
    if (i < NB) {
        int o = off[i] + sbase;
        off[i] = o;
        cnt[i] = o;                       // scatter cursor
    }
    if (blockIdx.x == SCAN_B - 1 && t == 1023) off[NB] = stot;
}

__global__ void scatter_kernel(const int* __restrict__ ei1, const int* __restrict__ ei2,
                               int* __restrict__ cursor, int* __restrict__ srcs) {
    int e = blockIdx.x * blockDim.x + threadIdx.x;
    if (e >= 2 * NE) return;
    int t, s;
    if (e < NE) { t = ei1[e];      s = ei1[NE + e]; }
    else        { int e2 = e - NE; t = ei2[e2] + NN; s = ei2[NE + e2] + NN; }
    int p = atomicAdd(cursor + t, 1);
    srcs[p] = s;
}

// ---------------------------------------------------------------------------
// Edge aggregation (CSR), 4-way src unroll for MLP:
// T[n] = sum_{src in csr(n)} relu(A[src] + B[n])
// ---------------------------------------------------------------------------
__global__ void edge_csr(const int* __restrict__ off, const int* __restrict__ srcs,
                         const float* __restrict__ AB, float* __restrict__ T) {
    const int node = blockIdx.x * 4 + (threadIdx.x >> 6);
    const int lane = threadIdx.x & 63;
    const float4* ABf = reinterpret_cast<const float4*>(AB);
    const int p0 = off[node], p1 = off[node + 1];
    float4 b = ABf[(size_t)node * 128 + 64 + lane];
    float4 acc = make_float4(0.f, 0.f, 0.f, 0.f);
    int p = p0;
    for (; p + 4 <= p1; p += 4) {
        int s0 = srcs[p], s1 = srcs[p + 1], s2 = srcs[p + 2], s3 = srcs[p + 3];
        float4 a0 = ABf[(size_t)s0 * 128 + lane];
        float4 a1 = ABf[(size_t)s1 * 128 + lane];
        float4 a2 = ABf[(size_t)s2 * 128 + lane];
        float4 a3 = ABf[(size_t)s3 * 128 + lane];
        acc.x += fmaxf(a0.x + b.x, 0.f) + fmaxf(a1.x + b.x, 0.f)
               + fmaxf(a2.x + b.x, 0.f) + fmaxf(a3.x + b.x, 0.f);
        acc.y += fmaxf(a0.y + b.y, 0.f) + fmaxf(a1.y + b.y, 0.f)
               + fmaxf(a2.y + b.y, 0.f) + fmaxf(a3.y + b.y, 0.f);
        acc.z += fmaxf(a0.z + b.z, 0.f) + fmaxf(a1.z + b.z, 0.f)
               + fmaxf(a2.z + b.z, 0.f) + fmaxf(a3.z + b.z, 0.f);
        acc.w += fmaxf(a0.w + b.w, 0.f) + fmaxf(a1.w + b.w, 0.f)
               + fmaxf(a2.w + b.w, 0.f) + fmaxf(a3.w + b.w, 0.f);
    }
    for (; p < p1; ++p) {
        int s = srcs[p];
        float4 a = ABf[(size_t)s * 128 + lane];
        acc.x += fmaxf(a.x + b.x, 0.f);
        acc.y += fmaxf(a.y + b.y, 0.f);
        acc.z += fmaxf(a.z + b.z, 0.f);
        acc.w += fmaxf(a.w + b.w, 0.f);
    }
    reinterpret_cast<float4*>(T)[(size_t)node * 64 + lane] = acc;
}

// ---------------------------------------------------------------------------
// Gate + pool (sorted batch, register run-accumulation)
// ---------------------------------------------------------------------------
#define GP_L 16
__global__ void gatepool_kernel(const float* __restrict__ nx,
                                const int* __restrict__ batch1,
                                const int* __restrict__ batch2,
                                float* __restrict__ gg) {
    const int r = threadIdx.x >> 5, c4 = threadIdx.x & 31;
    const int start = (blockIdx.x * 8 + r) * GP_L;
    float4 acc = make_float4(0.f, 0.f, 0.f, 0.f);
    int curb = -1;
    for (int i = 0; i < GP_L; i++) {
        int node = start + i;
        if (node >= NB) break;
        int b = (node < NN) ? batch1[node] : (batch2[node - NN] + NG);
        if (b != curb) {
            if (curb >= 0)
                atomicAdd(reinterpret_cast<float4*>(gg + (size_t)curb * HD) + c4, acc);
            acc = make_float4(0.f, 0.f, 0.f, 0.f);
            curb = b;
        }
        const float4* row = reinterpret_cast<const float4*>(nx + (size_t)node * 256);
        float4 g = row[c4];
        float4 v = row[32 + c4];
        acc.x += v.x / (1.f + expf(-g.x));
        acc.y += v.y / (1.f + expf(-g.y));
        acc.z += v.z / (1.f + expf(-g.z));
        acc.w += v.w / (1.f + expf(-g.w));
    }
    if (curb >= 0)
        atomicAdd(reinterpret_cast<float4*>(gg + (size_t)curb * HD) + c4, acc);
}

// ---------------------------------------------------------------------------
// Host orchestration
// ---------------------------------------------------------------------------
extern "C" void kernel_launch(void* const* d_in, const int* in_sizes, int n_in,
                              void* d_out, int out_size)
{
    (void)in_sizes; (void)n_in; (void)out_size;

    const float* x1      = (const float*)d_in[0];
    const int*   ei1     = (const int*)  d_in[1];
    const int*   batch1  = (const int*)  d_in[2];
    const float* x2      = (const float*)d_in[3];
    const int*   ei2     = (const int*)  d_in[4];
    const int*   batch2  = (const int*)  d_in[5];
    const float* W_emb   = (const float*)d_in[6];
    const float* b_emb   = (const float*)d_in[7];
    const float* msg_W1  = (const float*)d_in[8];
    const float* msg_b1  = (const float*)d_in[9];
    const float* msg_W2  = (const float*)d_in[10];
    const float* msg_b2  = (const float*)d_in[11];
    const float* upd_W1  = (const float*)d_in[12];
    const float* upd_b1  = (const float*)d_in[13];
    const float* upd_W2  = (const float*)d_in[14];
    const float* upd_b2  = (const float*)d_in[15];
    const float* node_b  = (const float*)d_in[17];
    const float* graph_b = (const float*)d_in[19];

    void *pAB, *pUI, *pT, *pdg, *pgg, *pcnt, *poff, *psrc, *pbs, *pW;
    cudaGetSymbolAddress(&pAB,  g_AB);
    cudaGetSymbolAddress(&pUI,  g_UI);
    cudaGetSymbolAddress(&pT,   g_T);
    cudaGetSymbolAddress(&pdg,  g_dg);
    cudaGetSymbolAddress(&pgg,  g_gg);
    cudaGetSymbolAddress(&pcnt, g_cnt);
    cudaGetSymbolAddress(&poff, g_off);
    cudaGetSymbolAddress(&psrc, g_src);
    cudaGetSymbolAddress(&pbs,  g_bsum);
    cudaGetSymbolAddress(&pW,   g_W);
    float* AB  = (float*)pAB;
    float* UI  = (float*)pUI;
    float* T   = (float*)pT;
    float* dg  = (float*)pdg;
    float* gg  = (float*)pgg;
    int*   cnt = (int*)pcnt;
    int*   off = (int*)poff;
    int*   src = (int*)psrc;
    int*   bs  = (int*)pbs;
    float* gw  = (float*)pW;

    float* h = UI + 256;                 // h lives at UI cols [256,384), stride 384

    // 0. round + pack weights
    prep_weights<<<(W_TOTAL + 255) / 256, 256>>>(
        W_emb, (const float*)d_in[16], (const float*)d_in[18],
        msg_W1, msg_b1, msg_W2, upd_W1, upd_W2, gw);

    // 1. CSR build (coalesced hierarchical scan)
    zero_kernel<<<(NB / 4 + 255) / 256, 256>>>((float4*)cnt, NB / 4);
    count_kernel<<<(2 * NE + 255) / 256, 256>>>(ei1, ei2, cnt);
    scan1_kernel<<<SCAN_B, 1024>>>(cnt, off, dg, bs);
    scan2_kernel<<<SCAN_B, 1024>>>(off, cnt, bs);
    scatter_kernel<<<(2 * NE + 255) / 256, 256>>>(ei1, ei2, cnt, src);

    // 2. embedding: h = x @ W_emb + b_emb  (into UI[:,256:384])
    const dim3 gEmb((NN + 127) / 128, 1);
    tgemm<0><<<gEmb, 256>>>(x1, 64, gw + OFF_EMB, h, 384, b_emb, nullptr, NN, HD, 64);
    tgemm<0><<<gEmb, 256>>>(x2, 64, gw + OFF_EMB, h + (size_t)NN * 384, 384,
                            b_emb, nullptr, NN, HD, 64);

    const int GM = (NB + 127) / 128;     // 157

    for (int l = 0; l < 2; l++) {
        const float* Wcat = gw + OFF_LAYER(l) + OFF_WCAT;
        const float* Wm2  = gw + OFF_LAYER(l) + OFF_WM2;
        const float* Wu1  = gw + OFF_LAYER(l) + OFF_WU1;
        const float* Wu2  = gw + OFF_LAYER(l) + OFF_WU2;
        const float* bcat = gw + OFF_BCAT + (size_t)l * 512;
        const float* bm2  = msg_b2 + (size_t)l * 256;
        const float* bu1  = upd_b1 + (size_t)l * 256;
        const float* bu2  = upd_b2 + (size_t)l * 128;

        // [A|B] = h @ Wcat + bcat              [2N,512]
        tgemm<0><<<dim3(GM, 4), 256>>>(h, 384, Wcat, AB, 512, bcat, nullptr,
                                       NB, 512, 128);
        // T[n] = sum relu(A[src] + B[n])       (CSR, no atomics)
        edge_csr<<<NB / 4, 256>>>(off, src, AB, T);
        // agg = T @ Wm2 + deg*b2  -> UI[:,0:256]
        tgemm<0><<<dim3(GM, 2), 256>>>(T, 256, Wm2, UI, 384, bm2, dg,
                                       NB, 256, 256);
        // u1 = relu(UI @ Wu1 + bu1)            (K=384, concat-free) -> T
        tgemm<1><<<dim3(GM, 2), 256>>>(UI, 384, Wu1, T, 256, bu1, nullptr,
                                       NB, 256, 384);
        // h += u1 @ Wu2 + bu2                  (residual, ldc=384)
        tgemm<2><<<dim3(GM, 1), 256>>>(T, 256, Wu2, h, 384, bu2, nullptr,
                                       NB, 128, 256);
    }

    // 3. readout
    tgemm<0><<<dim3(GM, 2), 256>>>(h, 384, gw + OFF_NODE, AB, 256, node_b, nullptr,
                                   NB, 256, 128);
    zero_kernel<<<(2 * NG * 32 + 255) / 256, 256>>>((float4*)gg, 2 * NG * 32);
    gatepool_kernel<<<(NB / 128) + 1, 256>>>(AB, batch1, batch2, gg);
    tgemm<0><<<dim3(1, 1), 256>>>(gg, 128, gw + OFF_GRAPH, (float*)d_out, 128,
                                  graph_b, nullptr, 2 * NG, HD, 128);
}

// round 13
// speedup vs baseline: 2.6125x; 1.0006x over previous
#include <cuda_runtime.h>
#include <math.h>

#define NN 10000   // nodes per branch
#define NE 160000  // edges per branch
#define NG 32      // graphs per branch
#define HD 128     // hidden
#define NB (2*NN)  // stacked nodes
#define SCAN_B 20  // scan blocks (1024 each >= NB)

// ---------------------------------------------------------------------------
// Static device scratch (allocation-free rule)
// ---------------------------------------------------------------------------
__device__ float g_AB[NB * 512];    // [A_row(256) | B_row(256)] per node (msg W1 out)
__device__ float g_UI[NB * 384];    // cols 0:256 = agg, cols 256:384 = h (persistent)
__device__ float g_T [NB * 256];    // edge sums / u1 / nx scratch
__device__ float g_dg[NB];          // in-degree (float)
__device__ float g_gg[2 * NG * HD]; // pooled per-graph [64,128]
__device__ int   g_cnt[NB];         // counts, then scatter cursor
__device__ int   g_off[NB + 1];     // CSR offsets
__device__ int   g_src[2 * NE];     // CSR source lists
__device__ int   g_bsum[SCAN_B];    // per-block scan sums
__device__ float g_W [582656];      // packed tf32-rounded weights + bcat

// packed weight offsets (floats)
#define OFF_EMB    0
#define OFF_NODE   8192
#define OFF_GRAPH  40960
#define OFF_LAYER(l) (57344 + (l) * 262144)
#define OFF_WCAT   0
#define OFF_WM2    65536
#define OFF_WU1    131072
#define OFF_WU2    229376
#define OFF_BCAT   581632
#define W_TOTAL    582656

// ---------------------------------------------------------------------------
// helpers
// ---------------------------------------------------------------------------
__device__ __forceinline__ float round_tf32(float f) {
    unsigned u;
    asm("cvt.rna.tf32.f32 %0, %1;" : "=r"(u) : "f"(f));
    return __uint_as_float(u);
}
__device__ __forceinline__ void cp16(void* smem, const void* g, int sz) {
    unsigned s = (unsigned)__cvta_generic_to_shared(smem);
    asm volatile("cp.async.cg.shared.global [%0], [%1], 16, %2;"
                 :: "r"(s), "l"(g), "r"(sz));
}

// ---------------------------------------------------------------------------
// TF32 tensor-core GEMM (m16n8k8): unchanged (protect the win)
// ---------------------------------------------------------------------------
template <int EPI>
__global__ __launch_bounds__(256, 2)
void tgemm(const float* __restrict__ Ag, int lda,
           const float* __restrict__ Bg,
           float* __restrict__ C, int ldc,
           const float* __restrict__ bias,
           const float* __restrict__ rowscale,
           int M, int N, int K)
{
    constexpr int BM = 128, BK = 16;
    __shared__ __align__(16) float As[2][BM][20];
    __shared__ __align__(16) float Bs[2][BK][136];

    const int tid = threadIdx.x;
    const int l = tid & 31, w = tid >> 5;
    const int wm = (w >> 2) * 64, wn = (w & 3) * 32;
    const int m0 = blockIdx.x * BM, n0 = blockIdx.y * 128;

    float acc[4][4][4];
#pragma unroll
    for (int a = 0; a < 4; a++)
#pragma unroll
        for (int b = 0; b < 4; b++)
#pragma unroll
            for (int c = 0; c < 4; c++) acc[a][b][c] = 0.f;

    auto docopy = [&](int t, int buf) {
#pragma unroll
        for (int i = 0; i < 2; i++) {
            int idx = tid + i * 256;
            int m = idx >> 2, k4 = idx & 3;
            const float* src = Ag + (size_t)(m0 + m) * lda + t * BK + k4 * 4;
            int sz = (m0 + m < M) ? 16 : 0;
            if (!sz) src = Ag;
            cp16(&As[buf][m][k4 * 4], src, sz);
        }
#pragma unroll
        for (int i = 0; i < 2; i++) {
            int idx = tid + i * 256;
            int k = idx >> 5, n4 = idx & 31;
            cp16(&Bs[buf][k][n4 * 4],
                 Bg + (size_t)(t * BK + k) * N + n0 + n4 * 4, 16);
        }
        asm volatile("cp.async.commit_group;");
    };

    docopy(0, 0);
    const int nt = K / BK;
    int buf = 0;
    for (int t = 0; t < nt; t++) {
        if (t + 1 < nt) {
            docopy(t + 1, buf ^ 1);
            asm volatile("cp.async.wait_group 1;");
        } else {
            asm volatile("cp.async.wait_group 0;");
        }
        __syncthreads();

#pragma unroll
        for (int j = 0; j < 2; j++) {
            const int kb = j * 8;
            unsigned ua[4][4];
#pragma unroll
            for (int mt = 0; mt < 4; mt++) {
                float f0 = As[buf][wm + mt * 16 +     (l >> 2)][kb +     (l & 3)];
                float f1 = As[buf][wm + mt * 16 + 8 + (l >> 2)][kb +     (l & 3)];
                float f2 = As[buf][wm + mt * 16 +     (l >> 2)][kb + 4 + (l & 3)];
                float f3 = As[buf][wm + mt * 16 + 8 + (l >> 2)][kb + 4 + (l & 3)];
                asm("cvt.rna.tf32.f32 %0, %1;" : "=r"(ua[mt][0]) : "f"(f0));
                asm("cvt.rna.tf32.f32 %0, %1;" : "=r"(ua[mt][1]) : "f"(f1));
                asm("cvt.rna.tf32.f32 %0, %1;" : "=r"(ua[mt][2]) : "f"(f2));
                asm("cvt.rna.tf32.f32 %0, %1;" : "=r"(ua[mt][3]) : "f"(f3));
            }
            unsigned ub[4][2];
#pragma unroll
            for (int q = 0; q < 4; q++) {
                ub[q][0] = __float_as_uint(Bs[buf][kb +     (l & 3)][wn + q * 8 + (l >> 2)]);
                ub[q][1] = __float_as_uint(Bs[buf][kb + 4 + (l & 3)][wn + q * 8 + (l >> 2)]);
            }
#pragma unroll
            for (int mt = 0; mt < 4; mt++)
#pragma unroll
                for (int q = 0; q < 4; q++)
                    asm volatile(
                        "mma.sync.aligned.m16n8k8.row.col.f32.tf32.tf32.f32 "
                        "{%0,%1,%2,%3}, {%4,%5,%6,%7}, {%8,%9}, {%0,%1,%2,%3};"
                        : "+f"(acc[mt][q][0]), "+f"(acc[mt][q][1]),
                          "+f"(acc[mt][q][2]), "+f"(acc[mt][q][3])
                        : "r"(ua[mt][0]), "r"(ua[mt][1]),
                          "r"(ua[mt][2]), "r"(ua[mt][3]),
                          "r"(ub[q][0]), "r"(ub[q][1]));
        }
        __syncthreads();
        buf ^= 1;
    }

#pragma unroll
    for (int mt = 0; mt < 4; mt++) {
#pragma unroll
        for (int half = 0; half < 2; half++) {
            const int r = m0 + wm + mt * 16 + half * 8 + (l >> 2);
            if (r < M) {
                const float rs = rowscale ? rowscale[r] : 1.f;
#pragma unroll
                for (int q = 0; q < 4; q++) {
                    const int c = n0 + wn + q * 8 + 2 * (l & 3);
                    float v0 = acc[mt][q][half * 2 + 0];
                    float v1 = acc[mt][q][half * 2 + 1];
                    if (bias) { v0 += bias[c] * rs; v1 += bias[c + 1] * rs; }
                    float* cp = C + (size_t)r * ldc + c;
                    if (EPI == 2) { v0 += cp[0]; v1 += cp[1]; }
                    if (EPI == 1) { v0 = fmaxf(v0, 0.f); v1 = fmaxf(v1, 0.f); }
                    *reinterpret_cast<float2*>(cp) = make_float2(v0, v1);
                }
            }
        }
    }
}

// ---------------------------------------------------------------------------
// Weight prep: round to tf32 and pack (Wcat = [W1_top | W1_bot] cols)
// ---------------------------------------------------------------------------
__global__ void prep_weights(const float* __restrict__ W_emb,
                             const float* __restrict__ node_W,
                             const float* __restrict__ graph_W,
                             const float* __restrict__ mW1,
                             const float* __restrict__ mb1,
                             const float* __restrict__ mW2,
                             const float* __restrict__ uW1,
                             const float* __restrict__ uW2,
                             float* __restrict__ gw)
{
    int i = blockIdx.x * 256 + threadIdx.x;
    if (i >= W_TOTAL) return;
    float v;
    if (i < OFF_NODE)        v = round_tf32(W_emb[i - OFF_EMB]);
    else if (i < OFF_GRAPH)  v = round_tf32(node_W[i - OFF_NODE]);
    else if (i < 57344)      v = round_tf32(graph_W[i - OFF_GRAPH]);
    else if (i < OFF_BCAT) {
        int j = i - 57344;
        int lay = j / 262144, r = j % 262144;
        if (r < 65536) {
            int k = r >> 9, c = r & 511;
            float s = (c < 256) ? mW1[(size_t)lay * 65536 + k * 256 + c]
                                : mW1[(size_t)lay * 65536 + (k + 128) * 256 + (c - 256)];
            v = round_tf32(s);
        } else if (r < 131072) v = round_tf32(mW2[(size_t)lay * 65536 + (r - 65536)]);
        else if (r < 229376)   v = round_tf32(uW1[(size_t)lay * 98304 + (r - 131072)]);
        else                   v = round_tf32(uW2[(size_t)lay * 32768 + (r - 229376)]);
    } else {
        int j = i - OFF_BCAT;
        int lay = j >> 9, c = j & 511;
        v = (c < 256) ? mb1[lay * 256 + c] : 0.f;
    }
    gw[i] = v;
}

// ---------------------------------------------------------------------------
// CSR construction
// ---------------------------------------------------------------------------
__global__ void count_kernel(const int* __restrict__ ei1, const int* __restrict__ ei2,
                             int* __restrict__ cnt) {
    int e = blockIdx.x * blockDim.x + threadIdx.x;
    if (e >= 2 * NE) return;
    int t = (e < NE) ? ei1[e] : (ei2[e - NE] + NN);
    atomicAdd(cnt + t, 1);
}

// scan stage 1: per-block coalesced exclusive scan (1 elem/thread, 20 blocks)
__global__ void scan1_kernel(const int* __restrict__ cnt, int* __restrict__ off,
                             float* __restrict__ dg, int* __restrict__ bsum) {
    __shared__ int wsum[32];
    const int t = threadIdx.x, lane = t & 31, wid = t >> 5;
    const int i = blockIdx.x * 1024 + t;
    int v = (i < NB) ? cnt[i] : 0;
    int inc = v;
#pragma unroll
    for (int d = 1; d < 32; d <<= 1) {
        int y = __shfl_up_sync(0xffffffffu, inc, d);
        if (lane >= d) inc += y;
    }
    if (lane == 31) wsum[wid] = inc;
    __syncthreads();
    if (wid == 0) {
        int ws = wsum[lane];
#pragma unroll
        for (int d = 1; d < 32; d <<= 1) {
            int y = __shfl_up_sync(0xffffffffu, ws, d);
            if (lane >= d) ws += y;
        }
        wsum[lane] = ws;
    }
    __syncthreads();
    int e = inc - v + (wid ? wsum[wid - 1] : 0);   // block-local exclusive
    if (i < NB) { off[i] = e; dg[i] = (float)v; }
    if (t == 1023) bsum[blockIdx.x] = e + v;       // block total
}

// scan stage 2: add block bases (each block re-scans the 20 sums in-warp)
__global__ void scan2_kernel(int* __restrict__ off, int* __restrict__ cnt,
                             const int* __restrict__ bsum) {
    __shared__ int sbase, stot;
    const int t = threadIdx.x, lane = t & 31;
    if (t < 32) {
        int v = (lane < SCAN_B) ? bsum[lane] : 0;
        int inc = v;
#pragma unroll
        for (int d = 1; d < 32; d <<= 1) {
            int y = __shfl_up_sync(0xffffffffu, inc, d);
            if (lane >= d) inc += y;
        }
        if (lane == (int)blockIdx.x) sbase = inc - v;
        if (lane == SCAN_B - 1)      stot = inc;
    }
    __syncthreads();
    const int i = blockIdx.x * 1024 + t;
    if (i < NB) {
        int o = off[i] + sbase;
        off[i] = o;
        cnt[i] = o;                       // scatter cursor
    }
    if (blockIdx.x == SCAN_B - 1 && t == 1023) off[NB] = stot;
}

__global__ void scatter_kernel(const int* __restrict__ ei1, const int* __restrict__ ei2,
                               int* __restrict__ cursor, int* __restrict__ srcs) {
    int e = blockIdx.x * blockDim.x + threadIdx.x;
    if (e >= 2 * NE) return;
    int t, s;
    if (e < NE) { t = ei1[e];      s = ei1[NE + e]; }
    else        { int e2 = e - NE; t = ei2[e2] + NN; s = ei2[NE + e2] + NN; }
    int p = atomicAdd(cursor + t, 1);
    srcs[p] = s;
}

// ---------------------------------------------------------------------------
// Edge aggregation (CSR), 4-way src unroll:
// T[n] = sum_{src in csr(n)} relu(A[src] + B[n])
// ---------------------------------------------------------------------------
__global__ void edge_csr(const int* __restrict__ off, const int* __restrict__ srcs,
                         const float* __restrict__ AB, float* __restrict__ T) {
    const int node = blockIdx.x * 4 + (threadIdx.x >> 6);
    const int lane = threadIdx.x & 63;
    const float4* ABf = reinterpret_cast<const float4*>(AB);
    const int p0 = off[node], p1 = off[node + 1];
    float4 b = ABf[(size_t)node * 128 + 64 + lane];
    float4 acc = make_float4(0.f, 0.f, 0.f, 0.f);
    int p = p0;
    for (; p + 4 <= p1; p += 4) {
        int s0 = srcs[p], s1 = srcs[p + 1], s2 = srcs[p + 2], s3 = srcs[p + 3];
        float4 a0 = ABf[(size_t)s0 * 128 + lane];
        float4 a1 = ABf[(size_t)s1 * 128 + lane];
        float4 a2 = ABf[(size_t)s2 * 128 + lane];
        float4 a3 = ABf[(size_t)s3 * 128 + lane];
        acc.x += fmaxf(a0.x + b.x, 0.f) + fmaxf(a1.x + b.x, 0.f)
               + fmaxf(a2.x + b.x, 0.f) + fmaxf(a3.x + b.x, 0.f);
        acc.y += fmaxf(a0.y + b.y, 0.f) + fmaxf(a1.y + b.y, 0.f)
               + fmaxf(a2.y + b.y, 0.f) + fmaxf(a3.y + b.y, 0.f);
        acc.z += fmaxf(a0.z + b.z, 0.f) + fmaxf(a1.z + b.z, 0.f)
               + fmaxf(a2.z + b.z, 0.f) + fmaxf(a3.z + b.z, 0.f);
        acc.w += fmaxf(a0.w + b.w, 0.f) + fmaxf(a1.w + b.w, 0.f)
               + fmaxf(a2.w + b.w, 0.f) + fmaxf(a3.w + b.w, 0.f);
    }
    for (; p < p1; ++p) {
        int s = srcs[p];
        float4 a = ABf[(size_t)s * 128 + lane];
        acc.x += fmaxf(a.x + b.x, 0.f);
        acc.y += fmaxf(a.y + b.y, 0.f);
        acc.z += fmaxf(a.z + b.z, 0.f);
        acc.w += fmaxf(a.w + b.w, 0.f);
    }
    reinterpret_cast<float4*>(T)[(size_t)node * 64 + lane] = acc;
}

// ---------------------------------------------------------------------------
// Gate + pool (sorted batch, register run-accumulation)
// ---------------------------------------------------------------------------
#define GP_L 16
__global__ void gatepool_kernel(const float* __restrict__ nx,
                                const int* __restrict__ batch1,
                                const int* __restrict__ batch2,
                                float* __restrict__ gg) {
    const int r = threadIdx.x >> 5, c4 = threadIdx.x & 31;
    const int start = (blockIdx.x * 8 + r) * GP_L;
    float4 acc = make_float4(0.f, 0.f, 0.f, 0.f);
    int curb = -1;
    for (int i = 0; i < GP_L; i++) {
        int node = start + i;
        if (node >= NB) break;
        int b = (node < NN) ? batch1[node] : (batch2[node - NN] + NG);
        if (b != curb) {
            if (curb >= 0)
                atomicAdd(reinterpret_cast<float4*>(gg + (size_t)curb * HD) + c4, acc);
            acc = make_float4(0.f, 0.f, 0.f, 0.f);
            curb = b;
        }
        const float4* row = reinterpret_cast<const float4*>(nx + (size_t)node * 256);
        float4 g = row[c4];
        float4 v = row[32 + c4];
        acc.x += v.x / (1.f + expf(-g.x));
        acc.y += v.y / (1.f + expf(-g.y));
        acc.z += v.z / (1.f + expf(-g.z));
        acc.w += v.w / (1.f + expf(-g.w));
    }
    if (curb >= 0)
        atomicAdd(reinterpret_cast<float4*>(gg + (size_t)curb * HD) + c4, acc);
}

// ---------------------------------------------------------------------------
// Host orchestration
// Launch order puts the big Wcat tgemm at kernel slot #4 so the fixed ncu
// capture (-s 5 -c 1, lands on the 4th kernel) profiles the GEMM next round.
// ---------------------------------------------------------------------------
extern "C" void kernel_launch(void* const* d_in, const int* in_sizes, int n_in,
                              void* d_out, int out_size)
{
    (void)in_sizes; (void)n_in; (void)out_size;

    const float* x1      = (const float*)d_in[0];
    const int*   ei1     = (const int*)  d_in[1];
    const int*   batch1  = (const int*)  d_in[2];
    const float* x2      = (const float*)d_in[3];
    const int*   ei2     = (const int*)  d_in[4];
    const int*   batch2  = (const int*)  d_in[5];
    const float* W_emb   = (const float*)d_in[6];
    const float* b_emb   = (const float*)d_in[7];
    const float* msg_W1  = (const float*)d_in[8];
    const float* msg_b1  = (const float*)d_in[9];
    const float* msg_W2  = (const float*)d_in[10];
    const float* msg_b2  = (const float*)d_in[11];
    const float* upd_W1  = (const float*)d_in[12];
    const float* upd_b1  = (const float*)d_in[13];
    const float* upd_W2  = (const float*)d_in[14];
    const float* upd_b2  = (const float*)d_in[15];
    const float* node_b  = (const float*)d_in[17];
    const float* graph_b = (const float*)d_in[19];

    void *pAB, *pUI, *pT, *pdg, *pgg, *pcnt, *poff, *psrc, *pbs, *pW;
    cudaGetSymbolAddress(&pAB,  g_AB);
    cudaGetSymbolAddress(&pUI,  g_UI);
    cudaGetSymbolAddress(&pT,   g_T);
    cudaGetSymbolAddress(&pdg,  g_dg);
    cudaGetSymbolAddress(&pgg,  g_gg);
    cudaGetSymbolAddress(&pcnt, g_cnt);
    cudaGetSymbolAddress(&poff, g_off);
    cudaGetSymbolAddress(&psrc, g_src);
    cudaGetSymbolAddress(&pbs,  g_bsum);
    cudaGetSymbolAddress(&pW,   g_W);
    float* AB  = (float*)pAB;
    float* UI  = (float*)pUI;
    float* T   = (float*)pT;
    float* dg  = (float*)pdg;
    float* gg  = (float*)pgg;
    int*   cnt = (int*)pcnt;
    int*   off = (int*)poff;
    int*   src = (int*)psrc;
    int*   bs  = (int*)pbs;
    float* gw  = (float*)pW;

    float* h = UI + 256;                 // h lives at UI cols [256,384), stride 384

    // #1: round + pack weights
    prep_weights<<<(W_TOTAL + 255) / 256, 256>>>(
        W_emb, (const float*)d_in[16], (const float*)d_in[18],
        msg_W1, msg_b1, msg_W2, upd_W1, upd_W2, gw);

    // #2,#3: embedding: h = x @ W_emb + b_emb  (into UI[:,256:384])
    const dim3 gEmb((NN + 127) / 128, 1);
    tgemm<0><<<gEmb, 256>>>(x1, 64, gw + OFF_EMB, h, 384, b_emb, nullptr, NN, HD, 64);
    tgemm<0><<<gEmb, 256>>>(x2, 64, gw + OFF_EMB, h + (size_t)NN * 384, 384,
                            b_emb, nullptr, NN, HD, 64);

    const int GM = (NB + 127) / 128;     // 157

    for (int l = 0; l < 2; l++) {
        const float* Wcat = gw + OFF_LAYER(l) + OFF_WCAT;
        const float* Wm2  = gw + OFF_LAYER(l) + OFF_WM2;
        const float* Wu1  = gw + OFF_LAYER(l) + OFF_WU1;
        const float* Wu2  = gw + OFF_LAYER(l) + OFF_WU2;
        const float* bcat = gw + OFF_BCAT + (size_t)l * 512;
        const float* bm2  = msg_b2 + (size_t)l * 256;
        const float* bu1  = upd_b1 + (size_t)l * 256;
        const float* bu2  = upd_b2 + (size_t)l * 128;

        // [A|B] = h @ Wcat + bcat              [2N,512]   (#4 on l==0 -> profiled)
        tgemm<0><<<dim3(GM, 4), 256>>>(h, 384, Wcat, AB, 512, bcat, nullptr,
                                       NB, 512, 128);

        if (l == 0) {
            // CSR build (needed only before the first edge pass; independent
            // of the GEMM above). Memset nodes replace the old zero_kernel.
            cudaMemsetAsync(cnt, 0, NB * sizeof(int));
            count_kernel<<<(2 * NE + 255) / 256, 256>>>(ei1, ei2, cnt);
            scan1_kernel<<<SCAN_B, 1024>>>(cnt, off, dg, bs);
            scan2_kernel<<<SCAN_B, 1024>>>(off, cnt, bs);
            scatter_kernel<<<(2 * NE + 255) / 256, 256>>>(ei1, ei2, cnt, src);
        }

        // T[n] = sum relu(A[src] + B[n])       (CSR, no atomics)
        edge_csr<<<NB / 4, 256>>>(off, src, AB, T);
        // agg = T @ Wm2 + deg*b2  -> UI[:,0:256]
        tgemm<0><<<dim3(GM, 2), 256>>>(T, 256, Wm2, UI, 384, bm2, dg,
                                       NB, 256, 256);
        // u1 = relu(UI @ Wu1 + bu1)            (K=384, concat-free) -> T
        tgemm<1><<<dim3(GM, 2), 256>>>(UI, 384, Wu1, T, 256, bu1, nullptr,
                                       NB, 256, 384);
        // h += u1 @ Wu2 + bu2                  (residual, ldc=384)
        tgemm<2><<<dim3(GM, 1), 256>>>(T, 256, Wu2, h, 384, bu2, nullptr,
                                       NB, 128, 256);
    }

    // readout
    tgemm<0><<<dim3(GM, 2), 256>>>(h, 384, gw + OFF_NODE, AB, 256, node_b, nullptr,
                                   NB, 256, 128);
    cudaMemsetAsync(gg, 0, 2 * NG * HD * sizeof(float));
    gatepool_kernel<<<(NB / 128) + 1, 256>>>(AB, batch1, batch2, gg);
    tgemm<0><<<dim3(1, 1), 256>>>(gg, 128, gw + OFF_GRAPH, (float*)d_out, 128,
                                  graph_b, nullptr, 2 * NG, HD, 128);
}

// round 14
// speedup vs baseline: 2.7801x; 1.0642x over previous
#include <cuda_runtime.h>
#include <math.h>

#define NN 10000   // nodes per branch
#define NE 160000  // edges per branch
#define NG 32      // graphs per branch
#define HD 128     // hidden
#define NB (2*NN)  // stacked nodes
#define SCAN_B 20  // scan blocks (1024 each >= NB)

// ---------------------------------------------------------------------------
// Static device scratch (allocation-free rule)
// ---------------------------------------------------------------------------
__device__ float g_AB[NB * 512];    // [A_row(256) | B_row(256)] per node (msg W1 out)
__device__ float g_UI[NB * 384];    // cols 0:256 = agg, cols 256:384 = h (persistent)
__device__ float g_T [NB * 256];    // edge sums / u1 / nx scratch
__device__ float g_dg[NB];          // in-degree (float)
__device__ float g_gg[2 * NG * HD]; // pooled per-graph [64,128]
__device__ int   g_cnt[NB];         // counts, then scatter cursor
__device__ int   g_off[NB + 1];     // CSR offsets
__device__ int   g_src[2 * NE];     // CSR source lists
__device__ int   g_bsum[SCAN_B];    // per-block scan sums
__device__ float g_W [582656];      // packed tf32-rounded weights + bcat

// packed weight offsets (floats)
#define OFF_EMB    0
#define OFF_NODE   8192
#define OFF_GRAPH  40960
#define OFF_LAYER(l) (57344 + (l) * 262144)
#define OFF_WCAT   0
#define OFF_WM2    65536
#define OFF_WU1    131072
#define OFF_WU2    229376
#define OFF_BCAT   581632
#define W_TOTAL    582656

// ---------------------------------------------------------------------------
// helpers
// ---------------------------------------------------------------------------
__device__ __forceinline__ float round_tf32(float f) {
    unsigned u;
    asm("cvt.rna.tf32.f32 %0, %1;" : "=r"(u) : "f"(f));
    return __uint_as_float(u);
}
__device__ __forceinline__ void cp16(void* smem, const void* g, int sz) {
    unsigned s = (unsigned)__cvta_generic_to_shared(smem);
    asm volatile("cp.async.cg.shared.global [%0], [%1], 16, %2;"
                 :: "r"(s), "l"(g), "r"(sz));
}

// ---------------------------------------------------------------------------
// TF32 tensor-core GEMM (m16n8k8).
//   EPI 0: C = acc + bias (bias optionally scaled per-row by rowscale)
//   EPI 1: C = relu(acc + bias)
//   EPI 2: C = C + acc + bias        (residual)
//   CVT 1: apply cvt.rna.tf32 to A fragments in-loop (for raw-fp32 A inputs)
//   CVT 0: A already tf32-rounded by its producer -> pass bits straight to MMA
//   RND 1: round outputs to tf32 in epilogue (when C feeds another GEMM's A)
// ---------------------------------------------------------------------------
template <int EPI, int CVT, int RND>
__global__ __launch_bounds__(256, 2)
void tgemm(const float* __restrict__ Ag, int lda,
           const float* __restrict__ Bg,
           float* __restrict__ C, int ldc,
           const float* __restrict__ bias,
           const float* __restrict__ rowscale,
           int M, int N, int K)
{
    constexpr int BM = 128, BK = 16;
    __shared__ __align__(16) float As[2][BM][20];
    __shared__ __align__(16) float Bs[2][BK][136];

    const int tid = threadIdx.x;
    const int l = tid & 31, w = tid >> 5;
    const int wm = (w >> 2) * 64, wn = (w & 3) * 32;
    const int m0 = blockIdx.x * BM, n0 = blockIdx.y * 128;

    float acc[4][4][4];
#pragma unroll
    for (int a = 0; a < 4; a++)
#pragma unroll
        for (int b = 0; b < 4; b++)
#pragma unroll
            for (int c = 0; c < 4; c++) acc[a][b][c] = 0.f;

    auto docopy = [&](int t, int buf) {
#pragma unroll
        for (int i = 0; i < 2; i++) {
            int idx = tid + i * 256;
            int m = idx >> 2, k4 = idx & 3;
            const float* src = Ag + (size_t)(m0 + m) * lda + t * BK + k4 * 4;
            int sz = (m0 + m < M) ? 16 : 0;
            if (!sz) src = Ag;
            cp16(&As[buf][m][k4 * 4], src, sz);
        }
#pragma unroll
        for (int i = 0; i < 2; i++) {
            int idx = tid + i * 256;
            int k = idx >> 5, n4 = idx & 31;
            cp16(&Bs[buf][k][n4 * 4],
                 Bg + (size_t)(t * BK + k) * N + n0 + n4 * 4, 16);
        }
        asm volatile("cp.async.commit_group;");
    };

    docopy(0, 0);
    const int nt = K / BK;
    int buf = 0;
    for (int t = 0; t < nt; t++) {
        if (t + 1 < nt) {
            docopy(t + 1, buf ^ 1);
            asm volatile("cp.async.wait_group 1;");
        } else {
            asm volatile("cp.async.wait_group 0;");
        }
        __syncthreads();

#pragma unroll
        for (int j = 0; j < 2; j++) {
            const int kb = j * 8;
            unsigned ua[4][4];
#pragma unroll
            for (int mt = 0; mt < 4; mt++) {
                float f0 = As[buf][wm + mt * 16 +     (l >> 2)][kb +     (l & 3)];
                float f1 = As[buf][wm + mt * 16 + 8 + (l >> 2)][kb +     (l & 3)];
                float f2 = As[buf][wm + mt * 16 +     (l >> 2)][kb + 4 + (l & 3)];
                float f3 = As[buf][wm + mt * 16 + 8 + (l >> 2)][kb + 4 + (l & 3)];
                if (CVT) {
                    asm("cvt.rna.tf32.f32 %0, %1;" : "=r"(ua[mt][0]) : "f"(f0));
                    asm("cvt.rna.tf32.f32 %0, %1;" : "=r"(ua[mt][1]) : "f"(f1));
                    asm("cvt.rna.tf32.f32 %0, %1;" : "=r"(ua[mt][2]) : "f"(f2));
                    asm("cvt.rna.tf32.f32 %0, %1;" : "=r"(ua[mt][3]) : "f"(f3));
                } else {
                    ua[mt][0] = __float_as_uint(f0);
                    ua[mt][1] = __float_as_uint(f1);
                    ua[mt][2] = __float_as_uint(f2);
                    ua[mt][3] = __float_as_uint(f3);
                }
            }
            unsigned ub[4][2];
#pragma unroll
            for (int q = 0; q < 4; q++) {
                ub[q][0] = __float_as_uint(Bs[buf][kb +     (l & 3)][wn + q * 8 + (l >> 2)]);
                ub[q][1] = __float_as_uint(Bs[buf][kb + 4 + (l & 3)][wn + q * 8 + (l >> 2)]);
            }
#pragma unroll
            for (int mt = 0; mt < 4; mt++)
#pragma unroll
                for (int q = 0; q < 4; q++)
                    asm volatile(
                        "mma.sync.aligned.m16n8k8.row.col.f32.tf32.tf32.f32 "
                        "{%0,%1,%2,%3}, {%4,%5,%6,%7}, {%8,%9}, {%0,%1,%2,%3};"
                        : "+f"(acc[mt][q][0]), "+f"(acc[mt][q][1]),
                          "+f"(acc[mt][q][2]), "+f"(acc[mt][q][3])
                        : "r"(ua[mt][0]), "r"(ua[mt][1]),
                          "r"(ua[mt][2]), "r"(ua[mt][3]),
                          "r"(ub[q][0]), "r"(ub[q][1]));
        }
        __syncthreads();
        buf ^= 1;
    }

#pragma unroll
    for (int mt = 0; mt < 4; mt++) {
#pragma unroll
        for (int half = 0; half < 2; half++) {
            const int r = m0 + wm + mt * 16 + half * 8 + (l >> 2);
            if (r < M) {
                const float rs = rowscale ? rowscale[r] : 1.f;
#pragma unroll
                for (int q = 0; q < 4; q++) {
                    const int c = n0 + wn + q * 8 + 2 * (l & 3);
                    float v0 = acc[mt][q][half * 2 + 0];
                    float v1 = acc[mt][q][half * 2 + 1];
                    if (bias) { v0 += bias[c] * rs; v1 += bias[c + 1] * rs; }
                    float* cp = C + (size_t)r * ldc + c;
                    if (EPI == 2) { v0 += cp[0]; v1 += cp[1]; }
                    if (EPI == 1) { v0 = fmaxf(v0, 0.f); v1 = fmaxf(v1, 0.f); }
                    if (RND) { v0 = round_tf32(v0); v1 = round_tf32(v1); }
                    *reinterpret_cast<float2*>(cp) = make_float2(v0, v1);
                }
            }
        }
    }
}

// ---------------------------------------------------------------------------
// Weight prep: round to tf32 and pack (Wcat = [W1_top | W1_bot] cols)
// ---------------------------------------------------------------------------
__global__ void prep_weights(const float* __restrict__ W_emb,
                             const float* __restrict__ node_W,
                             const float* __restrict__ graph_W,
                             const float* __restrict__ mW1,
                             const float* __restrict__ mb1,
                             const float* __restrict__ mW2,
                             const float* __restrict__ uW1,
                             const float* __restrict__ uW2,
                             float* __restrict__ gw)
{
    int i = blockIdx.x * 256 + threadIdx.x;
    if (i >= W_TOTAL) return;
    float v;
    if (i < OFF_NODE)        v = round_tf32(W_emb[i - OFF_EMB]);
    else if (i < OFF_GRAPH)  v = round_tf32(node_W[i - OFF_NODE]);
    else if (i < 57344)      v = round_tf32(graph_W[i - OFF_GRAPH]);
    else if (i < OFF_BCAT) {
        int j = i - 57344;
        int lay = j / 262144, r = j % 262144;
        if (r < 65536) {
            int k = r >> 9, c = r & 511;
            float s = (c < 256) ? mW1[(size_t)lay * 65536 + k * 256 + c]
                                : mW1[(size_t)lay * 65536 + (k + 128) * 256 + (c - 256)];
            v = round_tf32(s);
        } else if (r < 131072) v = round_tf32(mW2[(size_t)lay * 65536 + (r - 65536)]);
        else if (r < 229376)   v = round_tf32(uW1[(size_t)lay * 98304 + (r - 131072)]);
        else                   v = round_tf32(uW2[(size_t)lay * 32768 + (r - 229376)]);
    } else {
        int j = i - OFF_BCAT;
        int lay = j >> 9, c = j & 511;
        v = (c < 256) ? mb1[lay * 256 + c] : 0.f;
    }
    gw[i] = v;
}

// ---------------------------------------------------------------------------
// CSR construction
// ---------------------------------------------------------------------------
__global__ void count_kernel(const int* __restrict__ ei1, const int* __restrict__ ei2,
                             int* __restrict__ cnt) {
    int e = blockIdx.x * blockDim.x + threadIdx.x;
    if (e >= 2 * NE) return;
    int t = (e < NE) ? ei1[e] : (ei2[e - NE] + NN);
    atomicAdd(cnt + t, 1);
}

// scan stage 1: per-block coalesced exclusive scan (1 elem/thread, 20 blocks)
__global__ void scan1_kernel(const int* __restrict__ cnt, int* __restrict__ off,
                             float* __restrict__ dg, int* __restrict__ bsum) {
    __shared__ int wsum[32];
    const int t = threadIdx.x, lane = t & 31, wid = t >> 5;
    const int i = blockIdx.x * 1024 + t;
    int v = (i < NB) ? cnt[i] : 0;
    int inc = v;
#pragma unroll
    for (int d = 1; d < 32; d <<= 1) {
        int y = __shfl_up_sync(0xffffffffu, inc, d);
        if (lane >= d) inc += y;
    }
    if (lane == 31) wsum[wid] = inc;
    __syncthreads();
    if (wid == 0) {
        int ws = wsum[lane];
#pragma unroll
        for (int d = 1; d < 32; d <<= 1) {
            int y = __shfl_up_sync(0xffffffffu, ws, d);
            if (lane >= d) ws += y;
        }
        wsum[lane] = ws;
    }
    __syncthreads();
    int e = inc - v + (wid ? wsum[wid - 1] : 0);   // block-local exclusive
    if (i < NB) { off[i] = e; dg[i] = (float)v; }
    if (t == 1023) bsum[blockIdx.x] = e + v;       // block total
}

// scan stage 2: add block bases (each block re-scans the 20 sums in-warp)
__global__ void scan2_kernel(int* __restrict__ off, int* __restrict__ cnt,
                             const int* __restrict__ bsum) {
    __shared__ int sbase, stot;
    const int t = threadIdx.x, lane = t & 31;
    if (t < 32) {
        int v = (lane < SCAN_B) ? bsum[lane] : 0;
        int inc = v;
#pragma unroll
        for (int d = 1; d < 32; d <<= 1) {
            int y = __shfl_up_sync(0xffffffffu, inc, d);
            if (lane >= d) inc += y;
        }
        if (lane == (int)blockIdx.x) sbase = inc - v;
        if (lane == SCAN_B - 1)      stot = inc;
    }
    __syncthreads();
    const int i = blockIdx.x * 1024 + t;
    if (i < NB) {
        int o = off[i] + sbase;
        off[i] = o;
        cnt[i] = o;                       // scatter cursor
    }
    if (blockIdx.x == SCAN_B - 1 && t == 1023) off[NB] = stot;
}

__global__ void scatter_kernel(const int* __restrict__ ei1, const int* __restrict__ ei2,
                               int* __restrict__ cursor, int* __restrict__ srcs) {
    int e = blockIdx.x * blockDim.x + threadIdx.x;
    if (e >= 2 * NE) return;
    int t, s;
    if (e < NE) { t = ei1[e];      s = ei1[NE + e]; }
    else        { int e2 = e - NE; t = ei2[e2] + NN; s = ei2[NE + e2] + NN; }
    int p = atomicAdd(cursor + t, 1);
    srcs[p] = s;
}

// ---------------------------------------------------------------------------
// Edge aggregation (CSR), 4-way src unroll; output rounded to tf32 since T
// feeds the Wm2 GEMM A-operand (identical numerics to the old in-loop cvt):
// T[n] = round_tf32( sum_{src in csr(n)} relu(A[src] + B[n]) )
// ---------------------------------------------------------------------------
__global__ void edge_csr(const int* __restrict__ off, const int* __restrict__ srcs,
                         const float* __restrict__ AB, float* __restrict__ T) {
    const int node = blockIdx.x * 4 + (threadIdx.x >> 6);
    const int lane = threadIdx.x & 63;
    const float4* ABf = reinterpret_cast<const float4*>(AB);
    const int p0 = off[node], p1 = off[node + 1];
    float4 b = ABf[(size_t)node * 128 + 64 + lane];
    float4 acc = make_float4(0.f, 0.f, 0.f, 0.f);
    int p = p0;
    for (; p + 4 <= p1; p += 4) {
        int s0 = srcs[p], s1 = srcs[p + 1], s2 = srcs[p + 2], s3 = srcs[p + 3];
        float4 a0 = ABf[(size_t)s0 * 128 + lane];
        float4 a1 = ABf[(size_t)s1 * 128 + lane];
        float4 a2 = ABf[(size_t)s2 * 128 + lane];
        float4 a3 = ABf[(size_t)s3 * 128 + lane];
        acc.x += fmaxf(a0.x + b.x, 0.f) + fmaxf(a1.x + b.x, 0.f)
               + fmaxf(a2.x + b.x, 0.f) + fmaxf(a3.x + b.x, 0.f);
        acc.y += fmaxf(a0.y + b.y, 0.f) + fmaxf(a1.y + b.y, 0.f)
               + fmaxf(a2.y + b.y, 0.f) + fmaxf(a3.y + b.y, 0.f);
        acc.z += fmaxf(a0.z + b.z, 0.f) + fmaxf(a1.z + b.z, 0.f)
               + fmaxf(a2.z + b.z, 0.f) + fmaxf(a3.z + b.z, 0.f);
        acc.w += fmaxf(a0.w + b.w, 0.f) + fmaxf(a1.w + b.w, 0.f)
               + fmaxf(a2.w + b.w, 0.f) + fmaxf(a3.w + b.w, 0.f);
    }
    for (; p < p1; ++p) {
        int s = srcs[p];
        float4 a = ABf[(size_t)s * 128 + lane];
        acc.x += fmaxf(a.x + b.x, 0.f);
        acc.y += fmaxf(a.y + b.y, 0.f);
        acc.z += fmaxf(a.z + b.z, 0.f);
        acc.w += fmaxf(a.w + b.w, 0.f);
    }
    acc.x = round_tf32(acc.x);
    acc.y = round_tf32(acc.y);
    acc.z = round_tf32(acc.z);
    acc.w = round_tf32(acc.w);
    reinterpret_cast<float4*>(T)[(size_t)node * 64 + lane] = acc;
}

// ---------------------------------------------------------------------------
// Gate + pool (sorted batch, register run-accumulation)
// ---------------------------------------------------------------------------
#define GP_L 16
__global__ void gatepool_kernel(const float* __restrict__ nx,
                                const int* __restrict__ batch1,
                                const int* __restrict__ batch2,
                                float* __restrict__ gg) {
    const int r = threadIdx.x >> 5, c4 = threadIdx.x & 31;
    const int start = (blockIdx.x * 8 + r) * GP_L;
    float4 acc = make_float4(0.f, 0.f, 0.f, 0.f);
    int curb = -1;
    for (int i = 0; i < GP_L; i++) {
        int node = start + i;
        if (node >= NB) break;
        int b = (node < NN) ? batch1[node] : (batch2[node - NN] + NG);
        if (b != curb) {
            if (curb >= 0)
                atomicAdd(reinterpret_cast<float4*>(gg + (size_t)curb * HD) + c4, acc);
            acc = make_float4(0.f, 0.f, 0.f, 0.f);
            curb = b;
        }
        const float4* row = reinterpret_cast<const float4*>(nx + (size_t)node * 256);
        float4 g = row[c4];
        float4 v = row[32 + c4];
        acc.x += v.x / (1.f + expf(-g.x));
        acc.y += v.y / (1.f + expf(-g.y));
        acc.z += v.z / (1.f + expf(-g.z));
        acc.w += v.w / (1.f + expf(-g.w));
    }
    if (curb >= 0)
        atomicAdd(reinterpret_cast<float4*>(gg + (size_t)curb * HD) + c4, acc);
}

// ---------------------------------------------------------------------------
// Host orchestration (big Wcat tgemm stays at kernel slot #4 for ncu)
// ---------------------------------------------------------------------------
extern "C" void kernel_launch(void* const* d_in, const int* in_sizes, int n_in,
                              void* d_out, int out_size)
{
    (void)in_sizes; (void)n_in; (void)out_size;

    const float* x1      = (const float*)d_in[0];
    const int*   ei1     = (const int*)  d_in[1];
    const int*   batch1  = (const int*)  d_in[2];
    const float* x2      = (const float*)d_in[3];
    const int*   ei2     = (const int*)  d_in[4];
    const int*   batch2  = (const int*)  d_in[5];
    const float* W_emb   = (const float*)d_in[6];
    const float* b_emb   = (const float*)d_in[7];
    const float* msg_W1  = (const float*)d_in[8];
    const float* msg_b1  = (const float*)d_in[9];
    const float* msg_W2  = (const float*)d_in[10];
    const float* msg_b2  = (const float*)d_in[11];
    const float* upd_W1  = (const float*)d_in[12];
    const float* upd_b1  = (const float*)d_in[13];
    const float* upd_W2  = (const float*)d_in[14];
    const float* upd_b2  = (const float*)d_in[15];
    const float* node_b  = (const float*)d_in[17];
    const float* graph_b = (const float*)d_in[19];

    void *pAB, *pUI, *pT, *pdg, *pgg, *pcnt, *poff, *psrc, *pbs, *pW;
    cudaGetSymbolAddress(&pAB,  g_AB);
    cudaGetSymbolAddress(&pUI,  g_UI);
    cudaGetSymbolAddress(&pT,   g_T);
    cudaGetSymbolAddress(&pdg,  g_dg);
    cudaGetSymbolAddress(&pgg,  g_gg);
    cudaGetSymbolAddress(&pcnt, g_cnt);
    cudaGetSymbolAddress(&poff, g_off);
    cudaGetSymbolAddress(&psrc, g_src);
    cudaGetSymbolAddress(&pbs,  g_bsum);
    cudaGetSymbolAddress(&pW,   g_W);
    float* AB  = (float*)pAB;
    float* UI  = (float*)pUI;
    float* T   = (float*)pT;
    float* dg  = (float*)pdg;
    float* gg  = (float*)pgg;
    int*   cnt = (int*)pcnt;
    int*   off = (int*)poff;
    int*   src = (int*)psrc;
    int*   bs  = (int*)pbs;
    float* gw  = (float*)pW;

    float* h = UI + 256;                 // h lives at UI cols [256,384), stride 384

    // #1: round + pack weights
    prep_weights<<<(W_TOTAL + 255) / 256, 256>>>(
        W_emb, (const float*)d_in[16], (const float*)d_in[18],
        msg_W1, msg_b1, msg_W2, upd_W1, upd_W2, gw);

    // #2,#3: embedding (raw x -> CVT=1; h feeds GEMMs -> RND=1)
    const dim3 gEmb((NN + 127) / 128, 1);
    tgemm<0, 1, 1><<<gEmb, 256>>>(x1, 64, gw + OFF_EMB, h, 384, b_emb, nullptr,
                                  NN, HD, 64);
    tgemm<0, 1, 1><<<gEmb, 256>>>(x2, 64, gw + OFF_EMB, h + (size_t)NN * 384, 384,
                                  b_emb, nullptr, NN, HD, 64);

    const int GM = (NB + 127) / 128;     // 157

    for (int l = 0; l < 2; l++) {
        const float* Wcat = gw + OFF_LAYER(l) + OFF_WCAT;
        const float* Wm2  = gw + OFF_LAYER(l) + OFF_WM2;
        const float* Wu1  = gw + OFF_LAYER(l) + OFF_WU1;
        const float* Wu2  = gw + OFF_LAYER(l) + OFF_WU2;
        const float* bcat = gw + OFF_BCAT + (size_t)l * 512;
        const float* bm2  = msg_b2 + (size_t)l * 256;
        const float* bu1  = upd_b1 + (size_t)l * 256;
        const float* bu2  = upd_b2 + (size_t)l * 128;

        // [A|B] = h @ Wcat + bcat   (h rounded -> CVT=0; AB feeds edge only -> RND=0)
        tgemm<0, 0, 0><<<dim3(GM, 4), 256>>>(h, 384, Wcat, AB, 512, bcat, nullptr,
                                             NB, 512, 128);

        if (l == 0) {
            cudaMemsetAsync(cnt, 0, NB * sizeof(int));
            count_kernel<<<(2 * NE + 255) / 256, 256>>>(ei1, ei2, cnt);
            scan1_kernel<<<SCAN_B, 1024>>>(cnt, off, dg, bs);
            scan2_kernel<<<SCAN_B, 1024>>>(off, cnt, bs);
            scatter_kernel<<<(2 * NE + 255) / 256, 256>>>(ei1, ei2, cnt, src);
        }

        // T[n] = round(sum relu(A[src] + B[n]))
        edge_csr<<<NB / 4, 256>>>(off, src, AB, T);
        // agg = T @ Wm2 + deg*b2 -> UI[:,0:256]   (T rounded; agg feeds Wu1)
        tgemm<0, 0, 1><<<dim3(GM, 2), 256>>>(T, 256, Wm2, UI, 384, bm2, dg,
                                             NB, 256, 256);
        // u1 = relu(UI @ Wu1 + bu1) -> T          (UI rounded; u1 feeds Wu2)
        tgemm<1, 0, 1><<<dim3(GM, 2), 256>>>(UI, 384, Wu1, T, 256, bu1, nullptr,
                                             NB, 256, 384);
        // h += u1 @ Wu2 + bu2                     (u1 rounded; h feeds GEMMs)
        tgemm<2, 0, 1><<<dim3(GM, 1), 256>>>(T, 256, Wu2, h, 384, bu2, nullptr,
                                             NB, 128, 256);
    }

    // readout: nx = h @ node_W + node_b (nx feeds gatepool only -> RND=0)
    tgemm<0, 0, 0><<<dim3(GM, 2), 256>>>(h, 384, gw + OFF_NODE, AB, 256, node_b,
                                         nullptr, NB, 256, 128);
    cudaMemsetAsync(gg, 0, 2 * NG * HD * sizeof(float));
    gatepool_kernel<<<(NB / 128) + 1, 256>>>(AB, batch1, batch2, gg);
    // gg is raw fp32 (atomic sums) -> CVT=1; final output -> RND=0
    tgemm<0, 1, 0><<<dim3(1, 1), 256>>>(gg, 128, gw + OFF_GRAPH, (float*)d_out, 128,
                                        graph_b, nullptr, 2 * NG, HD, 128);
}

// round 15
// speedup vs baseline: 2.9404x; 1.0577x over previous
#include <cuda_runtime.h>
#include <math.h>

#define NN 10000   // nodes per branch
#define NE 160000  // edges per branch
#define NG 32      // graphs per branch
#define HD 128     // hidden
#define NB (2*NN)  // stacked nodes
#define SCAN_B 20  // scan blocks (1024 each >= NB)

// ---------------------------------------------------------------------------
// Static device scratch (allocation-free rule)
// ---------------------------------------------------------------------------
__device__ float g_AB[NB * 512];    // [A_row(256) | B_row(256)] per node (msg W1 out)
__device__ float g_UI[NB * 384];    // cols 0:256 = agg, cols 256:384 = h (persistent)
__device__ float g_T [NB * 256];    // edge sums / u1 / nx scratch
__device__ float g_dg[NB];          // in-degree (float)
__device__ float g_gg[2 * NG * HD]; // pooled per-graph [64,128]
__device__ int   g_cnt[NB];         // counts, then scatter cursor
__device__ int   g_off[NB + 1];     // CSR offsets
__device__ int   g_src[2 * NE];     // CSR source lists
__device__ int   g_bsum[SCAN_B];    // per-block scan sums
__device__ float g_W [582656];      // packed tf32-rounded weights + bcat

// packed weight offsets (floats)
#define OFF_EMB    0
#define OFF_NODE   8192
#define OFF_GRAPH  40960
#define OFF_LAYER(l) (57344 + (l) * 262144)
#define OFF_WCAT   0
#define OFF_WM2    65536
#define OFF_WU1    131072
#define OFF_WU2    229376
#define OFF_BCAT   581632
#define W_TOTAL    582656

// dynamic smem layout for tgemm (floats):
//   As: 2 buffers x 128 rows x 36  = 9216
//   Bs: 2 buffers x 32 rows  x 136 = 8704
#define AS_STRIDE 36
#define BS_STRIDE 136
#define AS_BUF    (128 * AS_STRIDE)      // 4608
#define BS_BASE   (2 * AS_BUF)           // 9216
#define BS_BUF    (32 * BS_STRIDE)       // 4352
#define SMEM_FLOATS (BS_BASE + 2 * BS_BUF)
#define SMEM_BYTES  (SMEM_FLOATS * 4)    // 71680

// ---------------------------------------------------------------------------
// helpers
// ---------------------------------------------------------------------------
__device__ __forceinline__ float round_tf32(float f) {
    unsigned u;
    asm("cvt.rna.tf32.f32 %0, %1;" : "=r"(u) : "f"(f));
    return __uint_as_float(u);
}
__device__ __forceinline__ void cp16(void* smem, const void* g, int sz) {
    unsigned s = (unsigned)__cvta_generic_to_shared(smem);
    asm volatile("cp.async.cg.shared.global [%0], [%1], 16, %2;"
                 :: "r"(s), "l"(g), "r"(sz));
}

// ---------------------------------------------------------------------------
// TF32 tensor-core GEMM (m16n8k8), BK=32, dynamic smem double-buffer.
//   EPI 0: C = acc + bias    EPI 1: relu    EPI 2: residual accumulate
//   CVT 1: cvt.rna A in-loop (raw fp32 A)   CVT 0: A pre-rounded
//   RND 1: round outputs to tf32 in epilogue
// BM=128, BN=128, 256 threads (8 warps 2x4), warp tile 64x32.
// Requires N%128==0, K%32==0.
// ---------------------------------------------------------------------------
template <int EPI, int CVT, int RND>
__global__ __launch_bounds__(256, 2)
void tgemm(const float* __restrict__ Ag, int lda,
           const float* __restrict__ Bg,
           float* __restrict__ C, int ldc,
           const float* __restrict__ bias,
           const float* __restrict__ rowscale,
           int M, int N, int K)
{
    constexpr int BM = 128, BK = 32;
    extern __shared__ __align__(16) float smem[];
    // As(buf, m, k) = smem[buf*AS_BUF + m*AS_STRIDE + k]
    // Bs(buf, k, n) = smem[BS_BASE + buf*BS_BUF + k*BS_STRIDE + n]

    const int tid = threadIdx.x;
    const int l = tid & 31, w = tid >> 5;
    const int wm = (w >> 2) * 64, wn = (w & 3) * 32;
    const int m0 = blockIdx.x * BM, n0 = blockIdx.y * 128;

    float acc[4][4][4];
#pragma unroll
    for (int a = 0; a < 4; a++)
#pragma unroll
        for (int b = 0; b < 4; b++)
#pragma unroll
            for (int c = 0; c < 4; c++) acc[a][b][c] = 0.f;

    auto docopy = [&](int t, int buf) {
#pragma unroll
        for (int i = 0; i < 4; i++) {                 // A: 128x32 = 1024 float4
            int idx = tid + i * 256;
            int m = idx >> 3, k4 = idx & 7;
            const float* src = Ag + (size_t)(m0 + m) * lda + t * BK + k4 * 4;
            int sz = (m0 + m < M) ? 16 : 0;
            if (!sz) src = Ag;
            cp16(&smem[buf * AS_BUF + m * AS_STRIDE + k4 * 4], src, sz);
        }
#pragma unroll
        for (int i = 0; i < 4; i++) {                 // B: 32x128 = 1024 float4
            int idx = tid + i * 256;
            int k = idx >> 5, n4 = idx & 31;
            cp16(&smem[BS_BASE + buf * BS_BUF + k * BS_STRIDE + n4 * 4],
                 Bg + (size_t)(t * BK + k) * N + n0 + n4 * 4, 16);
        }
        asm volatile("cp.async.commit_group;");
    };

    docopy(0, 0);
    const int nt = K / BK;
    int buf = 0;
    for (int t = 0; t < nt; t++) {
        if (t + 1 < nt) {
            docopy(t + 1, buf ^ 1);
            asm volatile("cp.async.wait_group 1;");
        } else {
            asm volatile("cp.async.wait_group 0;");
        }
        __syncthreads();

        const float* As = smem + buf * AS_BUF;
        const float* Bs = smem + BS_BASE + buf * BS_BUF;

#pragma unroll
        for (int j = 0; j < 4; j++) {                 // 4 k8-steps per BK=32
            const int kb = j * 8;
            unsigned ua[4][4];
#pragma unroll
            for (int mt = 0; mt < 4; mt++) {
                const float* ar0 = As + (wm + mt * 16 +     (l >> 2)) * AS_STRIDE;
                const float* ar1 = As + (wm + mt * 16 + 8 + (l >> 2)) * AS_STRIDE;
                float f0 = ar0[kb +     (l & 3)];
                float f1 = ar1[kb +     (l & 3)];
                float f2 = ar0[kb + 4 + (l & 3)];
                float f3 = ar1[kb + 4 + (l & 3)];
                if (CVT) {
                    asm("cvt.rna.tf32.f32 %0, %1;" : "=r"(ua[mt][0]) : "f"(f0));
                    asm("cvt.rna.tf32.f32 %0, %1;" : "=r"(ua[mt][1]) : "f"(f1));
                    asm("cvt.rna.tf32.f32 %0, %1;" : "=r"(ua[mt][2]) : "f"(f2));
                    asm("cvt.rna.tf32.f32 %0, %1;" : "=r"(ua[mt][3]) : "f"(f3));
                } else {
                    ua[mt][0] = __float_as_uint(f0);
                    ua[mt][1] = __float_as_uint(f1);
                    ua[mt][2] = __float_as_uint(f2);
                    ua[mt][3] = __float_as_uint(f3);
                }
            }
            unsigned ub[4][2];
#pragma unroll
            for (int q = 0; q < 4; q++) {
                ub[q][0] = __float_as_uint(
                    Bs[(kb +     (l & 3)) * BS_STRIDE + wn + q * 8 + (l >> 2)]);
                ub[q][1] = __float_as_uint(
                    Bs[(kb + 4 + (l & 3)) * BS_STRIDE + wn + q * 8 + (l >> 2)]);
            }
#pragma unroll
            for (int mt = 0; mt < 4; mt++)
#pragma unroll
                for (int q = 0; q < 4; q++)
                    asm volatile(
                        "mma.sync.aligned.m16n8k8.row.col.f32.tf32.tf32.f32 "
                        "{%0,%1,%2,%3}, {%4,%5,%6,%7}, {%8,%9}, {%0,%1,%2,%3};"
                        : "+f"(acc[mt][q][0]), "+f"(acc[mt][q][1]),
                          "+f"(acc[mt][q][2]), "+f"(acc[mt][q][3])
                        : "r"(ua[mt][0]), "r"(ua[mt][1]),
                          "r"(ua[mt][2]), "r"(ua[mt][3]),
                          "r"(ub[q][0]), "r"(ub[q][1]));
        }
        __syncthreads();
        buf ^= 1;
    }

#pragma unroll
    for (int mt = 0; mt < 4; mt++) {
#pragma unroll
        for (int half = 0; half < 2; half++) {
            const int r = m0 + wm + mt * 16 + half * 8 + (l >> 2);
            if (r < M) {
                const float rs = rowscale ? rowscale[r] : 1.f;
#pragma unroll
                for (int q = 0; q < 4; q++) {
                    const int c = n0 + wn + q * 8 + 2 * (l & 3);
                    float v0 = acc[mt][q][half * 2 + 0];
                    float v1 = acc[mt][q][half * 2 + 1];
                    if (bias) { v0 += bias[c] * rs; v1 += bias[c + 1] * rs; }
                    float* cp = C + (size_t)r * ldc + c;
                    if (EPI == 2) { v0 += cp[0]; v1 += cp[1]; }
                    if (EPI == 1) { v0 = fmaxf(v0, 0.f); v1 = fmaxf(v1, 0.f); }
                    if (RND) { v0 = round_tf32(v0); v1 = round_tf32(v1); }
                    *reinterpret_cast<float2*>(cp) = make_float2(v0, v1);
                }
            }
        }
    }
}

// ---------------------------------------------------------------------------
// Weight prep: round to tf32 and pack (Wcat = [W1_top | W1_bot] cols)
// ---------------------------------------------------------------------------
__global__ void prep_weights(const float* __restrict__ W_emb,
                             const float* __restrict__ node_W,
                             const float* __restrict__ graph_W,
                             const float* __restrict__ mW1,
                             const float* __restrict__ mb1,
                             const float* __restrict__ mW2,
                             const float* __restrict__ uW1,
                             const float* __restrict__ uW2,
                             float* __restrict__ gw)
{
    int i = blockIdx.x * 256 + threadIdx.x;
    if (i >= W_TOTAL) return;
    float v;
    if (i < OFF_NODE)        v = round_tf32(W_emb[i - OFF_EMB]);
    else if (i < OFF_GRAPH)  v = round_tf32(node_W[i - OFF_NODE]);
    else if (i < 57344)      v = round_tf32(graph_W[i - OFF_GRAPH]);
    else if (i < OFF_BCAT) {
        int j = i - 57344;
        int lay = j / 262144, r = j % 262144;
        if (r < 65536) {
            int k = r >> 9, c = r & 511;
            float s = (c < 256) ? mW1[(size_t)lay * 65536 + k * 256 + c]
                                : mW1[(size_t)lay * 65536 + (k + 128) * 256 + (c - 256)];
            v = round_tf32(s);
        } else if (r < 131072) v = round_tf32(mW2[(size_t)lay * 65536 + (r - 65536)]);
        else if (r < 229376)   v = round_tf32(uW1[(size_t)lay * 98304 + (r - 131072)]);
        else                   v = round_tf32(uW2[(size_t)lay * 32768 + (r - 229376)]);
    } else {
        int j = i - OFF_BCAT;
        int lay = j >> 9, c = j & 511;
        v = (c < 256) ? mb1[lay * 256 + c] : 0.f;
    }
    gw[i] = v;
}

// ---------------------------------------------------------------------------
// CSR construction
// ---------------------------------------------------------------------------
__global__ void count_kernel(const int* __restrict__ ei1, const int* __restrict__ ei2,
                             int* __restrict__ cnt) {
    int e = blockIdx.x * blockDim.x + threadIdx.x;
    if (e >= 2 * NE) return;
    int t = (e < NE) ? ei1[e] : (ei2[e - NE] + NN);
    atomicAdd(cnt + t, 1);
}

__global__ void scan1_kernel(const int* __restrict__ cnt, int* __restrict__ off,
                             float* __restrict__ dg, int* __restrict__ bsum) {
    __shared__ int wsum[32];
    const int t = threadIdx.x, lane = t & 31, wid = t >> 5;
    const int i = blockIdx.x * 1024 + t;
    int v = (i < NB) ? cnt[i] : 0;
    int inc = v;
#pragma unroll
    for (int d = 1; d < 32; d <<= 1) {
        int y = __shfl_up_sync(0xffffffffu, inc, d);
        if (lane >= d) inc += y;
    }
    if (lane == 31) wsum[wid] = inc;
    __syncthreads();
    if (wid == 0) {
        int ws = wsum[lane];
#pragma unroll
        for (int d = 1; d < 32; d <<= 1) {
            int y = __shfl_up_sync(0xffffffffu, ws, d);
            if (lane >= d) ws += y;
        }
        wsum[lane] = ws;
    }
    __syncthreads();
    int e = inc - v + (wid ? wsum[wid - 1] : 0);
    if (i < NB) { off[i] = e; dg[i] = (float)v; }
    if (t == 1023) bsum[blockIdx.x] = e + v;
}

__global__ void scan2_kernel(int* __restrict__ off, int* __restrict__ cnt,
                             const int* __restrict__ bsum) {
    __shared__ int sbase, stot;
    const int t = threadIdx.x, lane = t & 31;
    if (t < 32) {
        int v = (lane < SCAN_B) ? bsum[lane] : 0;
        int inc = v;
#pragma unroll
        for (int d = 1; d < 32; d <<= 1) {
            int y = __shfl_up_sync(0xffffffffu, inc, d);
            if (lane >= d) inc += y;
        }
        if (lane == (int)blockIdx.x) sbase = inc - v;
        if (lane == SCAN_B - 1)      stot = inc;
    }
    __syncthreads();
    const int i = blockIdx.x * 1024 + t;
    if (i < NB) {
        int o = off[i] + sbase;
        off[i] = o;
        cnt[i] = o;
    }
    if (blockIdx.x == SCAN_B - 1 && t == 1023) off[NB] = stot;
}

__global__ void scatter_kernel(const int* __restrict__ ei1, const int* __restrict__ ei2,
                               int* __restrict__ cursor, int* __restrict__ srcs) {
    int e = blockIdx.x * blockDim.x + threadIdx.x;
    if (e >= 2 * NE) return;
    int t, s;
    if (e < NE) { t = ei1[e];      s = ei1[NE + e]; }
    else        { int e2 = e - NE; t = ei2[e2] + NN; s = ei2[NE + e2] + NN; }
    int p = atomicAdd(cursor + t, 1);
    srcs[p] = s;
}

// ---------------------------------------------------------------------------
// Edge aggregation (CSR), 4-way src unroll, tf32-rounded output:
// T[n] = round_tf32( sum_{src in csr(n)} relu(A[src] + B[n]) )
// ---------------------------------------------------------------------------
__global__ void edge_csr(const int* __restrict__ off, const int* __restrict__ srcs,
                         const float* __restrict__ AB, float* __restrict__ T) {
    const int node = blockIdx.x * 4 + (threadIdx.x >> 6);
    const int lane = threadIdx.x & 63;
    const float4* ABf = reinterpret_cast<const float4*>(AB);
    const int p0 = off[node], p1 = off[node + 1];
    float4 b = ABf[(size_t)node * 128 + 64 + lane];
    float4 acc = make_float4(0.f, 0.f, 0.f, 0.f);
    int p = p0;
    for (; p + 4 <= p1; p += 4) {
        int s0 = srcs[p], s1 = srcs[p + 1], s2 = srcs[p + 2], s3 = srcs[p + 3];
        float4 a0 = ABf[(size_t)s0 * 128 + lane];
        float4 a1 = ABf[(size_t)s1 * 128 + lane];
        float4 a2 = ABf[(size_t)s2 * 128 + lane];
        float4 a3 = ABf[(size_t)s3 * 128 + lane];
        acc.x += fmaxf(a0.x + b.x, 0.f) + fmaxf(a1.x + b.x, 0.f)
               + fmaxf(a2.x + b.x, 0.f) + fmaxf(a3.x + b.x, 0.f);
        acc.y += fmaxf(a0.y + b.y, 0.f) + fmaxf(a1.y + b.y, 0.f)
               + fmaxf(a2.y + b.y, 0.f) + fmaxf(a3.y + b.y, 0.f);
        acc.z += fmaxf(a0.z + b.z, 0.f) + fmaxf(a1.z + b.z, 0.f)
               + fmaxf(a2.z + b.z, 0.f) + fmaxf(a3.z + b.z, 0.f);
        acc.w += fmaxf(a0.w + b.w, 0.f) + fmaxf(a1.w + b.w, 0.f)
               + fmaxf(a2.w + b.w, 0.f) + fmaxf(a3.w + b.w, 0.f);
    }
    for (; p < p1; ++p) {
        int s = srcs[p];
        float4 a = ABf[(size_t)s * 128 + lane];
        acc.x += fmaxf(a.x + b.x, 0.f);
        acc.y += fmaxf(a.y + b.y, 0.f);
        acc.z += fmaxf(a.z + b.z, 0.f);
        acc.w += fmaxf(a.w + b.w, 0.f);
    }
    acc.x = round_tf32(acc.x);
    acc.y = round_tf32(acc.y);
    acc.z = round_tf32(acc.z);
    acc.w = round_tf32(acc.w);
    reinterpret_cast<float4*>(T)[(size_t)node * 64 + lane] = acc;
}

// ---------------------------------------------------------------------------
// Gate + pool (sorted batch, register run-accumulation)
// ---------------------------------------------------------------------------
#define GP_L 16
__global__ void gatepool_kernel(const float* __restrict__ nx,
                                const int* __restrict__ batch1,
                                const int* __restrict__ batch2,
                                float* __restrict__ gg) {
    const int r = threadIdx.x >> 5, c4 = threadIdx.x & 31;
    const int start = (blockIdx.x * 8 + r) * GP_L;
    float4 acc = make_float4(0.f, 0.f, 0.f, 0.f);
    int curb = -1;
    for (int i = 0; i < GP_L; i++) {
        int node = start + i;
        if (node >= NB) break;
        int b = (node < NN) ? batch1[node] : (batch2[node - NN] + NG);
        if (b != curb) {
            if (curb >= 0)
                atomicAdd(reinterpret_cast<float4*>(gg + (size_t)curb * HD) + c4, acc);
            acc = make_float4(0.f, 0.f, 0.f, 0.f);
            curb = b;
        }
        const float4* row = reinterpret_cast<const float4*>(nx + (size_t)node * 256);
        float4 g = row[c4];
        float4 v = row[32 + c4];
        acc.x += v.x / (1.f + expf(-g.x));
        acc.y += v.y / (1.f + expf(-g.y));
        acc.z += v.z / (1.f + expf(-g.z));
        acc.w += v.w / (1.f + expf(-g.w));
    }
    if (curb >= 0)
        atomicAdd(reinterpret_cast<float4*>(gg + (size_t)curb * HD) + c4, acc);
}

// ---------------------------------------------------------------------------
// Host orchestration (big Wcat tgemm stays at kernel slot #4 for ncu)
// ---------------------------------------------------------------------------
extern "C" void kernel_launch(void* const* d_in, const int* in_sizes, int n_in,
                              void* d_out, int out_size)
{
    (void)in_sizes; (void)n_in; (void)out_size;

    const float* x1      = (const float*)d_in[0];
    const int*   ei1     = (const int*)  d_in[1];
    const int*   batch1  = (const int*)  d_in[2];
    const float* x2      = (const float*)d_in[3];
    const int*   ei2     = (const int*)  d_in[4];
    const int*   batch2  = (const int*)  d_in[5];
    const float* W_emb   = (const float*)d_in[6];
    const float* b_emb   = (const float*)d_in[7];
    const float* msg_W1  = (const float*)d_in[8];
    const float* msg_b1  = (const float*)d_in[9];
    const float* msg_W2  = (const float*)d_in[10];
    const float* msg_b2  = (const float*)d_in[11];
    const float* upd_W1  = (const float*)d_in[12];
    const float* upd_b1  = (const float*)d_in[13];
    const float* upd_W2  = (const float*)d_in[14];
    const float* upd_b2  = (const float*)d_in[15];
    const float* node_b  = (const float*)d_in[17];
    const float* graph_b = (const float*)d_in[19];

    void *pAB, *pUI, *pT, *pdg, *pgg, *pcnt, *poff, *psrc, *pbs, *pW;
    cudaGetSymbolAddress(&pAB,  g_AB);
    cudaGetSymbolAddress(&pUI,  g_UI);
    cudaGetSymbolAddress(&pT,   g_T);
    cudaGetSymbolAddress(&pdg,  g_dg);
    cudaGetSymbolAddress(&pgg,  g_gg);
    cudaGetSymbolAddress(&pcnt, g_cnt);
    cudaGetSymbolAddress(&poff, g_off);
    cudaGetSymbolAddress(&psrc, g_src);
    cudaGetSymbolAddress(&pbs,  g_bsum);
    cudaGetSymbolAddress(&pW,   g_W);
    float* AB  = (float*)pAB;
    float* UI  = (float*)pUI;
    float* T   = (float*)pT;
    float* dg  = (float*)pdg;
    float* gg  = (float*)pgg;
    int*   cnt = (int*)pcnt;
    int*   off = (int*)poff;
    int*   src = (int*)psrc;
    int*   bs  = (int*)pbs;
    float* gw  = (float*)pW;

    float* h = UI + 256;                 // h lives at UI cols [256,384), stride 384

    // enable >48KB dynamic smem on every tgemm instantiation we launch
    cudaFuncSetAttribute(tgemm<0,0,0>, cudaFuncAttributeMaxDynamicSharedMemorySize, SMEM_BYTES);
    cudaFuncSetAttribute(tgemm<0,1,1>, cudaFuncAttributeMaxDynamicSharedMemorySize, SMEM_BYTES);
    cudaFuncSetAttribute(tgemm<0,0,1>, cudaFuncAttributeMaxDynamicSharedMemorySize, SMEM_BYTES);
    cudaFuncSetAttribute(tgemm<1,0,1>, cudaFuncAttributeMaxDynamicSharedMemorySize, SMEM_BYTES);
    cudaFuncSetAttribute(tgemm<2,0,1>, cudaFuncAttributeMaxDynamicSharedMemorySize, SMEM_BYTES);
    cudaFuncSetAttribute(tgemm<0,1,0>, cudaFuncAttributeMaxDynamicSharedMemorySize, SMEM_BYTES);

    // #1: round + pack weights
    prep_weights<<<(W_TOTAL + 255) / 256, 256>>>(
        W_emb, (const float*)d_in[16], (const float*)d_in[18],
        msg_W1, msg_b1, msg_W2, upd_W1, upd_W2, gw);

    // #2,#3: embedding (raw x -> CVT=1; h feeds GEMMs -> RND=1)
    const dim3 gEmb((NN + 127) / 128, 1);
    tgemm<0, 1, 1><<<gEmb, 256, SMEM_BYTES>>>(x1, 64, gw + OFF_EMB, h, 384,
                                              b_emb, nullptr, NN, HD, 64);
    tgemm<0, 1, 1><<<gEmb, 256, SMEM_BYTES>>>(x2, 64, gw + OFF_EMB,
                                              h + (size_t)NN * 384, 384,
                                              b_emb, nullptr, NN, HD, 64);

    const int GM = (NB + 127) / 128;     // 157

    for (int l = 0; l < 2; l++) {
        const float* Wcat = gw + OFF_LAYER(l) + OFF_WCAT;
        const float* Wm2  = gw + OFF_LAYER(l) + OFF_WM2;
        const float* Wu1  = gw + OFF_LAYER(l) + OFF_WU1;
        const float* Wu2  = gw + OFF_LAYER(l) + OFF_WU2;
        const float* bcat = gw + OFF_BCAT + (size_t)l * 512;
        const float* bm2  = msg_b2 + (size_t)l * 256;
        const float* bu1  = upd_b1 + (size_t)l * 256;
        const float* bu2  = upd_b2 + (size_t)l * 128;

        // [A|B] = h @ Wcat + bcat   (#4 on l==0 -> profiled)
        tgemm<0, 0, 0><<<dim3(GM, 4), 256, SMEM_BYTES>>>(h, 384, Wcat, AB, 512,
                                                         bcat, nullptr, NB, 512, 128);

        if (l == 0) {
            cudaMemsetAsync(cnt, 0, NB * sizeof(int));
            count_kernel<<<(2 * NE + 255) / 256, 256>>>(ei1, ei2, cnt);
            scan1_kernel<<<SCAN_B, 1024>>>(cnt, off, dg, bs);
            scan2_kernel<<<SCAN_B, 1024>>>(off, cnt, bs);
            scatter_kernel<<<(2 * NE + 255) / 256, 256>>>(ei1, ei2, cnt, src);
        }

        // T[n] = round(sum relu(A[src] + B[n]))
        edge_csr<<<NB / 4, 256>>>(off, src, AB, T);
        // agg = T @ Wm2 + deg*b2 -> UI[:,0:256]
        tgemm<0, 0, 1><<<dim3(GM, 2), 256, SMEM_BYTES>>>(T, 256, Wm2, UI, 384,
                                                         bm2, dg, NB, 256, 256);
        // u1 = relu(UI @ Wu1 + bu1) -> T
        tgemm<1, 0, 1><<<dim3(GM, 2), 256, SMEM_BYTES>>>(UI, 384, Wu1, T, 256,
                                                         bu1, nullptr, NB, 256, 384);
        // h += u1 @ Wu2 + bu2
        tgemm<2, 0, 1><<<dim3(GM, 1), 256, SMEM_BYTES>>>(T, 256, Wu2, h, 384,
                                                         bu2, nullptr, NB, 128, 256);
    }

    // readout
    tgemm<0, 0, 0><<<dim3(GM, 2), 256, SMEM_BYTES>>>(h, 384, gw + OFF_NODE, AB, 256,
                                                     node_b, nullptr, NB, 256, 128);
    cudaMemsetAsync(gg, 0, 2 * NG * HD * sizeof(float));
    gatepool_kernel<<<(NB / 128) + 1, 256>>>(AB, batch1, batch2, gg);
    tgemm<0, 1, 0><<<dim3(1, 1), 256, SMEM_BYTES>>>(gg, 128, gw + OFF_GRAPH,
                                                    (float*)d_out, 128,
                                                    graph_b, nullptr, 2 * NG, HD, 128);
}

// round 17
// speedup vs baseline: 4.2750x; 1.4539x over previous
#include <cuda_runtime.h>
#include <cuda_fp16.h>
#include <math.h>
#include <stdint.h>

#define NN 10000   // nodes per branch
#define NE 160000  // edges per branch
#define NG 32      // graphs per branch
#define HD 128     // hidden
#define NB (2*NN)  // stacked nodes
#define SCAN_B 20

// ---------------------------------------------------------------------------
// Static device scratch
// ---------------------------------------------------------------------------
__device__ __half g_ABh[NB * 512];   // [A(256)|B(256)] per node; reused as nx
__device__ __half g_UIh[NB * 384];   // cols 0:256 agg, 256:384 h (persistent)
__device__ __half g_Th [NB * 256];   // edge sums / u1
__device__ float  g_dg[NB];
__device__ float  g_gg[2 * NG * HD];
__device__ int    g_cnt[NB];
__device__ int    g_off[NB + 1];
__device__ int    g_src[2 * NE];
__device__ int    g_bsum[SCAN_B];
__device__ float  g_W [25600];       // fp32: emb(tf32) + graph(tf32) + bcat
__device__ __half g_Wh[557056];      // fp16 weights, transposed [N][K]

// g_W offsets (floats)
#define OFF_EMB    0        // [64][128]
#define OFF_GRAPH  8192     // [128][128]
#define OFF_BCAT   24576    // 2 x 512
#define W_TOTAL    25600
// g_Wh offsets (halves)
#define HCAT(l)  ((l) * 65536)            // [512][128]
#define HM2(l)   (131072 + (l) * 65536)   // [256][256]
#define HU1(l)   (262144 + (l) * 98304)   // [256][384]
#define HU2(l)   (458752 + (l) * 32768)   // [128][256]
#define HNODE    524288                   // [256][128]
#define WH_TOTAL 557056

// ---------------------------------------------------------------------------
// helpers
// ---------------------------------------------------------------------------
__device__ __forceinline__ float round_tf32(float f) {
    unsigned u;
    asm("cvt.rna.tf32.f32 %0, %1;" : "=r"(u) : "f"(f));
    return __uint_as_float(u);
}
__device__ __forceinline__ void cp16(void* smem, const void* g, int sz) {
    unsigned s = (unsigned)__cvta_generic_to_shared(smem);
    asm volatile("cp.async.cg.shared.global [%0], [%1], 16, %2;"
                 :: "r"(s), "l"(g), "r"(sz));
}

// ---------------------------------------------------------------------------
// fp16 HMMA GEMM (m16n8k16), BM=128 BN=128 BK=64, 256 threads (8 warps 2x4),
// warp tile 64x32, fp32 accumulate, double-buffered dynamic smem.
//   EPI 0: C = acc + bias (rowscale-scaled)  EPI 1: relu  EPI 2: residual
// A: fp16 row-major [M][lda]. Bh: fp16 packed [Ntotal][K] (transposed).
// C: fp16 row-major [M][ldc]. grid = (ceil(M/128), N/128). K % 64 == 0.
// ---------------------------------------------------------------------------
#define HS 72                          // smem row stride in halves
#define HA_BUF (128 * HS)              // halves per A buffer (9216)
#define HSM_BYTES (1024 + 4 * HA_BUF * 2)   // 1024 hdr + 4 bufs * 18432B

template <int EPI>
__global__ __launch_bounds__(256, 2)
void hgemm(const __half* __restrict__ Ag, int lda,
           const __half* __restrict__ Bh, int K,
           __half* __restrict__ C, int ldc,
           const float* __restrict__ bias,
           const float* __restrict__ rowscale,
           int M)
{
    extern __shared__ __align__(16) char sm[];
    float* sbias = (float*)sm;                       // 512 B
    __half* Abuf = (__half*)(sm + 1024);             // 2 x HA_BUF
    __half* Bbuf = Abuf + 2 * HA_BUF;                // 2 x HA_BUF

    const int tid = threadIdx.x;
    const int l = tid & 31, w = tid >> 5;
    const int l4 = l >> 2, c2 = 2 * (l & 3);
    const int wm = (w >> 2) * 64, wn = (w & 3) * 32;
    const int m0 = blockIdx.x * 128;
    const int ntile = blockIdx.y;
    Bh += (size_t)ntile * 128 * K;
    C  += (size_t)ntile * 128;

    if (tid < 128) sbias[tid] = bias ? bias[ntile * 128 + tid] : 0.f;

    float acc[4][4][4];
#pragma unroll
    for (int a = 0; a < 4; a++)
#pragma unroll
        for (int b = 0; b < 4; b++)
#pragma unroll
            for (int c = 0; c < 4; c++) acc[a][b][c] = 0.f;

    auto docopy = [&](int t, int buf) {
#pragma unroll
        for (int i = 0; i < 4; i++) {                // A: 128 x 64 halves
            int idx = tid + i * 256;
            int row = idx >> 3, g = idx & 7;
            const __half* src = Ag + (size_t)(m0 + row) * lda + t * 64 + g * 8;
            int sz = (m0 + row < M) ? 16 : 0;
            if (!sz) src = Ag;
            cp16(Abuf + buf * HA_BUF + row * HS + g * 8, src, sz);
        }
#pragma unroll
        for (int i = 0; i < 4; i++) {                // B: 128 n-rows x 64 k
            int idx = tid + i * 256;
            int row = idx >> 3, g = idx & 7;
            cp16(Bbuf + buf * HA_BUF + row * HS + g * 8,
                 Bh + (size_t)row * K + t * 64 + g * 8, 16);
        }
        asm volatile("cp.async.commit_group;");
    };

    docopy(0, 0);
    const int nt = K >> 6;
    int buf = 0;
    for (int t = 0; t < nt; t++) {
        if (t + 1 < nt) { docopy(t + 1, buf ^ 1); asm volatile("cp.async.wait_group 1;"); }
        else            { asm volatile("cp.async.wait_group 0;"); }
        __syncthreads();

        const __half* As = Abuf + buf * HA_BUF;
        const __half* Bs = Bbuf + buf * HA_BUF;
#pragma unroll
        for (int j = 0; j < 4; j++) {                // 4 k16-steps per BK=64
            const int kb = j * 16;
            unsigned ua[4][4];
#pragma unroll
            for (int mt = 0; mt < 4; mt++) {
                const __half* r0 = As + (wm + mt * 16 + l4) * HS + kb + c2;
                const __half* r1 = r0 + 8 * HS;
                ua[mt][0] = *reinterpret_cast<const unsigned*>(r0);
                ua[mt][1] = *reinterpret_cast<const unsigned*>(r1);
                ua[mt][2] = *reinterpret_cast<const unsigned*>(r0 + 8);
                ua[mt][3] = *reinterpret_cast<const unsigned*>(r1 + 8);
            }
            unsigned ub[4][2];
#pragma unroll
            for (int q = 0; q < 4; q++) {
                const __half* br = Bs + (wn + q * 8 + l4) * HS + kb + c2;
                ub[q][0] = *reinterpret_cast<const unsigned*>(br);
                ub[q][1] = *reinterpret_cast<const unsigned*>(br + 8);
            }
#pragma unroll
            for (int mt = 0; mt < 4; mt++)
#pragma unroll
                for (int q = 0; q < 4; q++)
                    asm volatile(
                        "mma.sync.aligned.m16n8k16.row.col.f32.f16.f16.f32 "
                        "{%0,%1,%2,%3}, {%4,%5,%6,%7}, {%8,%9}, {%0,%1,%2,%3};"
                        : "+f"(acc[mt][q][0]), "+f"(acc[mt][q][1]),
                          "+f"(acc[mt][q][2]), "+f"(acc[mt][q][3])
                        : "r"(ua[mt][0]), "r"(ua[mt][1]),
                          "r"(ua[mt][2]), "r"(ua[mt][3]),
                          "r"(ub[q][0]), "r"(ub[q][1]));
        }
        __syncthreads();
        buf ^= 1;
    }

    // epilogue: C fragment layout identical to k8 path
#pragma unroll
    for (int mt = 0; mt < 4; mt++)
#pragma unroll
        for (int half = 0; half < 2; half++) {
            const int r = m0 + wm + mt * 16 + half * 8 + l4;
            if (r < M) {
                const float rs = rowscale ? rowscale[r] : 1.f;
#pragma unroll
                for (int q = 0; q < 4; q++) {
                    const int c = wn + q * 8 + c2;
                    float v0 = acc[mt][q][half * 2 + 0] + sbias[c]     * rs;
                    float v1 = acc[mt][q][half * 2 + 1] + sbias[c + 1] * rs;
                    __half2* cp = reinterpret_cast<__half2*>(C + (size_t)r * ldc + c);
                    if (EPI == 2) {
                        float2 o = __half22float2(*cp);
                        v0 += o.x; v1 += o.y;
                    }
                    if (EPI == 1) { v0 = fmaxf(v0, 0.f); v1 = fmaxf(v1, 0.f); }
                    *cp = __floats2half2_rn(v0, v1);
                }
            }
        }
}

// ---------------------------------------------------------------------------
// tf32 HMMA GEMM (m16n8k8, BK=32) — embedding (fp32 in, half out) + graph
// readout (fp32 out).  OUTH: store half2 instead of float2.
// ---------------------------------------------------------------------------
#define AS_STRIDE 36
#define BS_STRIDE 136
#define AS_BUF    (128 * AS_STRIDE)
#define BS_BASE   (2 * AS_BUF)
#define BS_BUF    (32 * BS_STRIDE)
#define SMEM_BYTES ((BS_BASE + 2 * BS_BUF) * 4)

template <int EPI, int OUTH>
__global__ __launch_bounds__(256, 2)
void tgemm(const float* __restrict__ Ag, int lda,
           const float* __restrict__ Bg,
           void* __restrict__ Cv, int ldc,
           const float* __restrict__ bias,
           int M, int N, int K)
{
    constexpr int BM = 128, BK = 32;
    extern __shared__ __align__(16) float smem[];
    const int tid = threadIdx.x;
    const int l = tid & 31, w = tid >> 5;
    const int wm = (w >> 2) * 64, wn = (w & 3) * 32;
    const int m0 = blockIdx.x * BM, n0 = blockIdx.y * 128;

    float acc[4][4][4];
#pragma unroll
    for (int a = 0; a < 4; a++)
#pragma unroll
        for (int b = 0; b < 4; b++)
#pragma unroll
            for (int c = 0; c < 4; c++) acc[a][b][c] = 0.f;

    auto docopy = [&](int t, int buf) {
#pragma unroll
        for (int i = 0; i < 4; i++) {
            int idx = tid + i * 256;
            int m = idx >> 3, k4 = idx & 7;
            const float* src = Ag + (size_t)(m0 + m) * lda + t * BK + k4 * 4;
            int sz = (m0 + m < M) ? 16 : 0;
            if (!sz) src = Ag;
            cp16(&smem[buf * AS_BUF + m * AS_STRIDE + k4 * 4], src, sz);
        }
#pragma unroll
        for (int i = 0; i < 4; i++) {
            int idx = tid + i * 256;
            int k = idx >> 5, n4 = idx & 31;
            cp16(&smem[BS_BASE + buf * BS_BUF + k * BS_STRIDE + n4 * 4],
                 Bg + (size_t)(t * BK + k) * N + n0 + n4 * 4, 16);
        }
        asm volatile("cp.async.commit_group;");
    };

    docopy(0, 0);
    const int nt = K / BK;
    int buf = 0;
    for (int t = 0; t < nt; t++) {
        if (t + 1 < nt) { docopy(t + 1, buf ^ 1); asm volatile("cp.async.wait_group 1;"); }
        else            { asm volatile("cp.async.wait_group 0;"); }
        __syncthreads();
        const float* As = smem + buf * AS_BUF;
        const float* Bs = smem + BS_BASE + buf * BS_BUF;
#pragma unroll
        for (int j = 0; j < 4; j++) {
            const int kb = j * 8;
            unsigned ua[4][4];
#pragma unroll
            for (int mt = 0; mt < 4; mt++) {
                const float* ar0 = As + (wm + mt * 16 +     (l >> 2)) * AS_STRIDE;
                const float* ar1 = As + (wm + mt * 16 + 8 + (l >> 2)) * AS_STRIDE;
                asm("cvt.rna.tf32.f32 %0, %1;" : "=r"(ua[mt][0]) : "f"(ar0[kb + (l & 3)]));
                asm("cvt.rna.tf32.f32 %0, %1;" : "=r"(ua[mt][1]) : "f"(ar1[kb + (l & 3)]));
                asm("cvt.rna.tf32.f32 %0, %1;" : "=r"(ua[mt][2]) : "f"(ar0[kb + 4 + (l & 3)]));
                asm("cvt.rna.tf32.f32 %0, %1;" : "=r"(ua[mt][3]) : "f"(ar1[kb + 4 + (l & 3)]));
            }
            unsigned ub[4][2];
#pragma unroll
            for (int q = 0; q < 4; q++) {
                ub[q][0] = __float_as_uint(Bs[(kb +     (l & 3)) * BS_STRIDE + wn + q * 8 + (l >> 2)]);
                ub[q][1] = __float_as_uint(Bs[(kb + 4 + (l & 3)) * BS_STRIDE + wn + q * 8 + (l >> 2)]);
            }
#pragma unroll
            for (int mt = 0; mt < 4; mt++)
#pragma unroll
                for (int q = 0; q < 4; q++)
                    asm volatile(
                        "mma.sync.aligned.m16n8k8.row.col.f32.tf32.tf32.f32 "
                        "{%0,%1,%2,%3}, {%4,%5,%6,%7}, {%8,%9}, {%0,%1,%2,%3};"
                        : "+f"(acc[mt][q][0]), "+f"(acc[mt][q][1]),
                          "+f"(acc[mt][q][2]), "+f"(acc[mt][q][3])
                        : "r"(ua[mt][0]), "r"(ua[mt][1]), "r"(ua[mt][2]), "r"(ua[mt][3]),
                          "r"(ub[q][0]), "r"(ub[q][1]));
        }
        __syncthreads();
        buf ^= 1;
    }
#pragma unroll
    for (int mt = 0; mt < 4; mt++)
#pragma unroll
        for (int half = 0; half < 2; half++) {
            const int r = m0 + wm + mt * 16 + half * 8 + (l >> 2);
            if (r < M) {
#pragma unroll
                for (int q = 0; q < 4; q++) {
                    const int c = n0 + wn + q * 8 + 2 * (l & 3);
                    float v0 = acc[mt][q][half * 2 + 0];
                    float v1 = acc[mt][q][half * 2 + 1];
                    if (bias) { v0 += bias[c]; v1 += bias[c + 1]; }
                    if (EPI == 1) { v0 = fmaxf(v0, 0.f); v1 = fmaxf(v1, 0.f); }
                    if (OUTH) {
                        __half* C = (__half*)Cv;
                        *reinterpret_cast<__half2*>(C + (size_t)r * ldc + c) =
                            __floats2half2_rn(v0, v1);
                    } else {
                        float* C = (float*)Cv;
                        *reinterpret_cast<float2*>(C + (size_t)r * ldc + c) =
                            make_float2(v0, v1);
                    }
                }
            }
        }
}

// ---------------------------------------------------------------------------
// Weight prep: fp32 (tf32-rounded) emb/graph + bcat, and fp16 transposed packs
// ---------------------------------------------------------------------------
__global__ void prep_all(const float* __restrict__ W_emb,
                         const float* __restrict__ node_W,
                         const float* __restrict__ graph_W,
                         const float* __restrict__ mW1,
                         const float* __restrict__ mb1,
                         const float* __restrict__ mW2,
                         const float* __restrict__ uW1,
                         const float* __restrict__ uW2,
                         float* __restrict__ gw,
                         __half* __restrict__ gh)
{
    int i = blockIdx.x * 256 + threadIdx.x;
    if (i < W_TOTAL) {
        float v;
        if (i < OFF_GRAPH)      v = round_tf32(W_emb[i]);
        else if (i < OFF_BCAT)  v = round_tf32(graph_W[i - OFF_GRAPH]);
        else {
            int j = i - OFF_BCAT;
            int lay = j >> 9, c = j & 511;
            v = (c < 256) ? mb1[lay * 256 + c] : 0.f;
        }
        gw[i] = v;
        return;
    }
    int j = i - W_TOTAL;
    if (j >= WH_TOTAL) return;
    float s;
    if (j < 131072) {                       // HCAT: [512][128]
        int lay = j >> 16, r = j & 65535;
        int n = r >> 7, k = r & 127;
        s = (n < 256) ? mW1[(size_t)lay * 65536 + k * 256 + n]
                      : mW1[(size_t)lay * 65536 + (k + 128) * 256 + (n - 256)];
    } else if (j < 262144) {                // HM2: [256][256]
        int q = j - 131072; int lay = q >> 16, r = q & 65535;
        int n = r >> 8, k = r & 255;
        s = mW2[(size_t)lay * 65536 + k * 256 + n];
    } else if (j < 458752) {                // HU1: [256][384]
        int q = j - 262144; int lay = q / 98304, r = q % 98304;
        int n = r / 384, k = r % 384;
        s = uW1[(size_t)lay * 98304 + k * 256 + n];
    } else if (j < 524288) {                // HU2: [128][256]
        int q = j - 458752; int lay = q >> 15, r = q & 32767;
        int n = r >> 8, k = r & 255;
        s = uW2[(size_t)lay * 32768 + k * 128 + n];
    } else {                                // HNODE: [256][128]
        int r = j - 524288;
        int n = r >> 7, k = r & 127;
        s = node_W[k * 256 + n];
    }
    gh[j] = __float2half_rn(s);
}

// ---------------------------------------------------------------------------
// CSR construction (proven)
// ---------------------------------------------------------------------------
__global__ void count_kernel(const int* __restrict__ ei1, const int* __restrict__ ei2,
                             int* __restrict__ cnt) {
    int e = blockIdx.x * blockDim.x + threadIdx.x;
    if (e >= 2 * NE) return;
    int t = (e < NE) ? ei1[e] : (ei2[e - NE] + NN);
    atomicAdd(cnt + t, 1);
}

__global__ void scan1_kernel(const int* __restrict__ cnt, int* __restrict__ off,
                             float* __restrict__ dg, int* __restrict__ bsum) {
    __shared__ int wsum[32];
    const int t = threadIdx.x, lane = t & 31, wid = t >> 5;
    const int i = blockIdx.x * 1024 + t;
    int v = (i < NB) ? cnt[i] : 0;
    int inc = v;
#pragma unroll
    for (int d = 1; d < 32; d <<= 1) {
        int y = __shfl_up_sync(0xffffffffu, inc, d);
        if (lane >= d) inc += y;
    }
    if (lane == 31) wsum[wid] = inc;
    __syncthreads();
    if (wid == 0) {
        int ws = wsum[lane];
#pragma unroll
        for (int d = 1; d < 32; d <<= 1) {
            int y = __shfl_up_sync(0xffffffffu, ws, d);
            if (lane >= d) ws += y;
        }
        wsum[lane] = ws;
    }
    __syncthreads();
    int e = inc - v + (wid ? wsum[wid - 1] : 0);
    if (i < NB) { off[i] = e; dg[i] = (float)v; }
    if (t == 1023) bsum[blockIdx.x] = e + v;
}

__global__ void scan2_kernel(int* __restrict__ off, int* __restrict__ cnt,
                             const int* __restrict__ bsum) {
    __shared__ int sbase, stot;
    const int t = threadIdx.x, lane = t & 31;
    if (t < 32) {
        int v = (lane < SCAN_B) ? bsum[lane] : 0;
        int inc = v;
#pragma unroll
        for (int d = 1; d < 32; d <<= 1) {
            int y = __shfl_up_sync(0xffffffffu, inc, d);
            if (lane >= d) inc += y;
        }
        if (lane == (int)blockIdx.x) sbase = inc - v;
        if (lane == SCAN_B - 1)      stot = inc;
    }
    __syncthreads();
    const int i = blockIdx.x * 1024 + t;
    if (i < NB) { int o = off[i] + sbase; off[i] = o; cnt[i] = o; }
    if (blockIdx.x == SCAN_B - 1 && t == 1023) off[NB] = stot;
}

__global__ void scatter_kernel(const int* __restrict__ ei1, const int* __restrict__ ei2,
                               int* __restrict__ cursor, int* __restrict__ srcs) {
    int e = blockIdx.x * blockDim.x + threadIdx.x;
    if (e >= 2 * NE) return;
    int t, s;
    if (e < NE) { t = ei1[e];      s = ei1[NE + e]; }
    else        { int e2 = e - NE; t = ei2[e2] + NN; s = ei2[NE + e2] + NN; }
    int p = atomicAdd(cursor + t, 1);
    srcs[p] = s;
}

// ---------------------------------------------------------------------------
// Edge aggregation (CSR, fp16 in/out, fp32 accumulate), 4-way src unroll.
// T[n] = sum relu(A[src] + B[n]).  Rows are 512 halves; lane handles 4.
// ---------------------------------------------------------------------------
__device__ __forceinline__ void acc4(float4& acc, uint2 araw,
                                     float2 b01, float2 b23) {
    const __half2* a2 = reinterpret_cast<const __half2*>(&araw);
    float2 a01 = __half22float2(a2[0]);
    float2 a23 = __half22float2(a2[1]);
    acc.x += fmaxf(a01.x + b01.x, 0.f);
    acc.y += fmaxf(a01.y + b01.y, 0.f);
    acc.z += fmaxf(a23.x + b23.x, 0.f);
    acc.w += fmaxf(a23.y + b23.y, 0.f);
}

__global__ void edge_csr(const int* __restrict__ off, const int* __restrict__ srcs,
                         const __half* __restrict__ AB, __half* __restrict__ T) {
    const int node = blockIdx.x * 4 + (threadIdx.x >> 6);
    const int lane = threadIdx.x & 63;
    const uint2* ABv = reinterpret_cast<const uint2*>(AB);
    const int p0 = off[node], p1 = off[node + 1];
    uint2 braw = ABv[(size_t)node * 128 + 64 + lane];
    const __half2* b2 = reinterpret_cast<const __half2*>(&braw);
    float2 b01 = __half22float2(b2[0]);
    float2 b23 = __half22float2(b2[1]);
    float4 acc = make_float4(0.f, 0.f, 0.f, 0.f);
    int p = p0;
    for (; p + 4 <= p1; p += 4) {
        int s0 = srcs[p], s1 = srcs[p + 1], s2 = srcs[p + 2], s3 = srcs[p + 3];
        uint2 a0 = ABv[(size_t)s0 * 128 + lane];
        uint2 a1 = ABv[(size_t)s1 * 128 + lane];
        uint2 a2 = ABv[(size_t)s2 * 128 + lane];
        uint2 a3 = ABv[(size_t)s3 * 128 + lane];
        acc4(acc, a0, b01, b23); acc4(acc, a1, b01, b23);
        acc4(acc, a2, b01, b23); acc4(acc, a3, b01, b23);
    }
    for (; p < p1; ++p)
        acc4(acc, ABv[(size_t)srcs[p] * 128 + lane], b01, b23);
    uint2 out;
    reinterpret_cast<__half2*>(&out)[0] = __floats2half2_rn(acc.x, acc.y);
    reinterpret_cast<__half2*>(&out)[1] = __floats2half2_rn(acc.z, acc.w);
    reinterpret_cast<uint2*>(T)[(size_t)node * 64 + lane] = out;
}

// ---------------------------------------------------------------------------
// Gate + pool (fp16 nx, sorted batch, register run-accumulation)
// ---------------------------------------------------------------------------
#define GP_L 16
__global__ void gatepool_kernel(const __half* __restrict__ nx,
                                const int* __restrict__ batch1,
                                const int* __restrict__ batch2,
                                float* __restrict__ gg) {
    const int r = threadIdx.x >> 5, c4 = threadIdx.x & 31;
    const int start = (blockIdx.x * 8 + r) * GP_L;
    float4 acc = make_float4(0.f, 0.f, 0.f, 0.f);
    int curb = -1;
    for (int i = 0; i < GP_L; i++) {
        int node = start + i;
        if (node >= NB) break;
        int b = (node < NN) ? batch1[node] : (batch2[node - NN] + NG);
        if (b != curb) {
            if (curb >= 0)
                atomicAdd(reinterpret_cast<float4*>(gg + (size_t)curb * HD) + c4, acc);
            acc = make_float4(0.f, 0.f, 0.f, 0.f);
            curb = b;
        }
        const uint2* row = reinterpret_cast<const uint2*>(nx + (size_t)node * 256);
        uint2 graw = row[c4];
        uint2 vraw = row[32 + c4];
        const __half2* g2 = reinterpret_cast<const __half2*>(&graw);
        const __half2* v2 = reinterpret_cast<const __half2*>(&vraw);
        float2 g01 = __half22float2(g2[0]), g23 = __half22float2(g2[1]);
        float2 v01 = __half22float2(v2[0]), v23 = __half22float2(v2[1]);
        acc.x += v01.x / (1.f + expf(-g01.x));
        acc.y += v01.y / (1.f + expf(-g01.y));
        acc.z += v23.x / (1.f + expf(-g23.x));
        acc.w += v23.y / (1.f + expf(-g23.y));
    }
    if (curb >= 0)
        atomicAdd(reinterpret_cast<float4*>(gg + (size_t)curb * HD) + c4, acc);
}

// ---------------------------------------------------------------------------
// Host orchestration (slot #4 = Wcat hgemm for ncu)
// ---------------------------------------------------------------------------
extern "C" void kernel_launch(void* const* d_in, const int* in_sizes, int n_in,
                              void* d_out, int out_size)
{
    (void)in_sizes; (void)n_in; (void)out_size;

    const float* x1      = (const float*)d_in[0];
    const int*   ei1     = (const int*)  d_in[1];
    const int*   batch1  = (const int*)  d_in[2];
    const float* x2      = (const float*)d_in[3];
    const int*   ei2     = (const int*)  d_in[4];
    const int*   batch2  = (const int*)  d_in[5];
    const float* W_emb   = (const float*)d_in[6];
    const float* b_emb   = (const float*)d_in[7];
    const float* msg_W1  = (const float*)d_in[8];
    const float* msg_b1  = (const float*)d_in[9];
    const float* msg_W2  = (const float*)d_in[10];
    const float* msg_b2  = (const float*)d_in[11];
    const float* upd_W1  = (const float*)d_in[12];
    const float* upd_b1  = (const float*)d_in[13];
    const float* upd_W2  = (const float*)d_in[14];
    const float* upd_b2  = (const float*)d_in[15];
    const float* node_b  = (const float*)d_in[17];
    const float* graph_b = (const float*)d_in[19];

    void *pAB, *pUI, *pT, *pdg, *pgg, *pcnt, *poff, *psrc, *pbs, *pW, *pWh;
    cudaGetSymbolAddress(&pAB,  g_ABh);
    cudaGetSymbolAddress(&pUI,  g_UIh);
    cudaGetSymbolAddress(&pT,   g_Th);
    cudaGetSymbolAddress(&pdg,  g_dg);
    cudaGetSymbolAddress(&pgg,  g_gg);
    cudaGetSymbolAddress(&pcnt, g_cnt);
    cudaGetSymbolAddress(&poff, g_off);
    cudaGetSymbolAddress(&psrc, g_src);
    cudaGetSymbolAddress(&pbs,  g_bsum);
    cudaGetSymbolAddress(&pW,   g_W);
    cudaGetSymbolAddress(&pWh,  g_Wh);
    __half* AB  = (__half*)pAB;
    __half* UI  = (__half*)pUI;
    __half* T   = (__half*)pT;
    float*  dg  = (float*)pdg;
    float*  gg  = (float*)pgg;
    int*    cnt = (int*)pcnt;
    int*    off = (int*)poff;
    int*    src = (int*)psrc;
    int*    bs  = (int*)pbs;
    float*  gw  = (float*)pW;
    __half* gh  = (__half*)pWh;

    __half* h = UI + 256;                // h at UI cols [256,384), stride 384

    cudaFuncSetAttribute(tgemm<0,1>, cudaFuncAttributeMaxDynamicSharedMemorySize, SMEM_BYTES);
    cudaFuncSetAttribute(tgemm<0,0>, cudaFuncAttributeMaxDynamicSharedMemorySize, SMEM_BYTES);
    cudaFuncSetAttribute(hgemm<0>,   cudaFuncAttributeMaxDynamicSharedMemorySize, HSM_BYTES);
    cudaFuncSetAttribute(hgemm<1>,   cudaFuncAttributeMaxDynamicSharedMemorySize, HSM_BYTES);
    cudaFuncSetAttribute(hgemm<2>,   cudaFuncAttributeMaxDynamicSharedMemorySize, HSM_BYTES);

    // #1: pack weights (fp32 tf32 + fp16 transposed)
    prep_all<<<(W_TOTAL + WH_TOTAL + 255) / 256, 256>>>(
        W_emb, (const float*)d_in[16], (const float*)d_in[18],
        msg_W1, msg_b1, msg_W2, upd_W1, upd_W2, gw, gh);

    // #2,#3: embedding (fp32 x -> tf32 MMA -> half store into UI cols 256:384)
    const dim3 gEmb((NN + 127) / 128, 1);
    tgemm<0, 1><<<gEmb, 256, SMEM_BYTES>>>(x1, 64, gw + OFF_EMB, h, 384,
                                           b_emb, NN, HD, 64);
    tgemm<0, 1><<<gEmb, 256, SMEM_BYTES>>>(x2, 64, gw + OFF_EMB,
                                           h + (size_t)NN * 384, 384,
                                           b_emb, NN, HD, 64);

    const int GM = (NB + 127) / 128;     // 157

    for (int l = 0; l < 2; l++) {
        const float* bcat = gw + OFF_BCAT + (size_t)l * 512;
        const float* bm2  = msg_b2 + (size_t)l * 256;
        const float* bu1  = upd_b1 + (size_t)l * 256;
        const float* bu2  = upd_b2 + (size_t)l * 128;

        // [A|B] = h @ Wcat + bcat        (#4 on l==0 -> profiled)
        hgemm<0><<<dim3(GM, 4), 256, HSM_BYTES>>>(h, 384, gh + HCAT(l), 128,
                                                  AB, 512, bcat, nullptr, NB);
        if (l == 0) {
            cudaMemsetAsync(cnt, 0, NB * sizeof(int));
            count_kernel<<<(2 * NE + 255) / 256, 256>>>(ei1, ei2, cnt);
            scan1_kernel<<<SCAN_B, 1024>>>(cnt, off, dg, bs);
            scan2_kernel<<<SCAN_B, 1024>>>(off, cnt, bs);
            scatter_kernel<<<(2 * NE + 255) / 256, 256>>>(ei1, ei2, cnt, src);
        }

        edge_csr<<<NB / 4, 256>>>(off, src, AB, T);
        // agg = T @ Wm2 + deg*b2 -> UI[:,0:256]
        hgemm<0><<<dim3(GM, 2), 256, HSM_BYTES>>>(T, 256, gh + HM2(l), 256,
                                                  UI, 384, bm2, dg, NB);
        // u1 = relu(UI @ Wu1 + bu1) -> T
        hgemm<1><<<dim3(GM, 2), 256, HSM_BYTES>>>(UI, 384, gh + HU1(l), 384,
                                                  T, 256, bu1, nullptr, NB);
        // h += u1 @ Wu2 + bu2
        hgemm<2><<<dim3(GM, 1), 256, HSM_BYTES>>>(T, 256, gh + HU2(l), 256,
                                                  h, 384, bu2, nullptr, NB);
    }

    // readout: nx = h @ node_W + node_b -> AB
    hgemm<0><<<dim3(GM, 2), 256, HSM_BYTES>>>(h, 384, gh + HNODE, 128,
                                              AB, 256, node_b, nullptr, NB);
    cudaMemsetAsync(gg, 0, 2 * NG * HD * sizeof(float));
    gatepool_kernel<<<(NB / 128) + 1, 256>>>(AB, batch1, batch2, gg);
    // graph GEMM: gg fp32 -> fp32 out
    tgemm<0, 0><<<dim3(1, 1), 256, SMEM_BYTES>>>(gg, 128, gw + OFF_GRAPH,
                                                 (float*)d_out, 128,
                                                 graph_b, 2 * NG, HD, 128);
}